// round 2
// baseline (speedup 1.0000x reference)
#include <cuda_runtime.h>
#include <math.h>

// Problem constants
#define NCLIP 64
#define TCLIP 784
#define DDIM  1024
#define KFT   196
#define KFK   147
#define NI0   588
#define NFIN  196
#define HDIM  4096
#define MROWS (NCLIP*NFIN)   // 12544

// ---------------- scratch (device globals; no allocations allowed) ----------
__device__ float g_kfn  [NCLIP*KFT*DDIM];   // normalized keyframes
__device__ float g_incrn[NCLIP*NI0*DDIM];   // normalized incremental tokens
__device__ float g_red  [NCLIP*KFT];
__device__ int   g_keep [NCLIP*KFK];
__device__ float g_kfsum[NCLIP*KFK*DDIM];
__device__ float g_kfcnt[NCLIP*KFK];
__device__ float g_kfavgn[NCLIP*KFK*DDIM];
__device__ float g_maxsim[NCLIP*NI0];
__device__ int   g_bestkf[NCLIP*NI0];
__device__ int   g_surv [NCLIP*NI0];
__device__ float g_z    [NCLIP*NFIN*DDIM];
__device__ float g_h    [MROWS*HDIM];

// ---------------- helpers ----------------
__device__ __forceinline__ float blockSum256(float v){
    __shared__ float sh[8];
    int lane = threadIdx.x & 31, w = threadIdx.x >> 5;
    #pragma unroll
    for(int o=16;o;o>>=1) v += __shfl_xor_sync(0xffffffffu, v, o);
    if(lane==0) sh[w] = v;
    __syncthreads();
    float r = (threadIdx.x < 8) ? sh[threadIdx.x] : 0.f;
    if(w==0){
        #pragma unroll
        for(int o=4;o;o>>=1) r += __shfl_xor_sync(0xffffffffu, r, o);
        if(lane==0) sh[0] = r;
    }
    __syncthreads();
    float out = sh[0];
    __syncthreads();
    return out;
}

// Bitonic sort of (key, pos) ascending lexicographically. blockDim.x == N.
// Composite key makes all keys distinct -> exactly reproduces stable argsort.
__device__ __forceinline__ void bitonic_sort(float* key, int* pos, int N){
    int t = threadIdx.x;
    for(int k=2;k<=N;k<<=1){
        for(int j=k>>1;j>0;j>>=1){
            __syncthreads();
            int ixj = t ^ j;
            if(ixj > t){
                float ka = key[t], kb = key[ixj];
                int   pa = pos[t], pb = pos[ixj];
                bool agtb = (ka > kb) || (ka == kb && pa > pb);
                bool up = ((t & k) == 0);
                if(agtb == up){
                    key[t]=kb; key[ixj]=ka;
                    pos[t]=pb; pos[ixj]=pa;
                }
            }
        }
    }
    __syncthreads();
}

__device__ __forceinline__ float gelu_exact(float v){
    return 0.5f * v * (1.0f + erff(v * 0.70710678118654752440f));
}

// ---------------- compression kernels ----------------

// L2-normalize every token row, split into kf / incr buffers.
__global__ void k_normalize(const float* __restrict__ x){
    int b = blockIdx.x / TCLIP;
    int r = blockIdx.x % TCLIP;
    const float* row = x + ((size_t)b*TCLIP + r)*DDIM;
    float ss = 0.f;
    for(int i=threadIdx.x;i<DDIM;i+=256){ float v = row[i]; ss += v*v; }
    ss = blockSum256(ss);
    float inv = 1.0f / fmaxf(sqrtf(ss), 1e-12f);
    float* dst = (r < KFT) ? (g_kfn   + ((size_t)b*KFT + r)*DDIM)
                           : (g_incrn + ((size_t)b*NI0 + (r - KFT))*DDIM);
    for(int i=threadIdx.x;i<DDIM;i+=256) dst[i] = row[i]*inv;
}

// redundancy_i = sum_j <kfn_i, kfn_j> - 1  (self term included numerically)
__global__ void k_redundancy(){
    int b = blockIdx.x / KFT;
    int i = blockIdx.x % KFT;
    __shared__ float rowi[DDIM];
    const float* ri = g_kfn + ((size_t)b*KFT + i)*DDIM;
    for(int t=threadIdx.x;t<DDIM;t+=256) rowi[t] = ri[t];
    __syncthreads();
    int w = threadIdx.x >> 5, lane = threadIdx.x & 31;
    const float4* rowi4 = (const float4*)rowi;
    float acc = 0.f;
    for(int j=w;j<KFT;j+=8){
        const float4* rj = (const float4*)(g_kfn + ((size_t)b*KFT + j)*DDIM);
        float s = 0.f;
        #pragma unroll
        for(int it=0;it<8;it++){
            float4 a = rowi4[lane + it*32];
            float4 c = rj  [lane + it*32];
            s += a.x*c.x + a.y*c.y + a.z*c.z + a.w*c.w;
        }
        #pragma unroll
        for(int o=16;o;o>>=1) s += __shfl_xor_sync(0xffffffffu, s, o);
        acc += s;
    }
    __shared__ float part[8];
    if(lane==0) part[w] = acc;
    __syncthreads();
    if(threadIdx.x==0){
        float r = 0.f;
        for(int q=0;q<8;q++) r += part[q];
        g_red[b*KFT + i] = r - 1.0f;
    }
}

// Stable argsort(redundancy) asc, keep first 147, emit kept indices ascending.
// Also init survivor list for incr tokens.
__global__ void k_select(){
    int b = blockIdx.x;
    __shared__ float key[256];
    __shared__ int   pos[256];
    __shared__ unsigned char kept[KFT];
    int t = threadIdx.x;
    key[t] = (t < KFT) ? g_red[b*KFT + t] : __int_as_float(0x7f800000);
    pos[t] = t;
    if(t < KFT) kept[t] = 0;
    bitonic_sort(key, pos, 256);
    if(t < KFK) kept[pos[t]] = 1;
    __syncthreads();
    if(t==0){
        int c = 0;
        for(int i=0;i<KFT;i++) if(kept[i]) g_keep[b*KFK + (c++)] = i;
    }
    for(int s=t;s<NI0;s+=256) g_surv[b*NI0 + s] = s;
}

__global__ void k_init(const float* __restrict__ x){
    int b = blockIdx.x / KFK, k = blockIdx.x % KFK;
    int src = g_keep[b*KFK + k];
    const float* row = x + ((size_t)b*TCLIP + src)*DDIM;
    float* dst = g_kfsum + ((size_t)b*KFK + k)*DDIM;
    for(int i=threadIdx.x;i<DDIM;i+=256) dst[i] = row[i];
    if(threadIdx.x==0) g_kfcnt[b*KFK + k] = 1.0f;
}

// kfavgn = l2norm(kf_sum / kf_count)
__global__ void k_avg(){
    int b = blockIdx.x / KFK, k = blockIdx.x % KFK;
    const float* s = g_kfsum + ((size_t)b*KFK + k)*DDIM;
    float invc = 1.0f / g_kfcnt[b*KFK + k];
    float ss = 0.f;
    for(int i=threadIdx.x;i<DDIM;i+=256){ float v = s[i]*invc; ss += v*v; }
    ss = blockSum256(ss);
    float inv = invc / fmaxf(sqrtf(ss), 1e-12f);
    float* dst = g_kfavgn + ((size_t)b*KFK + k)*DDIM;
    for(int i=threadIdx.x;i<DDIM;i+=256) dst[i] = s[i]*inv;
}

// For each surviving incr token: max / first-argmax over 147 kf similarities.
__global__ void k_sim(int n){
    int b = blockIdx.x / n, s = blockIdx.x % n;
    int tok = g_surv[b*NI0 + s];
    __shared__ float rowi[DDIM];
    const float* ri = g_incrn + ((size_t)b*NI0 + tok)*DDIM;
    for(int t=threadIdx.x;t<DDIM;t+=256) rowi[t] = ri[t];
    __syncthreads();
    int w = threadIdx.x >> 5, lane = threadIdx.x & 31;
    const float4* rowi4 = (const float4*)rowi;
    float best = -3.0e38f; int bestk = 0x7fffffff;
    for(int k=w;k<KFK;k+=8){
        const float4* rk = (const float4*)(g_kfavgn + ((size_t)b*KFK + k)*DDIM);
        float sum = 0.f;
        #pragma unroll
        for(int it=0;it<8;it++){
            float4 a = rowi4[lane + it*32];
            float4 c = rk  [lane + it*32];
            sum += a.x*c.x + a.y*c.y + a.z*c.z + a.w*c.w;
        }
        #pragma unroll
        for(int o=16;o;o>>=1) sum += __shfl_xor_sync(0xffffffffu, sum, o);
        if(sum > best){ best = sum; bestk = k; }   // k increasing -> first max in-warp
    }
    __shared__ float bv[8]; __shared__ int bk[8];
    if(lane==0){ bv[w] = best; bk[w] = bestk; }
    __syncthreads();
    if(threadIdx.x==0){
        float B0 = bv[0]; int K0 = bk[0];
        for(int q=1;q<8;q++)
            if(bv[q] > B0 || (bv[q] == B0 && bk[q] < K0)){ B0 = bv[q]; K0 = bk[q]; }
        g_maxsim[b*NI0 + s] = B0;
        g_bestkf[b*NI0 + s] = K0;
    }
}

// rank = stable argsort(-max_sim); merge top nm into kf_sum/count sequentially
// (deterministic); compact survivors preserving original order.
__global__ void k_merge(const float* __restrict__ x, int n, int nm){
    int b = blockIdx.x, t = threadIdx.x;
    __shared__ float key[1024];
    __shared__ int   pos[1024];
    __shared__ int   mpos[196], mtgt[196], mtok[196];
    __shared__ unsigned char mflag[NI0];
    key[t] = (t < n) ? -g_maxsim[b*NI0 + t] : __int_as_float(0x7f800000);
    pos[t] = t;
    bitonic_sort(key, pos, 1024);
    if(t < nm){
        int p = pos[t];
        mpos[t] = p;
        mtgt[t] = g_bestkf[b*NI0 + p];
        mtok[t] = g_surv  [b*NI0 + p];
    }
    __syncthreads();
    // Sequential merges: each thread owns one of the 1024 dims -> no races,
    // per-element accumulation order matches merge order.
    for(int m=0;m<nm;m++){
        int tgt = mtgt[m], tok = mtok[m];
        const float* feat = x + ((size_t)b*TCLIP + KFT + tok)*DDIM;
        float* dst = g_kfsum + ((size_t)b*KFK + tgt)*DDIM;
        dst[t] += feat[t];
        if(t==0) g_kfcnt[b*KFK + tgt] += 1.0f;
    }
    for(int i=t;i<n;i+=1024) mflag[i] = 0;
    __syncthreads();
    if(t < nm) mflag[mpos[t]] = 1;
    __syncthreads();
    if(t==0){
        int c = 0;
        for(int p=0;p<n;p++)
            if(!mflag[p]){ int v = g_surv[b*NI0 + p]; g_surv[b*NI0 + c] = v; c++; }
    }
}

// z = concat(kf_sum/count, surviving incr tokens)
__global__ void k_z(const float* __restrict__ x){
    int b = blockIdx.x / NFIN, r = blockIdx.x % NFIN;
    float* dst = g_z + ((size_t)b*NFIN + r)*DDIM;
    if(r < KFK){
        float invc = 1.0f / g_kfcnt[b*KFK + r];
        const float* s = g_kfsum + ((size_t)b*KFK + r)*DDIM;
        for(int i=threadIdx.x;i<DDIM;i+=256) dst[i] = s[i]*invc;
    } else {
        int tok = g_surv[b*NI0 + (r - KFK)];
        const float* s = x + ((size_t)b*TCLIP + KFT + tok)*DDIM;
        for(int i=threadIdx.x;i<DDIM;i+=256) dst[i] = s[i];
    }
}

// ---------------- fp32 SGEMM: C = act(A[M,K] @ B[K,N] + bias) ----------------
// 128x128 tile, BK=8, 256 threads, 8x8 register blocking. M,N multiples of 128,
// K multiple of 8 (true here), so no bounds checks.
__global__ __launch_bounds__(256) void sgemm128(
    const float* __restrict__ A, const float* __restrict__ B,
    const float* __restrict__ bias, float* __restrict__ C,
    int K, int N, int act)
{
    __shared__ float As[8][128];
    __shared__ float Bs[8][128];
    int tid = threadIdx.x;
    int row0 = blockIdx.y * 128, col0 = blockIdx.x * 128;
    int ar = tid >> 1, ac = (tid & 1) * 4;
    int br = tid >> 5, bc = (tid & 31) * 4;
    int ty = tid >> 4, tx = tid & 15;

    float acc[8][8];
    #pragma unroll
    for(int i=0;i<8;i++)
        #pragma unroll
        for(int j=0;j<8;j++) acc[i][j] = 0.f;

    const float* Aptr = A + (size_t)(row0 + ar)*K + ac;
    const float* Bptr = B + (size_t)br*N + col0 + bc;

    for(int k0=0;k0<K;k0+=8){
        float4 av = *(const float4*)(Aptr + k0);
        float4 bv = *(const float4*)(Bptr + (size_t)k0*N);
        As[ac+0][ar] = av.x; As[ac+1][ar] = av.y;
        As[ac+2][ar] = av.z; As[ac+3][ar] = av.w;
        *(float4*)&Bs[br][bc] = bv;
        __syncthreads();
        #pragma unroll
        for(int kk=0;kk<8;kk++){
            float a[8], bb[8];
            *(float4*)(&a[0])  = *(const float4*)(&As[kk][ty*8]);
            *(float4*)(&a[4])  = *(const float4*)(&As[kk][ty*8+4]);
            *(float4*)(&bb[0]) = *(const float4*)(&Bs[kk][tx*8]);
            *(float4*)(&bb[4]) = *(const float4*)(&Bs[kk][tx*8+4]);
            #pragma unroll
            for(int i=0;i<8;i++)
                #pragma unroll
                for(int j=0;j<8;j++) acc[i][j] += a[i]*bb[j];
        }
        __syncthreads();
    }

    #pragma unroll
    for(int i=0;i<8;i++){
        float* cp = C + (size_t)(row0 + ty*8 + i)*N + col0 + tx*8;
        float r[8];
        #pragma unroll
        for(int j=0;j<8;j++){
            float v = acc[i][j] + bias[col0 + tx*8 + j];
            if(act) v = gelu_exact(v);
            r[j] = v;
        }
        *(float4*)cp       = make_float4(r[0], r[1], r[2], r[3]);
        *((float4*)cp + 1) = make_float4(r[4], r[5], r[6], r[7]);
    }
}

// ---------------- launch ----------------
extern "C" void kernel_launch(void* const* d_in, const int* in_sizes, int n_in,
                              void* d_out, int out_size){
    (void)in_sizes; (void)n_in; (void)out_size;
    const float* x  = (const float*)d_in[0];
    const float* w1 = (const float*)d_in[1];
    const float* b1 = (const float*)d_in[2];
    const float* w2 = (const float*)d_in[3];
    const float* b2 = (const float*)d_in[4];
    float* out = (float*)d_out;

    k_normalize<<<NCLIP*TCLIP, 256>>>(x);
    k_redundancy<<<NCLIP*KFT, 256>>>();
    k_select<<<NCLIP, 256>>>();
    k_init<<<NCLIP*KFK, 256>>>(x);

    // merge schedule: n_incr 588->392->262->175->117->78->52->49
    const int nlist[7] = {588, 392, 262, 175, 117, 78, 52};
    const int mlist[7] = {196, 130,  87,  58,  39, 26,  3};
    for(int it=0; it<7; it++){
        k_avg<<<NCLIP*KFK, 256>>>();
        k_sim<<<NCLIP*nlist[it], 256>>>(nlist[it]);
        k_merge<<<NCLIP, 1024>>>(x, nlist[it], mlist[it]);
    }
    k_z<<<NCLIP*NFIN, 256>>>(x);

    float *pz, *ph;
    cudaGetSymbolAddress((void**)&pz, g_z);
    cudaGetSymbolAddress((void**)&ph, g_h);

    dim3 grid(HDIM/128, MROWS/128);
    sgemm128<<<grid, 256>>>(pz, w1, b1, ph, DDIM, HDIM, 1);
    sgemm128<<<grid, 256>>>(ph, w2, b2, out, HDIM, HDIM, 0);
}

// round 6
// speedup vs baseline: 2.0494x; 2.0494x over previous
#include <cuda_runtime.h>
#include <cuda_bf16.h>
#include <math.h>
#include <stdint.h>

// Problem constants
#define NCLIP 64
#define TCLIP 784
#define DDIM  1024
#define KFT   196
#define KFK   147
#define NI0   588
#define NFIN  196
#define HDIM  4096
#define MROWS (NCLIP*NFIN)   // 12544
#define K3_1  (3*DDIM)       // 3072
#define K3_2  (3*HDIM)       // 12288

// ---------------- scratch (device globals; no allocations allowed) ----------
__device__ float g_kfn  [NCLIP*KFT*DDIM];
__device__ float g_incrn[NCLIP*NI0*DDIM];
__device__ float g_red  [NCLIP*KFT];
__device__ int   g_keep [NCLIP*KFK];
__device__ float g_kfsum[NCLIP*KFK*DDIM];
__device__ float g_kfcnt[NCLIP*KFK];
__device__ float g_kfavgn[NCLIP*KFK*DDIM];
__device__ float g_maxsim[NCLIP*NI0];
__device__ int   g_bestkf[NCLIP*NI0];
__device__ int   g_surv [NCLIP*NI0];
__device__ float g_z    [NCLIP*NFIN*DDIM];

// split-bf16 operands
__device__ __nv_bfloat16 g_A1 [(size_t)MROWS*K3_1];   // z  -> [hi|lo|hi]
__device__ __nv_bfloat16 g_A2 [(size_t)MROWS*K3_2];   // h  -> [hi|lo|hi]
__device__ __nv_bfloat16 g_Bt1[(size_t)HDIM*K3_1];    // w1^T segs [Bhi|Bhi|Blo]
__device__ __nv_bfloat16 g_Bt2[(size_t)HDIM*K3_2];    // w2^T segs

// ---------------- low-level helpers ----------------
__device__ __forceinline__ uint32_t smem_to_u32(const void* p){
    uint32_t a;
    asm("{ .reg .u64 t; cvta.to.shared.u64 t, %1; cvt.u32.u64 %0, t; }" : "=r"(a) : "l"(p));
    return a;
}
#define SW128(off) ((off) ^ (((off) >> 3) & 0x70))

__device__ __forceinline__ void cp_async16(uint32_t saddr, const void* gaddr){
    asm volatile("cp.async.cg.shared.global [%0], [%1], 16;" :: "r"(saddr), "l"(gaddr));
}
__device__ __forceinline__ void cp_commit(){ asm volatile("cp.async.commit_group;" ::: "memory"); }
__device__ __forceinline__ void cp_wait1(){ asm volatile("cp.async.wait_group 1;" ::: "memory"); }

__device__ __forceinline__ void ldmx4(uint32_t* r, uint32_t addr){
    asm volatile("ldmatrix.sync.aligned.m8n8.x4.shared.b16 {%0,%1,%2,%3}, [%4];"
        : "=r"(r[0]), "=r"(r[1]), "=r"(r[2]), "=r"(r[3]) : "r"(addr));
}
__device__ __forceinline__ void mma16816(float* c, const uint32_t* a, uint32_t b0, uint32_t b1){
    asm volatile("mma.sync.aligned.m16n8k16.row.col.f32.bf16.bf16.f32 "
        "{%0,%1,%2,%3}, {%4,%5,%6,%7}, {%8,%9}, {%0,%1,%2,%3};"
        : "+f"(c[0]), "+f"(c[1]), "+f"(c[2]), "+f"(c[3])
        : "r"(a[0]), "r"(a[1]), "r"(a[2]), "r"(a[3]), "r"(b0), "r"(b1));
}

// ---------------- generic helpers ----------------
__device__ __forceinline__ float blockSum256(float v){
    __shared__ float sh[8];
    int lane = threadIdx.x & 31, w = threadIdx.x >> 5;
    #pragma unroll
    for(int o=16;o;o>>=1) v += __shfl_xor_sync(0xffffffffu, v, o);
    if(lane==0) sh[w] = v;
    __syncthreads();
    float r = (threadIdx.x < 8) ? sh[threadIdx.x] : 0.f;
    if(w==0){
        #pragma unroll
        for(int o=4;o;o>>=1) r += __shfl_xor_sync(0xffffffffu, r, o);
        if(lane==0) sh[0] = r;
    }
    __syncthreads();
    float out = sh[0];
    __syncthreads();
    return out;
}

__device__ __forceinline__ void bitonic_sort(float* key, int* pos, int N){
    int t = threadIdx.x;
    for(int k=2;k<=N;k<<=1){
        for(int j=k>>1;j>0;j>>=1){
            __syncthreads();
            int ixj = t ^ j;
            if(ixj > t){
                float ka = key[t], kb = key[ixj];
                int   pa = pos[t], pb = pos[ixj];
                bool agtb = (ka > kb) || (ka == kb && pa > pb);
                bool up = ((t & k) == 0);
                if(agtb == up){
                    key[t]=kb; key[ixj]=ka;
                    pos[t]=pb; pos[ixj]=pa;
                }
            }
        }
    }
    __syncthreads();
}

__device__ __forceinline__ float gelu_exact(float v){
    return 0.5f * v * (1.0f + erff(v * 0.70710678118654752440f));
}

// ---------------- compression kernels (unchanged, correct since R2) ---------
__global__ void k_normalize(const float* __restrict__ x){
    int b = blockIdx.x / TCLIP;
    int r = blockIdx.x % TCLIP;
    const float* row = x + ((size_t)b*TCLIP + r)*DDIM;
    float ss = 0.f;
    for(int i=threadIdx.x;i<DDIM;i+=256){ float v = row[i]; ss += v*v; }
    ss = blockSum256(ss);
    float inv = 1.0f / fmaxf(sqrtf(ss), 1e-12f);
    float* dst = (r < KFT) ? (g_kfn   + ((size_t)b*KFT + r)*DDIM)
                           : (g_incrn + ((size_t)b*NI0 + (r - KFT))*DDIM);
    for(int i=threadIdx.x;i<DDIM;i+=256) dst[i] = row[i]*inv;
}

__global__ void k_redundancy(){
    int b = blockIdx.x / KFT;
    int i = blockIdx.x % KFT;
    __shared__ float rowi[DDIM];
    const float* ri = g_kfn + ((size_t)b*KFT + i)*DDIM;
    for(int t=threadIdx.x;t<DDIM;t+=256) rowi[t] = ri[t];
    __syncthreads();
    int w = threadIdx.x >> 5, lane = threadIdx.x & 31;
    const float4* rowi4 = (const float4*)rowi;
    float acc = 0.f;
    for(int j=w;j<KFT;j+=8){
        const float4* rj = (const float4*)(g_kfn + ((size_t)b*KFT + j)*DDIM);
        float s = 0.f;
        #pragma unroll
        for(int it=0;it<8;it++){
            float4 a = rowi4[lane + it*32];
            float4 c = rj  [lane + it*32];
            s += a.x*c.x + a.y*c.y + a.z*c.z + a.w*c.w;
        }
        #pragma unroll
        for(int o=16;o;o>>=1) s += __shfl_xor_sync(0xffffffffu, s, o);
        acc += s;
    }
    __shared__ float part[8];
    if(lane==0) part[w] = acc;
    __syncthreads();
    if(threadIdx.x==0){
        float r = 0.f;
        for(int q=0;q<8;q++) r += part[q];
        g_red[b*KFT + i] = r - 1.0f;
    }
}

__global__ void k_select(){
    int b = blockIdx.x;
    __shared__ float key[256];
    __shared__ int   pos[256];
    __shared__ unsigned char kept[KFT];
    int t = threadIdx.x;
    key[t] = (t < KFT) ? g_red[b*KFT + t] : __int_as_float(0x7f800000);
    pos[t] = t;
    if(t < KFT) kept[t] = 0;
    bitonic_sort(key, pos, 256);
    if(t < KFK) kept[pos[t]] = 1;
    __syncthreads();
    if(t==0){
        int c = 0;
        for(int i=0;i<KFT;i++) if(kept[i]) g_keep[b*KFK + (c++)] = i;
    }
    for(int s=t;s<NI0;s+=256) g_surv[b*NI0 + s] = s;
}

__global__ void k_init(const float* __restrict__ x){
    int b = blockIdx.x / KFK, k = blockIdx.x % KFK;
    int src = g_keep[b*KFK + k];
    const float* row = x + ((size_t)b*TCLIP + src)*DDIM;
    float* dst = g_kfsum + ((size_t)b*KFK + k)*DDIM;
    for(int i=threadIdx.x;i<DDIM;i+=256) dst[i] = row[i];
    if(threadIdx.x==0) g_kfcnt[b*KFK + k] = 1.0f;
}

__global__ void k_avg(){
    int b = blockIdx.x / KFK, k = blockIdx.x % KFK;
    const float* s = g_kfsum + ((size_t)b*KFK + k)*DDIM;
    float invc = 1.0f / g_kfcnt[b*KFK + k];
    float ss = 0.f;
    for(int i=threadIdx.x;i<DDIM;i+=256){ float v = s[i]*invc; ss += v*v; }
    ss = blockSum256(ss);
    float inv = invc / fmaxf(sqrtf(ss), 1e-12f);
    float* dst = g_kfavgn + ((size_t)b*KFK + k)*DDIM;
    for(int i=threadIdx.x;i<DDIM;i+=256) dst[i] = s[i]*inv;
}

__global__ void k_sim(int n){
    int b = blockIdx.x / n, s = blockIdx.x % n;
    int tok = g_surv[b*NI0 + s];
    __shared__ float rowi[DDIM];
    const float* ri = g_incrn + ((size_t)b*NI0 + tok)*DDIM;
    for(int t=threadIdx.x;t<DDIM;t+=256) rowi[t] = ri[t];
    __syncthreads();
    int w = threadIdx.x >> 5, lane = threadIdx.x & 31;
    const float4* rowi4 = (const float4*)rowi;
    float best = -3.0e38f; int bestk = 0x7fffffff;
    for(int k=w;k<KFK;k+=8){
        const float4* rk = (const float4*)(g_kfavgn + ((size_t)b*KFK + k)*DDIM);
        float sum = 0.f;
        #pragma unroll
        for(int it=0;it<8;it++){
            float4 a = rowi4[lane + it*32];
            float4 c = rk  [lane + it*32];
            sum += a.x*c.x + a.y*c.y + a.z*c.z + a.w*c.w;
        }
        #pragma unroll
        for(int o=16;o;o>>=1) sum += __shfl_xor_sync(0xffffffffu, sum, o);
        if(sum > best){ best = sum; bestk = k; }
    }
    __shared__ float bv[8]; __shared__ int bk[8];
    if(lane==0){ bv[w] = best; bk[w] = bestk; }
    __syncthreads();
    if(threadIdx.x==0){
        float B0 = bv[0]; int K0 = bk[0];
        for(int q=1;q<8;q++)
            if(bv[q] > B0 || (bv[q] == B0 && bk[q] < K0)){ B0 = bv[q]; K0 = bk[q]; }
        g_maxsim[b*NI0 + s] = B0;
        g_bestkf[b*NI0 + s] = K0;
    }
}

__global__ void k_merge(const float* __restrict__ x, int n, int nm){
    int b = blockIdx.x, t = threadIdx.x;
    __shared__ float key[1024];
    __shared__ int   pos[1024];
    __shared__ int   mpos[196], mtgt[196], mtok[196];
    __shared__ unsigned char mflag[NI0];
    key[t] = (t < n) ? -g_maxsim[b*NI0 + t] : __int_as_float(0x7f800000);
    pos[t] = t;
    bitonic_sort(key, pos, 1024);
    if(t < nm){
        int p = pos[t];
        mpos[t] = p;
        mtgt[t] = g_bestkf[b*NI0 + p];
        mtok[t] = g_surv  [b*NI0 + p];
    }
    __syncthreads();
    for(int m=0;m<nm;m++){
        int tgt = mtgt[m], tok = mtok[m];
        const float* feat = x + ((size_t)b*TCLIP + KFT + tok)*DDIM;
        float* dst = g_kfsum + ((size_t)b*KFK + tgt)*DDIM;
        dst[t] += feat[t];
        if(t==0) g_kfcnt[b*KFK + tgt] += 1.0f;
    }
    for(int i=t;i<n;i+=1024) mflag[i] = 0;
    __syncthreads();
    if(t < nm) mflag[mpos[t]] = 1;
    __syncthreads();
    if(t==0){
        int c = 0;
        for(int p=0;p<n;p++)
            if(!mflag[p]){ int v = g_surv[b*NI0 + p]; g_surv[b*NI0 + c] = v; c++; }
    }
}

__global__ void k_z(const float* __restrict__ x){
    int b = blockIdx.x / NFIN, r = blockIdx.x % NFIN;
    float* dst = g_z + ((size_t)b*NFIN + r)*DDIM;
    if(r < KFK){
        float invc = 1.0f / g_kfcnt[b*KFK + r];
        const float* s = g_kfsum + ((size_t)b*KFK + r)*DDIM;
        for(int i=threadIdx.x;i<DDIM;i+=256) dst[i] = s[i]*invc;
    } else {
        int tok = g_surv[b*NI0 + (r - KFK)];
        const float* s = x + ((size_t)b*TCLIP + KFT + tok)*DDIM;
        for(int i=threadIdx.x;i<DDIM;i+=256) dst[i] = s[i];
    }
}

// ---------------- split-bf16 conversions ----------------
__global__ void k_splitA(const float* __restrict__ src, __nv_bfloat16* __restrict__ dst, int K){
    int row = blockIdx.x;
    const float* s = src + (size_t)row*K;
    __nv_bfloat16* d = dst + (size_t)row*3*K;
    for(int i=threadIdx.x;i<K;i+=256){
        float v = s[i];
        __nv_bfloat16 h = __float2bfloat16(v);
        __nv_bfloat16 l = __float2bfloat16(v - __bfloat162float(h));
        d[i] = h; d[K+i] = l; d[2*K+i] = h;
    }
}

__global__ void k_splitW(const float* __restrict__ w, __nv_bfloat16* __restrict__ bt, int K, int N){
    __shared__ float tile[32][33];
    int kb = blockIdx.y*32, nb = blockIdx.x*32;
    int tx = threadIdx.x & 31, ty = threadIdx.x >> 5;
    for(int i=ty;i<32;i+=8) tile[i][tx] = w[(size_t)(kb+i)*N + nb + tx];
    __syncthreads();
    for(int i=ty;i<32;i+=8){
        float v = tile[tx][i];
        __nv_bfloat16 h = __float2bfloat16(v);
        __nv_bfloat16 l = __float2bfloat16(v - __bfloat162float(h));
        size_t base = (size_t)(nb+i)*3*K + kb + tx;
        bt[base]       = h;
        bt[base + K]   = h;
        bt[base + 2*K] = l;
    }
}

// ---------------- HMMA (mma.sync) bf16 GEMM ----------------
// C[M, 4096] = A3[M, K3] * Bt[4096, K3]^T ; CTA tile 128x128, BK=64, 3 stages.
// mode 0: outF = acc + bias (fp32)
// mode 1: outS = split-bf16(gelu(acc+bias)) in [hi|lo|hi] layout (stride 12288)
#define BM 128
#define BN 128
#define BK 64
#define NSTAGE 3
#define ABYTES (BM*128)            // 16KB
#define STAGE_BYTES (ABYTES + BN*128)  // 32KB
#define SMEM_GEMM (NSTAGE*STAGE_BYTES) // 96KB

__global__ void __launch_bounds__(256, 2) mma_gemm(
    const __nv_bfloat16* __restrict__ A3, const __nv_bfloat16* __restrict__ Bt,
    const float* __restrict__ bias, float* __restrict__ outF,
    __nv_bfloat16* __restrict__ outS, int K3, int mode)
{
    extern __shared__ char smem[];
    uint32_t sb = smem_to_u32(smem);
    int tid = threadIdx.x, wid = tid >> 5, l = tid & 31;
    int row0 = blockIdx.y * BM, col0 = blockIdx.x * BN;
    int wm = wid & 3, wn = wid >> 2;     // warps 4(m) x 2(n); warp tile 32x64
    int T = K3 / BK;

    // per-thread cp.async source/dest precompute
    int ldr = tid >> 1;                  // 0..127 rows (2 thread-chunks/row? no:)
    (void)ldr;

    float acc[2][8][4];
    #pragma unroll
    for(int mt=0;mt<2;mt++)
        #pragma unroll
        for(int nt=0;nt<8;nt++)
            #pragma unroll
            for(int q=0;q<4;q++) acc[mt][nt][q] = 0.f;

    // ldmatrix per-lane address components
    int ra   = wm*32 + (l & 15);         // A row within tile (+mt*16)
    int ca16 = (l >> 4) * 16;            // A byte col (16B unit)
    int rb   = wn*64 + (l & 7) + ((l >> 4) << 3);  // B row (+ntp*16)
    int cb16 = ((l >> 3) & 1) * 16;      // B byte col

    #define LOAD_STAGE(s, buf) { \
        uint32_t base_ = sb + (buf)*STAGE_BYTES; \
        int k0_ = (s)*BK; \
        const __nv_bfloat16* Ap_ = A3 + (size_t)row0*K3 + k0_; \
        const __nv_bfloat16* Bp_ = Bt + (size_t)col0*K3 + k0_; \
        _Pragma("unroll") \
        for(int i_=0;i_<4;i_++){ \
            int u_ = tid + i_*256; \
            int r_ = u_ >> 3, sg_ = u_ & 7; \
            cp_async16(base_ + SW128((uint32_t)(r_*128 + sg_*16)), Ap_ + (size_t)r_*K3 + sg_*8); \
        } \
        _Pragma("unroll") \
        for(int i_=0;i_<4;i_++){ \
            int u_ = tid + i_*256; \
            int r_ = u_ >> 3, sg_ = u_ & 7; \
            cp_async16(base_ + ABYTES + SW128((uint32_t)(r_*128 + sg_*16)), Bp_ + (size_t)r_*K3 + sg_*8); \
        } }

    LOAD_STAGE(0, 0); cp_commit();
    LOAD_STAGE(1, 1); cp_commit();

    for(int t=0; t<T; t++){
        cp_wait1();
        __syncthreads();
        if(t+2 < T){
            int nb = (t+2) % NSTAGE;
            LOAD_STAGE(t+2, nb);
        }
        cp_commit();

        uint32_t abase = sb + (t % NSTAGE)*STAGE_BYTES;
        uint32_t bbase = abase + ABYTES;
        #pragma unroll
        for(int ks=0; ks<4; ks++){
            uint32_t a[2][4];
            #pragma unroll
            for(int mt=0; mt<2; mt++)
                ldmx4(a[mt], abase + SW128((uint32_t)((ra + mt*16)*128 + ks*32 + ca16)));
            #pragma unroll
            for(int ntp=0; ntp<4; ntp++){
                uint32_t b[4];
                ldmx4(b, bbase + SW128((uint32_t)((rb + ntp*16)*128 + ks*32 + cb16)));
                #pragma unroll
                for(int mt=0; mt<2; mt++){
                    mma16816(acc[mt][ntp*2],   a[mt], b[0], b[1]);
                    mma16816(acc[mt][ntp*2+1], a[mt], b[2], b[3]);
                }
            }
        }
    }

    // ---- epilogue ----
    #pragma unroll
    for(int mt=0; mt<2; mt++){
        #pragma unroll
        for(int nt=0; nt<8; nt++){
            float* a4 = acc[mt][nt];
            int r = row0 + wm*32 + mt*16 + (l >> 2);
            int c = col0 + wn*64 + nt*8 + ((l & 3) << 1);
            float bi0 = bias[c], bi1 = bias[c+1];
            if(mode == 0){
                float2 v0; v0.x = a4[0] + bi0; v0.y = a4[1] + bi1;
                float2 v1; v1.x = a4[2] + bi0; v1.y = a4[3] + bi1;
                *(float2*)(outF + (size_t)r*HDIM + c)     = v0;
                *(float2*)(outF + (size_t)(r+8)*HDIM + c) = v1;
            } else {
                #pragma unroll
                for(int hrow=0; hrow<2; hrow++){
                    float v0 = gelu_exact(a4[hrow*2+0] + bi0);
                    float v1 = gelu_exact(a4[hrow*2+1] + bi1);
                    __nv_bfloat16 h0 = __float2bfloat16(v0);
                    __nv_bfloat16 h1 = __float2bfloat16(v1);
                    __nv_bfloat16 l0 = __float2bfloat16(v0 - __bfloat162float(h0));
                    __nv_bfloat16 l1 = __float2bfloat16(v1 - __bfloat162float(h1));
                    __nv_bfloat162 hh; hh.x = h0; hh.y = h1;
                    __nv_bfloat162 ll; ll.x = l0; ll.y = l1;
                    size_t rbse = (size_t)(r + hrow*8) * K3_2;
                    *(__nv_bfloat162*)(outS + rbse + c)          = hh;
                    *(__nv_bfloat162*)(outS + rbse + HDIM + c)   = ll;
                    *(__nv_bfloat162*)(outS + rbse + 2*HDIM + c) = hh;
                }
            }
        }
    }
}

// ---------------- launch ----------------
extern "C" void kernel_launch(void* const* d_in, const int* in_sizes, int n_in,
                              void* d_out, int out_size){
    (void)in_sizes; (void)n_in; (void)out_size;
    const float* x  = (const float*)d_in[0];
    const float* w1 = (const float*)d_in[1];
    const float* b1 = (const float*)d_in[2];
    const float* w2 = (const float*)d_in[3];
    const float* b2 = (const float*)d_in[4];
    float* out = (float*)d_out;

    __nv_bfloat16 *pBt1, *pBt2, *pA1, *pA2;
    float* pz;
    cudaGetSymbolAddress((void**)&pBt1, g_Bt1);
    cudaGetSymbolAddress((void**)&pBt2, g_Bt2);
    cudaGetSymbolAddress((void**)&pA1, g_A1);
    cudaGetSymbolAddress((void**)&pA2, g_A2);
    cudaGetSymbolAddress((void**)&pz,  g_z);

    k_splitW<<<dim3(HDIM/32, DDIM/32), 256>>>(w1, pBt1, DDIM, HDIM);
    k_splitW<<<dim3(HDIM/32, HDIM/32), 256>>>(w2, pBt2, HDIM, HDIM);

    k_normalize<<<NCLIP*TCLIP, 256>>>(x);
    k_redundancy<<<NCLIP*KFT, 256>>>();
    k_select<<<NCLIP, 256>>>();
    k_init<<<NCLIP*KFK, 256>>>(x);

    const int nlist[7] = {588, 392, 262, 175, 117, 78, 52};
    const int mlist[7] = {196, 130,  87,  58,  39, 26,  3};
    for(int it=0; it<7; it++){
        k_avg<<<NCLIP*KFK, 256>>>();
        k_sim<<<NCLIP*nlist[it], 256>>>(nlist[it]);
        k_merge<<<NCLIP, 1024>>>(x, nlist[it], mlist[it]);
    }
    k_z<<<NCLIP*NFIN, 256>>>(x);
    k_splitA<<<MROWS, 256>>>(pz, pA1, DDIM);

    cudaFuncSetAttribute(mma_gemm, cudaFuncAttributeMaxDynamicSharedMemorySize, SMEM_GEMM);
    dim3 grid(HDIM/BN, MROWS/BM);   // (32, 98)
    mma_gemm<<<grid, 256, SMEM_GEMM>>>(pA1, pBt1, b1, nullptr, pA2, K3_1, 1);
    mma_gemm<<<grid, 256, SMEM_GEMM>>>(pA2, pBt2, b2, out, nullptr, K3_2, 0);
}

// round 7
// speedup vs baseline: 2.3261x; 1.1350x over previous
#include <cuda_runtime.h>
#include <cuda_bf16.h>
#include <math.h>
#include <stdint.h>

// Problem constants
#define NCLIP 64
#define TCLIP 784
#define DDIM  1024
#define KFT   196
#define KFK   147
#define NI0   588
#define NFIN  196
#define HDIM  4096
#define MROWS (NCLIP*NFIN)   // 12544

// ---------------- scratch (device globals; no allocations allowed) ----------
__device__ float g_kfn  [NCLIP*KFT*DDIM];
__device__ float g_incrn[NCLIP*NI0*DDIM];
__device__ float g_red  [NCLIP*KFT];
__device__ int   g_keep [NCLIP*KFK];
__device__ float g_kfsum[NCLIP*KFK*DDIM];
__device__ float g_kfcnt[NCLIP*KFK];
__device__ float g_kfavgn[NCLIP*KFK*DDIM];
__device__ float g_maxsim[NCLIP*NI0];
__device__ int   g_bestkf[NCLIP*NI0];
__device__ int   g_surv [NCLIP*NI0];
__device__ float g_z    [NCLIP*NFIN*DDIM];

// split-bf16 operands: [hi | lo] along K (row stride 2K)
__device__ __nv_bfloat16 g_A1 [(size_t)MROWS*2*DDIM];   // z split
__device__ __nv_bfloat16 g_A2 [(size_t)MROWS*2*HDIM];   // h split
__device__ __nv_bfloat16 g_Bt1[(size_t)HDIM*2*DDIM];    // w1^T split
__device__ __nv_bfloat16 g_Bt2[(size_t)HDIM*2*HDIM];    // w2^T split

// ---------------- low-level helpers ----------------
__device__ __forceinline__ uint32_t smem_to_u32(const void* p){
    uint32_t a;
    asm("{ .reg .u64 t; cvta.to.shared.u64 t, %1; cvt.u32.u64 %0, t; }" : "=r"(a) : "l"(p));
    return a;
}
#define SW128(off) ((off) ^ (((off) >> 3) & 0x70))

__device__ __forceinline__ void cp_async16(uint32_t saddr, const void* gaddr){
    asm volatile("cp.async.cg.shared.global [%0], [%1], 16;" :: "r"(saddr), "l"(gaddr));
}
__device__ __forceinline__ void cp_commit(){ asm volatile("cp.async.commit_group;" ::: "memory"); }
__device__ __forceinline__ void cp_wait2(){ asm volatile("cp.async.wait_group 2;" ::: "memory"); }

__device__ __forceinline__ void ldmx4(uint32_t* r, uint32_t addr){
    asm volatile("ldmatrix.sync.aligned.m8n8.x4.shared.b16 {%0,%1,%2,%3}, [%4];"
        : "=r"(r[0]), "=r"(r[1]), "=r"(r[2]), "=r"(r[3]) : "r"(addr));
}
__device__ __forceinline__ void mma16816(float* c, const uint32_t* a, uint32_t b0, uint32_t b1){
    asm volatile("mma.sync.aligned.m16n8k16.row.col.f32.bf16.bf16.f32 "
        "{%0,%1,%2,%3}, {%4,%5,%6,%7}, {%8,%9}, {%0,%1,%2,%3};"
        : "+f"(c[0]), "+f"(c[1]), "+f"(c[2]), "+f"(c[3])
        : "r"(a[0]), "r"(a[1]), "r"(a[2]), "r"(a[3]), "r"(b0), "r"(b1));
}

// ---------------- generic helpers ----------------
__device__ __forceinline__ float blockSum256(float v){
    __shared__ float sh[8];
    int lane = threadIdx.x & 31, w = threadIdx.x >> 5;
    #pragma unroll
    for(int o=16;o;o>>=1) v += __shfl_xor_sync(0xffffffffu, v, o);
    if(lane==0) sh[w] = v;
    __syncthreads();
    float r = (threadIdx.x < 8) ? sh[threadIdx.x] : 0.f;
    if(w==0){
        #pragma unroll
        for(int o=4;o;o>>=1) r += __shfl_xor_sync(0xffffffffu, r, o);
        if(lane==0) sh[0] = r;
    }
    __syncthreads();
    float out = sh[0];
    __syncthreads();
    return out;
}

__device__ __forceinline__ void bitonic_sort(float* key, int* pos, int N){
    int t = threadIdx.x;
    for(int k=2;k<=N;k<<=1){
        for(int j=k>>1;j>0;j>>=1){
            __syncthreads();
            int ixj = t ^ j;
            if(ixj > t){
                float ka = key[t], kb = key[ixj];
                int   pa = pos[t], pb = pos[ixj];
                bool agtb = (ka > kb) || (ka == kb && pa > pb);
                bool up = ((t & k) == 0);
                if(agtb == up){
                    key[t]=kb; key[ixj]=ka;
                    pos[t]=pb; pos[ixj]=pa;
                }
            }
        }
    }
    __syncthreads();
}

__device__ __forceinline__ float gelu_exact(float v){
    return 0.5f * v * (1.0f + erff(v * 0.70710678118654752440f));
}

// ---------------- compression kernels ----------------
__global__ void k_normalize(const float* __restrict__ x){
    int b = blockIdx.x / TCLIP;
    int r = blockIdx.x % TCLIP;
    const float* row = x + ((size_t)b*TCLIP + r)*DDIM;
    float ss = 0.f;
    for(int i=threadIdx.x;i<DDIM;i+=256){ float v = row[i]; ss += v*v; }
    ss = blockSum256(ss);
    float inv = 1.0f / fmaxf(sqrtf(ss), 1e-12f);
    float* dst = (r < KFT) ? (g_kfn   + ((size_t)b*KFT + r)*DDIM)
                           : (g_incrn + ((size_t)b*NI0 + (r - KFT))*DDIM);
    for(int i=threadIdx.x;i<DDIM;i+=256) dst[i] = row[i]*inv;
}

__global__ void k_redundancy(){
    int b = blockIdx.x / KFT;
    int i = blockIdx.x % KFT;
    __shared__ float rowi[DDIM];
    const float* ri = g_kfn + ((size_t)b*KFT + i)*DDIM;
    for(int t=threadIdx.x;t<DDIM;t+=256) rowi[t] = ri[t];
    __syncthreads();
    int w = threadIdx.x >> 5, lane = threadIdx.x & 31;
    const float4* rowi4 = (const float4*)rowi;
    float acc = 0.f;
    for(int j=w;j<KFT;j+=8){
        const float4* rj = (const float4*)(g_kfn + ((size_t)b*KFT + j)*DDIM);
        float s = 0.f;
        #pragma unroll
        for(int it=0;it<8;it++){
            float4 a = rowi4[lane + it*32];
            float4 c = rj  [lane + it*32];
            s += a.x*c.x + a.y*c.y + a.z*c.z + a.w*c.w;
        }
        #pragma unroll
        for(int o=16;o;o>>=1) s += __shfl_xor_sync(0xffffffffu, s, o);
        acc += s;
    }
    __shared__ float part[8];
    if(lane==0) part[w] = acc;
    __syncthreads();
    if(threadIdx.x==0){
        float r = 0.f;
        for(int q=0;q<8;q++) r += part[q];
        g_red[b*KFT + i] = r - 1.0f;
    }
}

__global__ void k_select(){
    int b = blockIdx.x;
    __shared__ float key[256];
    __shared__ int   pos[256];
    __shared__ unsigned char kept[KFT];
    int t = threadIdx.x;
    key[t] = (t < KFT) ? g_red[b*KFT + t] : __int_as_float(0x7f800000);
    pos[t] = t;
    if(t < KFT) kept[t] = 0;
    bitonic_sort(key, pos, 256);
    if(t < KFK) kept[pos[t]] = 1;
    __syncthreads();
    if(t==0){
        int c = 0;
        for(int i=0;i<KFT;i++) if(kept[i]) g_keep[b*KFK + (c++)] = i;
    }
    for(int s=t;s<NI0;s+=256) g_surv[b*NI0 + s] = s;
}

__global__ void k_init(const float* __restrict__ x){
    int b = blockIdx.x / KFK, k = blockIdx.x % KFK;
    int src = g_keep[b*KFK + k];
    const float* row = x + ((size_t)b*TCLIP + src)*DDIM;
    float* dst = g_kfsum + ((size_t)b*KFK + k)*DDIM;
    for(int i=threadIdx.x;i<DDIM;i+=256) dst[i] = row[i];
    if(threadIdx.x==0) g_kfcnt[b*KFK + k] = 1.0f;
}

__global__ void k_avg(){
    int b = blockIdx.x / KFK, k = blockIdx.x % KFK;
    const float* s = g_kfsum + ((size_t)b*KFK + k)*DDIM;
    float invc = 1.0f / g_kfcnt[b*KFK + k];
    float ss = 0.f;
    for(int i=threadIdx.x;i<DDIM;i+=256){ float v = s[i]*invc; ss += v*v; }
    ss = blockSum256(ss);
    float inv = invc / fmaxf(sqrtf(ss), 1e-12f);
    float* dst = g_kfavgn + ((size_t)b*KFK + k)*DDIM;
    for(int i=threadIdx.x;i<DDIM;i+=256) dst[i] = s[i]*inv;
}

// ---- tiled sim: CTA = (64-token tile, clip). thread tile: 5 kf x 8 tokens ----
// smem: kf chunk 160x64 fp32 (16B-col XOR swizzled) + incr chunk 64x64 fp32
#define SIM_SMEM (160*64*4 + 64*64*4)   // 40KB + 16KB
__global__ void __launch_bounds__(256) k_sim_tiled(int n){
    extern __shared__ float sm[];
    float4* kf4 = (float4*)sm;                 // 160*16 float4
    float4* in4 = (float4*)(sm + 160*64);      // 64*16 float4
    int b = blockIdx.y;
    int tile0 = blockIdx.x * 64;
    int tid = threadIdx.x;
    int tkf = tid & 31;         // kf lane
    int ttok = tid >> 5;        // warp id -> token octet
    int swz = tkf & 7;

    float acc[5][8];
    #pragma unroll
    for(int i=0;i<5;i++)
        #pragma unroll
        for(int j=0;j<8;j++) acc[i][j] = 0.f;

    for(int dc=0; dc<16; dc++){
        int d0 = dc*64;
        // load kf chunk: 2560 float4
        for(int idx=tid; idx<2560; idx+=256){
            int row = idx >> 4, g = idx & 15;
            float4 v = make_float4(0.f,0.f,0.f,0.f);
            if(row < KFK)
                v = *(const float4*)(g_kfavgn + ((size_t)b*KFK + row)*DDIM + d0 + g*4);
            kf4[(row<<4) + (g ^ (row & 7))] = v;
        }
        // load incr chunk: 1024 float4 (token indirection via g_surv)
        for(int idx=tid; idx<1024; idx+=256){
            int row = idx >> 4, g = idx & 15;
            int s = tile0 + row;
            float4 v = make_float4(0.f,0.f,0.f,0.f);
            if(s < n){
                int tok = g_surv[b*NI0 + s];
                v = *(const float4*)(g_incrn + ((size_t)b*NI0 + tok)*DDIM + d0 + g*4);
            }
            in4[(row<<4) + g] = v;
        }
        __syncthreads();
        #pragma unroll
        for(int dg=0; dg<16; dg++){
            float4 kv[5];
            #pragma unroll
            for(int i=0;i<5;i++)
                kv[i] = kf4[((tkf + 32*i)<<4) + (dg ^ swz)];
            #pragma unroll
            for(int jj=0; jj<8; jj++){
                float4 iv = in4[((ttok*8 + jj)<<4) + dg];
                #pragma unroll
                for(int i=0;i<5;i++)
                    acc[i][jj] += kv[i].x*iv.x + kv[i].y*iv.y + kv[i].z*iv.z + kv[i].w*iv.w;
            }
        }
        __syncthreads();
    }

    // per-token first-argmax over 147 kf
    #pragma unroll
    for(int jj=0; jj<8; jj++){
        float best = -3.0e38f; int bk = 0x7fffffff;
        #pragma unroll
        for(int i=0;i<5;i++){
            int k = tkf + 32*i;
            if(k < KFK && acc[i][jj] > best){ best = acc[i][jj]; bk = k; }
        }
        #pragma unroll
        for(int o=16;o;o>>=1){
            float ov = __shfl_xor_sync(0xffffffffu, best, o);
            int   ok = __shfl_xor_sync(0xffffffffu, bk, o);
            if(ov > best || (ov == best && ok < bk)){ best = ov; bk = ok; }
        }
        int s = tile0 + ttok*8 + jj;
        if(tkf == 0 && s < n){
            g_maxsim[b*NI0 + s] = best;
            g_bestkf[b*NI0 + s] = bk;
        }
    }
}

__global__ void k_merge(const float* __restrict__ x, int n, int nm){
    int b = blockIdx.x, t = threadIdx.x;
    __shared__ float key[1024];
    __shared__ int   pos[1024];
    __shared__ int   mpos[196], mtgt[196], mtok[196];
    __shared__ unsigned char mflag[NI0];
    key[t] = (t < n) ? -g_maxsim[b*NI0 + t] : __int_as_float(0x7f800000);
    pos[t] = t;
    bitonic_sort(key, pos, 1024);
    if(t < nm){
        int p = pos[t];
        mpos[t] = p;
        mtgt[t] = g_bestkf[b*NI0 + p];
        mtok[t] = g_surv  [b*NI0 + p];
    }
    __syncthreads();
    for(int m=0;m<nm;m++){
        int tgt = mtgt[m], tok = mtok[m];
        const float* feat = x + ((size_t)b*TCLIP + KFT + tok)*DDIM;
        float* dst = g_kfsum + ((size_t)b*KFK + tgt)*DDIM;
        dst[t] += feat[t];
        if(t==0) g_kfcnt[b*KFK + tgt] += 1.0f;
    }
    for(int i=t;i<n;i+=1024) mflag[i] = 0;
    __syncthreads();
    if(t < nm) mflag[mpos[t]] = 1;
    __syncthreads();
    if(t==0){
        int c = 0;
        for(int p=0;p<n;p++)
            if(!mflag[p]){ int v = g_surv[b*NI0 + p]; g_surv[b*NI0 + c] = v; c++; }
    }
}

__global__ void k_z(const float* __restrict__ x){
    int b = blockIdx.x / NFIN, r = blockIdx.x % NFIN;
    float* dst = g_z + ((size_t)b*NFIN + r)*DDIM;
    if(r < KFK){
        float invc = 1.0f / g_kfcnt[b*KFK + r];
        const float* s = g_kfsum + ((size_t)b*KFK + r)*DDIM;
        for(int i=threadIdx.x;i<DDIM;i+=256) dst[i] = s[i]*invc;
    } else {
        int tok = g_surv[b*NI0 + (r - KFK)];
        const float* s = x + ((size_t)b*TCLIP + KFT + tok)*DDIM;
        for(int i=threadIdx.x;i<DDIM;i+=256) dst[i] = s[i];
    }
}

// ---------------- split-bf16 conversions: [hi | lo], row stride 2K ----------
__global__ void k_splitA(const float* __restrict__ src, __nv_bfloat16* __restrict__ dst, int K){
    int row = blockIdx.x;
    const float* s = src + (size_t)row*K;
    __nv_bfloat16* d = dst + (size_t)row*2*K;
    for(int i=threadIdx.x;i<K;i+=256){
        float v = s[i];
        __nv_bfloat16 h = __float2bfloat16(v);
        __nv_bfloat16 l = __float2bfloat16(v - __bfloat162float(h));
        d[i] = h; d[K+i] = l;
    }
}

__global__ void k_splitW(const float* __restrict__ w, __nv_bfloat16* __restrict__ bt, int K, int N){
    __shared__ float tile[32][33];
    int kb = blockIdx.y*32, nb = blockIdx.x*32;
    int tx = threadIdx.x & 31, ty = threadIdx.x >> 5;
    for(int i=ty;i<32;i+=8) tile[i][tx] = w[(size_t)(kb+i)*N + nb + tx];
    __syncthreads();
    for(int i=ty;i<32;i+=8){
        float v = tile[tx][i];
        __nv_bfloat16 h = __float2bfloat16(v);
        __nv_bfloat16 l = __float2bfloat16(v - __bfloat162float(h));
        size_t base = (size_t)(nb+i)*2*K + kb + tx;
        bt[base]     = h;
        bt[base + K] = l;
    }
}

// ---------------- HMMA bf16 GEMM, 256x128x64, 4 stages ----------------
// Virtual K = 3*K (segments: Ahi*Bhi, Alo*Bhi, Ahi*Blo); A,B stored [hi|lo].
// mode 0: outF = acc + bias (fp32, stride HDIM)
// mode 1: outS = split-bf16(gelu(acc+bias)) [hi|lo] (stride 2*HDIM)
#define BM 256
#define BN 128
#define BK 64
#define NSTAGE 4
#define ABYTES (BM*128)                 // 32KB
#define STAGE_BYTES (ABYTES + BN*128)   // 48KB
#define SMEM_GEMM (NSTAGE*STAGE_BYTES)  // 192KB
#define GY 7                            // serpentine row-group

__global__ void __launch_bounds__(256, 1) mma_gemm(
    const __nv_bfloat16* __restrict__ A2s, const __nv_bfloat16* __restrict__ Bt,
    const float* __restrict__ bias, float* __restrict__ outF,
    __nv_bfloat16* __restrict__ outS, int K, int mode)
{
    extern __shared__ char smem[];
    uint32_t sb = smem_to_u32(smem);
    int tid = threadIdx.x, wid = tid >> 5, l = tid & 31;

    // rasterize: group GY M-rows per column sweep for L2 reuse
    int lin = blockIdx.y * gridDim.x + blockIdx.x;
    int gy  = lin / ((int)gridDim.x * GY);
    int rem = lin % ((int)gridDim.x * GY);
    int bx  = rem / GY;
    int by  = gy*GY + rem % GY;
    int row0 = by * BM, col0 = bx * BN;

    int wm = wid & 3, wn = wid >> 2;     // 4 x 2 warps; warp tile 64x64
    int T = 3*K / BK;
    int stride2K = 2*K;

    float acc[4][8][4];
    #pragma unroll
    for(int mt=0;mt<4;mt++)
        #pragma unroll
        for(int nt=0;nt<8;nt++)
            #pragma unroll
            for(int q=0;q<4;q++) acc[mt][nt][q] = 0.f;

    int ra   = wm*64 + (l & 15);
    int ca16 = (l >> 4) * 16;
    int rb   = wn*64 + (l & 7) + ((l >> 4) << 3);
    int cb16 = ((l >> 3) & 1) * 16;

    #define LOAD_STAGE(s, buf) { \
        uint32_t base_ = sb + (buf)*STAGE_BYTES; \
        int kv_ = (s)*BK; \
        int seg_ = kv_ / K, w_ = kv_ - seg_*K; \
        int kA_ = (seg_ == 1) ? K + w_ : w_; \
        int kB_ = (seg_ == 2) ? K + w_ : w_; \
        const __nv_bfloat16* Ap_ = A2s + (size_t)row0*stride2K + kA_; \
        const __nv_bfloat16* Bp_ = Bt  + (size_t)col0*stride2K + kB_; \
        _Pragma("unroll") \
        for(int i_=0;i_<8;i_++){ \
            int u_ = tid + i_*256; \
            int r_ = u_ >> 3, sg_ = u_ & 7; \
            cp_async16(base_ + SW128((uint32_t)(r_*128 + sg_*16)), Ap_ + (size_t)r_*stride2K + sg_*8); \
        } \
        _Pragma("unroll") \
        for(int i_=0;i_<4;i_++){ \
            int u_ = tid + i_*256; \
            int r_ = u_ >> 3, sg_ = u_ & 7; \
            cp_async16(base_ + ABYTES + SW128((uint32_t)(r_*128 + sg_*16)), Bp_ + (size_t)r_*stride2K + sg_*8); \
        } }

    LOAD_STAGE(0, 0); cp_commit();
    LOAD_STAGE(1, 1); cp_commit();
    LOAD_STAGE(2, 2); cp_commit();

    for(int t=0; t<T; t++){
        cp_wait2();
        __syncthreads();
        if(t+3 < T){
            LOAD_STAGE(t+3, (t+3) & 3);
        }
        cp_commit();

        uint32_t abase = sb + (t & 3)*STAGE_BYTES;
        uint32_t bbase = abase + ABYTES;
        #pragma unroll
        for(int ks=0; ks<4; ks++){
            uint32_t a[4][4];
            #pragma unroll
            for(int mt=0; mt<4; mt++)
                ldmx4(a[mt], abase + SW128((uint32_t)((ra + mt*16)*128 + ks*32 + ca16)));
            #pragma unroll
            for(int ntp=0; ntp<4; ntp++){
                uint32_t bfr[4];
                ldmx4(bfr, bbase + SW128((uint32_t)((rb + ntp*16)*128 + ks*32 + cb16)));
                #pragma unroll
                for(int mt=0; mt<4; mt++){
                    mma16816(acc[mt][ntp*2],   a[mt], bfr[0], bfr[1]);
                    mma16816(acc[mt][ntp*2+1], a[mt], bfr[2], bfr[3]);
                }
            }
        }
    }

    // ---- epilogue ----
    #pragma unroll
    for(int mt=0; mt<4; mt++){
        #pragma unroll
        for(int nt=0; nt<8; nt++){
            float* a4 = acc[mt][nt];
            int r = row0 + wm*64 + mt*16 + (l >> 2);
            int c = col0 + wn*64 + nt*8 + ((l & 3) << 1);
            float bi0 = bias[c], bi1 = bias[c+1];
            if(mode == 0){
                float2 v0; v0.x = a4[0] + bi0; v0.y = a4[1] + bi1;
                float2 v1; v1.x = a4[2] + bi0; v1.y = a4[3] + bi1;
                *(float2*)(outF + (size_t)r*HDIM + c)     = v0;
                *(float2*)(outF + (size_t)(r+8)*HDIM + c) = v1;
            } else {
                #pragma unroll
                for(int hrow=0; hrow<2; hrow++){
                    float v0 = gelu_exact(a4[hrow*2+0] + bi0);
                    float v1 = gelu_exact(a4[hrow*2+1] + bi1);
                    __nv_bfloat16 h0 = __float2bfloat16(v0);
                    __nv_bfloat16 h1 = __float2bfloat16(v1);
                    __nv_bfloat16 l0 = __float2bfloat16(v0 - __bfloat162float(h0));
                    __nv_bfloat16 l1 = __float2bfloat16(v1 - __bfloat162float(h1));
                    __nv_bfloat162 hh; hh.x = h0; hh.y = h1;
                    __nv_bfloat162 ll; ll.x = l0; ll.y = l1;
                    size_t rbse = (size_t)(r + hrow*8) * (2*HDIM);
                    *(__nv_bfloat162*)(outS + rbse + c)        = hh;
                    *(__nv_bfloat162*)(outS + rbse + HDIM + c) = ll;
                }
            }
        }
    }
}

// ---------------- launch ----------------
extern "C" void kernel_launch(void* const* d_in, const int* in_sizes, int n_in,
                              void* d_out, int out_size){
    (void)in_sizes; (void)n_in; (void)out_size;
    const float* x  = (const float*)d_in[0];
    const float* w1 = (const float*)d_in[1];
    const float* b1 = (const float*)d_in[2];
    const float* w2 = (const float*)d_in[3];
    const float* b2 = (const float*)d_in[4];
    float* out = (float*)d_out;

    __nv_bfloat16 *pBt1, *pBt2, *pA1, *pA2;
    float* pz;
    cudaGetSymbolAddress((void**)&pBt1, g_Bt1);
    cudaGetSymbolAddress((void**)&pBt2, g_Bt2);
    cudaGetSymbolAddress((void**)&pA1, g_A1);
    cudaGetSymbolAddress((void**)&pA2, g_A2);
    cudaGetSymbolAddress((void**)&pz,  g_z);

    k_splitW<<<dim3(HDIM/32, DDIM/32), 256>>>(w1, pBt1, DDIM, HDIM);
    k_splitW<<<dim3(HDIM/32, HDIM/32), 256>>>(w2, pBt2, HDIM, HDIM);

    k_normalize<<<NCLIP*TCLIP, 256>>>(x);
    k_redundancy<<<NCLIP*KFT, 256>>>();
    k_select<<<NCLIP, 256>>>();
    k_init<<<NCLIP*KFK, 256>>>(x);

    cudaFuncSetAttribute(k_sim_tiled, cudaFuncAttributeMaxDynamicSharedMemorySize, SIM_SMEM);

    const int nlist[7] = {588, 392, 262, 175, 117, 78, 52};
    const int mlist[7] = {196, 130,  87,  58,  39, 26,  3};
    for(int it=0; it<7; it++){
        int n = nlist[it];
        k_avg<<<NCLIP*KFK, 256>>>();
        k_sim_tiled<<<dim3((n+63)/64, NCLIP), 256, SIM_SMEM>>>(n);
        k_merge<<<NCLIP, 1024>>>(x, n, mlist[it]);
    }
    k_z<<<NCLIP*NFIN, 256>>>(x);
    k_splitA<<<MROWS, 256>>>(pz, pA1, DDIM);

    cudaFuncSetAttribute(mma_gemm, cudaFuncAttributeMaxDynamicSharedMemorySize, SMEM_GEMM);
    dim3 grid(HDIM/BN, MROWS/BM);   // (32, 49)
    mma_gemm<<<grid, 256, SMEM_GEMM>>>(pA1, pBt1, b1, nullptr, pA2, DDIM, 1);
    mma_gemm<<<grid, 256, SMEM_GEMM>>>(pA2, pBt2, b2, out, nullptr, HDIM, 0);
}

// round 9
// speedup vs baseline: 2.4457x; 1.0514x over previous
#include <cuda_runtime.h>
#include <cuda_bf16.h>
#include <math.h>
#include <stdint.h>

// Problem constants
#define NCLIP 64
#define TCLIP 784
#define DDIM  1024
#define KFT   196
#define KFK   147
#define NI0   588
#define NFIN  196
#define HDIM  4096
#define MROWS (NCLIP*NFIN)   // 12544

// ---------------- scratch (device globals; no allocations allowed) ----------
__device__ float g_kfn  [NCLIP*KFT*DDIM];
__device__ float g_incrn[NCLIP*NI0*DDIM];
__device__ float g_S    [NCLIP*DDIM];
__device__ float g_red  [NCLIP*KFT];
__device__ int   g_keep [NCLIP*KFK];
__device__ float g_kfsum[NCLIP*KFK*DDIM];
__device__ float g_kfcnt[NCLIP*KFK];
__device__ float g_kfavgn[NCLIP*KFK*DDIM];
__device__ float g_maxsim[NCLIP*NI0];
__device__ int   g_bestkf[NCLIP*NI0];
__device__ int   g_surv [NCLIP*NI0];

// split-bf16 operands: [hi | lo] along K (row stride 2K)
__device__ __nv_bfloat16 g_A1 [(size_t)MROWS*2*DDIM];   // z split
__device__ __nv_bfloat16 g_A2 [(size_t)MROWS*2*HDIM];   // h split
__device__ __nv_bfloat16 g_Bt1[(size_t)HDIM*2*DDIM];    // w1^T split
__device__ __nv_bfloat16 g_Bt2[(size_t)HDIM*2*HDIM];    // w2^T split

// ---------------- low-level helpers ----------------
__device__ __forceinline__ uint32_t smem_to_u32(const void* p){
    uint32_t a;
    asm("{ .reg .u64 t; cvta.to.shared.u64 t, %1; cvt.u32.u64 %0, t; }" : "=r"(a) : "l"(p));
    return a;
}
#define SW128(off) ((off) ^ (((off) >> 3) & 0x70))

__device__ __forceinline__ void cp_async16(uint32_t saddr, const void* gaddr){
    asm volatile("cp.async.cg.shared.global [%0], [%1], 16;" :: "r"(saddr), "l"(gaddr));
}
__device__ __forceinline__ void cp_commit(){ asm volatile("cp.async.commit_group;" ::: "memory"); }
__device__ __forceinline__ void cp_wait2(){ asm volatile("cp.async.wait_group 2;" ::: "memory"); }

__device__ __forceinline__ void ldmx4(uint32_t* r, uint32_t addr){
    asm volatile("ldmatrix.sync.aligned.m8n8.x4.shared.b16 {%0,%1,%2,%3}, [%4];"
        : "=r"(r[0]), "=r"(r[1]), "=r"(r[2]), "=r"(r[3]) : "r"(addr));
}
__device__ __forceinline__ void mma16816(float* c, const uint32_t* a, uint32_t b0, uint32_t b1){
    asm volatile("mma.sync.aligned.m16n8k16.row.col.f32.bf16.bf16.f32 "
        "{%0,%1,%2,%3}, {%4,%5,%6,%7}, {%8,%9}, {%0,%1,%2,%3};"
        : "+f"(c[0]), "+f"(c[1]), "+f"(c[2]), "+f"(c[3])
        : "r"(a[0]), "r"(a[1]), "r"(a[2]), "r"(a[3]), "r"(b0), "r"(b1));
}

// ---------------- generic helpers ----------------
__device__ __forceinline__ float blockSum256(float v){
    __shared__ float sh[8];
    int lane = threadIdx.x & 31, w = threadIdx.x >> 5;
    #pragma unroll
    for(int o=16;o;o>>=1) v += __shfl_xor_sync(0xffffffffu, v, o);
    if(lane==0) sh[w] = v;
    __syncthreads();
    float r = (threadIdx.x < 8) ? sh[threadIdx.x] : 0.f;
    if(w==0){
        #pragma unroll
        for(int o=4;o;o>>=1) r += __shfl_xor_sync(0xffffffffu, r, o);
        if(lane==0) sh[0] = r;
    }
    __syncthreads();
    float out = sh[0];
    __syncthreads();
    return out;
}

__device__ __forceinline__ void bitonic_sort(float* key, int* pos, int N){
    int t = threadIdx.x;
    for(int k=2;k<=N;k<<=1){
        for(int j=k>>1;j>0;j>>=1){
            __syncthreads();
            int ixj = t ^ j;
            if(ixj > t){
                float ka = key[t], kb = key[ixj];
                int   pa = pos[t], pb = pos[ixj];
                bool agtb = (ka > kb) || (ka == kb && pa > pb);
                bool up = ((t & k) == 0);
                if(agtb == up){
                    key[t]=kb; key[ixj]=ka;
                    pos[t]=pb; pos[ixj]=pa;
                }
            }
        }
    }
    __syncthreads();
}

__device__ __forceinline__ float gelu_exact(float v){
    return 0.5f * v * (1.0f + erff(v * 0.70710678118654752440f));
}

// ---------------- compression kernels ----------------
__global__ void k_normalize(const float* __restrict__ x){
    int b = blockIdx.x / TCLIP;
    int r = blockIdx.x % TCLIP;
    const float* row = x + ((size_t)b*TCLIP + r)*DDIM;
    float ss = 0.f;
    for(int i=threadIdx.x;i<DDIM;i+=256){ float v = row[i]; ss += v*v; }
    ss = blockSum256(ss);
    float inv = 1.0f / fmaxf(sqrtf(ss), 1e-12f);
    float* dst = (r < KFT) ? (g_kfn   + ((size_t)b*KFT + r)*DDIM)
                           : (g_incrn + ((size_t)b*NI0 + (r - KFT))*DDIM);
    for(int i=threadIdx.x;i<DDIM;i+=256) dst[i] = row[i]*inv;
}

// S[b] = sum_j kfn[b,j,:]  (row-sum trick: redundancy_i = <r_i, S> - 1)
__global__ void k_sumrows(){
    int b = blockIdx.x;
    int d0 = threadIdx.x * 4;
    float4 acc = make_float4(0.f,0.f,0.f,0.f);
    const float* base = g_kfn + (size_t)b*KFT*DDIM + d0;
    for(int j=0;j<KFT;j++){
        float4 v = *(const float4*)(base + (size_t)j*DDIM);
        acc.x += v.x; acc.y += v.y; acc.z += v.z; acc.w += v.w;
    }
    *(float4*)(g_S + (size_t)b*DDIM + d0) = acc;
}

__global__ void k_reddot(){
    int b = blockIdx.x / KFT, i = blockIdx.x % KFT;
    const float* ri = g_kfn + ((size_t)b*KFT + i)*DDIM;
    const float* S  = g_S + (size_t)b*DDIM;
    float s = 0.f;
    for(int d=threadIdx.x; d<DDIM; d+=256) s += ri[d]*S[d];
    s = blockSum256(s);
    if(threadIdx.x==0) g_red[b*KFT + i] = s - 1.0f;
}

__global__ void k_select(){
    int b = blockIdx.x;
    __shared__ float key[256];
    __shared__ int   pos[256];
    __shared__ unsigned char kept[KFT];
    int t = threadIdx.x;
    key[t] = (t < KFT) ? g_red[b*KFT + t] : __int_as_float(0x7f800000);
    pos[t] = t;
    if(t < KFT) kept[t] = 0;
    bitonic_sort(key, pos, 256);
    if(t < KFK) kept[pos[t]] = 1;
    __syncthreads();
    if(t==0){
        int c = 0;
        for(int i=0;i<KFT;i++) if(kept[i]) g_keep[b*KFK + (c++)] = i;
    }
    for(int s=t;s<NI0;s+=256) g_surv[b*NI0 + s] = s;
}

__global__ void k_init(const float* __restrict__ x){
    int b = blockIdx.x / KFK, k = blockIdx.x % KFK;
    int src = g_keep[b*KFK + k];
    const float* row = x + ((size_t)b*TCLIP + src)*DDIM;
    float* dst = g_kfsum + ((size_t)b*KFK + k)*DDIM;
    for(int i=threadIdx.x;i<DDIM;i+=256) dst[i] = row[i];
    if(threadIdx.x==0) g_kfcnt[b*KFK + k] = 1.0f;
}

__global__ void k_avg(){
    int b = blockIdx.x / KFK, k = blockIdx.x % KFK;
    const float* s = g_kfsum + ((size_t)b*KFK + k)*DDIM;
    float invc = 1.0f / g_kfcnt[b*KFK + k];
    float ss = 0.f;
    for(int i=threadIdx.x;i<DDIM;i+=256){ float v = s[i]*invc; ss += v*v; }
    ss = blockSum256(ss);
    float inv = invc / fmaxf(sqrtf(ss), 1e-12f);
    float* dst = g_kfavgn + ((size_t)b*KFK + k)*DDIM;
    for(int i=threadIdx.x;i<DDIM;i+=256) dst[i] = s[i]*inv;
}

// ---- tiled sim: CTA = (64-token tile, clip). thread tile: 5 kf x 8 tokens ----
#define SIM_SMEM (160*64*4 + 64*64*4)
__global__ void __launch_bounds__(256) k_sim_tiled(int n){
    extern __shared__ float sm[];
    float4* kf4 = (float4*)sm;
    float4* in4 = (float4*)(sm + 160*64);
    int b = blockIdx.y;
    int tile0 = blockIdx.x * 64;
    int tid = threadIdx.x;
    int tkf = tid & 31;
    int ttok = tid >> 5;
    int swz = tkf & 7;

    float acc[5][8];
    #pragma unroll
    for(int i=0;i<5;i++)
        #pragma unroll
        for(int j=0;j<8;j++) acc[i][j] = 0.f;

    for(int dc=0; dc<16; dc++){
        int d0 = dc*64;
        for(int idx=tid; idx<2560; idx+=256){
            int row = idx >> 4, g = idx & 15;
            float4 v = make_float4(0.f,0.f,0.f,0.f);
            if(row < KFK)
                v = *(const float4*)(g_kfavgn + ((size_t)b*KFK + row)*DDIM + d0 + g*4);
            kf4[(row<<4) + (g ^ (row & 7))] = v;
        }
        for(int idx=tid; idx<1024; idx+=256){
            int row = idx >> 4, g = idx & 15;
            int s = tile0 + row;
            float4 v = make_float4(0.f,0.f,0.f,0.f);
            if(s < n){
                int tok = g_surv[b*NI0 + s];
                v = *(const float4*)(g_incrn + ((size_t)b*NI0 + tok)*DDIM + d0 + g*4);
            }
            in4[(row<<4) + g] = v;
        }
        __syncthreads();
        #pragma unroll
        for(int dg=0; dg<16; dg++){
            float4 kv[5];
            #pragma unroll
            for(int i=0;i<5;i++)
                kv[i] = kf4[((tkf + 32*i)<<4) + (dg ^ swz)];
            #pragma unroll
            for(int jj=0; jj<8; jj++){
                float4 iv = in4[((ttok*8 + jj)<<4) + dg];
                #pragma unroll
                for(int i=0;i<5;i++)
                    acc[i][jj] += kv[i].x*iv.x + kv[i].y*iv.y + kv[i].z*iv.z + kv[i].w*iv.w;
            }
        }
        __syncthreads();
    }

    #pragma unroll
    for(int jj=0; jj<8; jj++){
        float best = -3.0e38f; int bk = 0x7fffffff;
        #pragma unroll
        for(int i=0;i<5;i++){
            int k = tkf + 32*i;
            if(k < KFK && acc[i][jj] > best){ best = acc[i][jj]; bk = k; }
        }
        #pragma unroll
        for(int o=16;o;o>>=1){
            float ov = __shfl_xor_sync(0xffffffffu, best, o);
            int   ok = __shfl_xor_sync(0xffffffffu, bk, o);
            if(ov > best || (ov == best && ok < bk)){ best = ov; bk = ok; }
        }
        int s = tile0 + ttok*8 + jj;
        if(tkf == 0 && s < n){
            g_maxsim[b*NI0 + s] = best;
            g_bestkf[b*NI0 + s] = bk;
        }
    }
}

__global__ void k_merge(const float* __restrict__ x, int n, int nm){
    int b = blockIdx.x, t = threadIdx.x;
    __shared__ float key[1024];
    __shared__ int   pos[1024];
    __shared__ int   mpos[196], mtgt[196], mtok[196];
    __shared__ unsigned char mflag[NI0];
    key[t] = (t < n) ? -g_maxsim[b*NI0 + t] : __int_as_float(0x7f800000);
    pos[t] = t;
    bitonic_sort(key, pos, 1024);
    if(t < nm){
        int p = pos[t];
        mpos[t] = p;
        mtgt[t] = g_bestkf[b*NI0 + p];
        mtok[t] = g_surv  [b*NI0 + p];
    }
    __syncthreads();
    for(int m=0;m<nm;m++){
        int tgt = mtgt[m], tok = mtok[m];
        const float* feat = x + ((size_t)b*TCLIP + KFT + tok)*DDIM;
        float* dst = g_kfsum + ((size_t)b*KFK + tgt)*DDIM;
        dst[t] += feat[t];
        if(t==0) g_kfcnt[b*KFK + tgt] += 1.0f;
    }
    for(int i=t;i<n;i+=1024) mflag[i] = 0;
    __syncthreads();
    if(t < nm) mflag[mpos[t]] = 1;
    __syncthreads();
    if(t==0){
        int c = 0;
        for(int p=0;p<n;p++)
            if(!mflag[p]){ int v = g_surv[b*NI0 + p]; g_surv[b*NI0 + c] = v; c++; }
    }
}

// fused z + split-bf16: write g_A1 row [hi|lo] directly (stride 2*DDIM)
__global__ void k_z_split(const float* __restrict__ x, __nv_bfloat16* __restrict__ dst){
    int b = blockIdx.x / NFIN, r = blockIdx.x % NFIN;
    __nv_bfloat16* d = dst + ((size_t)b*NFIN + r)*2*DDIM;
    if(r < KFK){
        float invc = 1.0f / g_kfcnt[b*KFK + r];
        const float* s = g_kfsum + ((size_t)b*KFK + r)*DDIM;
        for(int i=threadIdx.x;i<DDIM;i+=256){
            float v = s[i]*invc;
            __nv_bfloat16 h = __float2bfloat16(v);
            d[i] = h; d[DDIM+i] = __float2bfloat16(v - __bfloat162float(h));
        }
    } else {
        int tok = g_surv[b*NI0 + (r - KFK)];
        const float* s = x + ((size_t)b*TCLIP + KFT + tok)*DDIM;
        for(int i=threadIdx.x;i<DDIM;i+=256){
            float v = s[i];
            __nv_bfloat16 h = __float2bfloat16(v);
            d[i] = h; d[DDIM+i] = __float2bfloat16(v - __bfloat162float(h));
        }
    }
}

__global__ void k_splitW(const float* __restrict__ w, __nv_bfloat16* __restrict__ bt, int K, int N){
    __shared__ float tile[32][33];
    int kb = blockIdx.y*32, nb = blockIdx.x*32;
    int tx = threadIdx.x & 31, ty = threadIdx.x >> 5;
    for(int i=ty;i<32;i+=8) tile[i][tx] = w[(size_t)(kb+i)*N + nb + tx];
    __syncthreads();
    for(int i=ty;i<32;i+=8){
        float v = tile[tx][i];
        __nv_bfloat16 h = __float2bfloat16(v);
        __nv_bfloat16 l = __float2bfloat16(v - __bfloat162float(h));
        size_t base = (size_t)(nb+i)*2*K + kb + tx;
        bt[base]     = h;
        bt[base + K] = l;
    }
}

// ---------------- HMMA bf16 GEMM, 256x128x64, 512 threads, 4 stages ---------
// Virtual K = 3*K (segments: Ahi*Bhi, Alo*Bhi, Ahi*Blo); A,B stored [hi|lo].
#define BM 256
#define BN 128
#define BK 64
#define ABYTES (BM*128)                 // 32KB
#define STAGE_BYTES (ABYTES + BN*128)   // 48KB
#define SMEM_GEMM (4*STAGE_BYTES)       // 192KB

__global__ void __launch_bounds__(512, 1) mma_gemm(
    const __nv_bfloat16* __restrict__ A2s, const __nv_bfloat16* __restrict__ Bt,
    const float* __restrict__ bias, float* __restrict__ outF,
    __nv_bfloat16* __restrict__ outS, int K, int mode)
{
    extern __shared__ char smem[];
    uint32_t sb = smem_to_u32(smem);
    int tid = threadIdx.x, wid = tid >> 5, l = tid & 31;
    int row0 = blockIdx.y * BM, col0 = blockIdx.x * BN;

    int wm = wid & 7, wn = wid >> 3;     // 8 x 2 warps; warp tile 32x64
    int T = 3*K / BK;
    int stride2K = 2*K;

    float acc[2][8][4];
    #pragma unroll
    for(int mt=0;mt<2;mt++)
        #pragma unroll
        for(int nt=0;nt<8;nt++)
            #pragma unroll
            for(int q=0;q<4;q++) acc[mt][nt][q] = 0.f;

    int ra   = wm*32 + (l & 15);
    int ca16 = (l >> 4) * 16;
    int rb   = wn*64 + (l & 7) + ((l >> 4) << 3);
    int cb16 = ((l >> 3) & 1) * 16;

    #define LOAD_STAGE(s, buf) { \
        uint32_t base_ = sb + (buf)*STAGE_BYTES; \
        int kv_ = (s)*BK; \
        int seg_ = kv_ / K, w_ = kv_ - seg_*K; \
        int kA_ = (seg_ == 1) ? K + w_ : w_; \
        int kB_ = (seg_ == 2) ? K + w_ : w_; \
        const __nv_bfloat16* Ap_ = A2s + (size_t)row0*stride2K + kA_; \
        const __nv_bfloat16* Bp_ = Bt  + (size_t)col0*stride2K + kB_; \
        _Pragma("unroll") \
        for(int i_=0;i_<4;i_++){ \
            int u_ = tid + i_*512; \
            int r_ = u_ >> 3, sg_ = u_ & 7; \
            cp_async16(base_ + SW128((uint32_t)(r_*128 + sg_*16)), Ap_ + (size_t)r_*stride2K + sg_*8); \
        } \
        _Pragma("unroll") \
        for(int i_=0;i_<2;i_++){ \
            int u_ = tid + i_*512; \
            int r_ = u_ >> 3, sg_ = u_ & 7; \
            cp_async16(base_ + ABYTES + SW128((uint32_t)(r_*128 + sg_*16)), Bp_ + (size_t)r_*stride2K + sg_*8); \
        } }

    LOAD_STAGE(0, 0); cp_commit();
    LOAD_STAGE(1, 1); cp_commit();
    LOAD_STAGE(2, 2); cp_commit();

    for(int t=0; t<T; t++){
        cp_wait2();
        __syncthreads();
        if(t+3 < T){
            LOAD_STAGE(t+3, (t+3) & 3);
        }
        cp_commit();

        uint32_t abase = sb + (t & 3)*STAGE_BYTES;
        uint32_t bbase = abase + ABYTES;
        #pragma unroll
        for(int ks=0; ks<4; ks++){
            uint32_t a[2][4];
            #pragma unroll
            for(int mt=0; mt<2; mt++)
                ldmx4(a[mt], abase + SW128((uint32_t)((ra + mt*16)*128 + ks*32 + ca16)));
            #pragma unroll
            for(int ntp=0; ntp<4; ntp++){
                uint32_t bfr[4];
                ldmx4(bfr, bbase + SW128((uint32_t)((rb + ntp*16)*128 + ks*32 + cb16)));
                #pragma unroll
                for(int mt=0; mt<2; mt++){
                    mma16816(acc[mt][ntp*2],   a[mt], bfr[0], bfr[1]);
                    mma16816(acc[mt][ntp*2+1], a[mt], bfr[2], bfr[3]);
                }
            }
        }
    }

    // ---- epilogue ----
    #pragma unroll
    for(int mt=0; mt<2; mt++){
        #pragma unroll
        for(int nt=0; nt<8; nt++){
            float* a4 = acc[mt][nt];
            int r = row0 + wm*32 + mt*16 + (l >> 2);
            int c = col0 + wn*64 + nt*8 + ((l & 3) << 1);
            float bi0 = bias[c], bi1 = bias[c+1];
            if(mode == 0){
                float2 v0; v0.x = a4[0] + bi0; v0.y = a4[1] + bi1;
                float2 v1; v1.x = a4[2] + bi0; v1.y = a4[3] + bi1;
                *(float2*)(outF + (size_t)r*HDIM + c)     = v0;
                *(float2*)(outF + (size_t)(r+8)*HDIM + c) = v1;
            } else {
                #pragma unroll
                for(int hrow=0; hrow<2; hrow++){
                    float v0 = gelu_exact(a4[hrow*2+0] + bi0);
                    float v1 = gelu_exact(a4[hrow*2+1] + bi1);
                    __nv_bfloat16 h0 = __float2bfloat16(v0);
                    __nv_bfloat16 h1 = __float2bfloat16(v1);
                    __nv_bfloat16 l0 = __float2bfloat16(v0 - __bfloat162float(h0));
                    __nv_bfloat16 l1 = __float2bfloat16(v1 - __bfloat162float(h1));
                    __nv_bfloat162 hh; hh.x = h0; hh.y = h1;
                    __nv_bfloat162 ll; ll.x = l0; ll.y = l1;
                    size_t rbse = (size_t)(r + hrow*8) * (2*HDIM);
                    *(__nv_bfloat162*)(outS + rbse + c)        = hh;
                    *(__nv_bfloat162*)(outS + rbse + HDIM + c) = ll;
                }
            }
        }
    }
}

// ---------------- launch ----------------
extern "C" void kernel_launch(void* const* d_in, const int* in_sizes, int n_in,
                              void* d_out, int out_size){
    (void)in_sizes; (void)n_in; (void)out_size;
    const float* x  = (const float*)d_in[0];
    const float* w1 = (const float*)d_in[1];
    const float* b1 = (const float*)d_in[2];
    const float* w2 = (const float*)d_in[3];
    const float* b2 = (const float*)d_in[4];
    float* out = (float*)d_out;

    __nv_bfloat16 *pBt1, *pBt2, *pA1, *pA2;
    cudaGetSymbolAddress((void**)&pBt1, g_Bt1);
    cudaGetSymbolAddress((void**)&pBt2, g_Bt2);
    cudaGetSymbolAddress((void**)&pA1, g_A1);
    cudaGetSymbolAddress((void**)&pA2, g_A2);

    k_splitW<<<dim3(HDIM/32, DDIM/32), 256>>>(w1, pBt1, DDIM, HDIM);
    k_splitW<<<dim3(HDIM/32, HDIM/32), 256>>>(w2, pBt2, HDIM, HDIM);

    k_normalize<<<NCLIP*TCLIP, 256>>>(x);
    k_sumrows<<<NCLIP, 256>>>();
    k_reddot<<<NCLIP*KFT, 256>>>();
    k_select<<<NCLIP, 256>>>();
    k_init<<<NCLIP*KFK, 256>>>(x);

    cudaFuncSetAttribute(k_sim_tiled, cudaFuncAttributeMaxDynamicSharedMemorySize, SIM_SMEM);

    const int nlist[7] = {588, 392, 262, 175, 117, 78, 52};
    const int mlist[7] = {196, 130,  87,  58,  39, 26,  3};
    for(int it=0; it<7; it++){
        int n = nlist[it];
        k_avg<<<NCLIP*KFK, 256>>>();
        k_sim_tiled<<<dim3((n+63)/64, NCLIP), 256, SIM_SMEM>>>(n);
        k_merge<<<NCLIP, 1024>>>(x, n, mlist[it]);
    }
    k_z_split<<<NCLIP*NFIN, 256>>>(x, pA1);

    cudaFuncSetAttribute(mma_gemm, cudaFuncAttributeMaxDynamicSharedMemorySize, SMEM_GEMM);
    dim3 grid(HDIM/BN, MROWS/BM);   // (32, 49)
    mma_gemm<<<grid, 512, SMEM_GEMM>>>(pA1, pBt1, b1, nullptr, pA2, DDIM, 1);
    mma_gemm<<<grid, 512, SMEM_GEMM>>>(pA2, pBt2, b2, out, nullptr, HDIM, 0);
}

// round 10
// speedup vs baseline: 2.7979x; 1.1440x over previous
#include <cuda_runtime.h>
#include <cuda_bf16.h>
#include <math.h>
#include <stdint.h>

// Problem constants
#define NCLIP 64
#define TCLIP 784
#define DDIM  1024
#define KFT   196
#define KFK   147
#define NI0   588
#define NFIN  196
#define HDIM  4096
#define MROWS (NCLIP*NFIN)   // 12544

// ---------------- scratch (device globals) ----------------
__device__ float g_kfn  [NCLIP*KFT*DDIM];
__device__ float g_incrn[NCLIP*NI0*DDIM];
__device__ float g_S    [NCLIP*DDIM];
__device__ float g_red  [NCLIP*KFT];
__device__ int   g_keep [NCLIP*KFK];
__device__ float g_kfsum[NCLIP*KFK*DDIM];
__device__ float g_kfcnt[NCLIP*KFK];
__device__ float g_kfinv[NCLIP*KFK];
__device__ float g_maxsim[NCLIP*NI0];
__device__ int   g_bestkf[NCLIP*NI0];
__device__ int   g_surv [NCLIP*NI0];

// split-bf16 operands: [hi | lo] along K (row stride 2K)
__device__ __nv_bfloat16 g_A1 [(size_t)MROWS*2*DDIM];
__device__ __nv_bfloat16 g_A2 [(size_t)MROWS*2*HDIM];
__device__ __nv_bfloat16 g_Bt1[(size_t)HDIM*2*DDIM];
__device__ __nv_bfloat16 g_Bt2[(size_t)HDIM*2*HDIM];

// ---------------- low-level helpers ----------------
__device__ __forceinline__ uint32_t smem_to_u32(const void* p){
    uint32_t a;
    asm("{ .reg .u64 t; cvta.to.shared.u64 t, %1; cvt.u32.u64 %0, t; }" : "=r"(a) : "l"(p));
    return a;
}
#define SW128(off) ((off) ^ (((off) >> 3) & 0x70))

__device__ __forceinline__ void cp_async16(uint32_t saddr, const void* gaddr){
    asm volatile("cp.async.cg.shared.global [%0], [%1], 16;" :: "r"(saddr), "l"(gaddr));
}
__device__ __forceinline__ void cp_commit(){ asm volatile("cp.async.commit_group;" ::: "memory"); }
__device__ __forceinline__ void cp_wait1(){ asm volatile("cp.async.wait_group 1;" ::: "memory"); }

__device__ __forceinline__ void ldmx4(uint32_t* r, uint32_t addr){
    asm volatile("ldmatrix.sync.aligned.m8n8.x4.shared.b16 {%0,%1,%2,%3}, [%4];"
        : "=r"(r[0]), "=r"(r[1]), "=r"(r[2]), "=r"(r[3]) : "r"(addr));
}
__device__ __forceinline__ void mma16816(float* c, const uint32_t* a, uint32_t b0, uint32_t b1){
    asm volatile("mma.sync.aligned.m16n8k16.row.col.f32.bf16.bf16.f32 "
        "{%0,%1,%2,%3}, {%4,%5,%6,%7}, {%8,%9}, {%0,%1,%2,%3};"
        : "+f"(c[0]), "+f"(c[1]), "+f"(c[2]), "+f"(c[3])
        : "r"(a[0]), "r"(a[1]), "r"(a[2]), "r"(a[3]), "r"(b0), "r"(b1));
}

// ---------------- generic helpers ----------------
__device__ __forceinline__ float blockSum256(float v){
    __shared__ float sh[8];
    int lane = threadIdx.x & 31, w = threadIdx.x >> 5;
    #pragma unroll
    for(int o=16;o;o>>=1) v += __shfl_xor_sync(0xffffffffu, v, o);
    if(lane==0) sh[w] = v;
    __syncthreads();
    float r = (threadIdx.x < 8) ? sh[threadIdx.x] : 0.f;
    if(w==0){
        #pragma unroll
        for(int o=4;o;o>>=1) r += __shfl_xor_sync(0xffffffffu, r, o);
        if(lane==0) sh[0] = r;
    }
    __syncthreads();
    float out = sh[0];
    __syncthreads();
    return out;
}

__device__ __forceinline__ void bitonic_sort(float* key, int* pos, int N){
    int t = threadIdx.x;
    for(int k=2;k<=N;k<<=1){
        for(int j=k>>1;j>0;j>>=1){
            __syncthreads();
            int ixj = t ^ j;
            if(ixj > t){
                float ka = key[t], kb = key[ixj];
                int   pa = pos[t], pb = pos[ixj];
                bool agtb = (ka > kb) || (ka == kb && pa > pb);
                bool up = ((t & k) == 0);
                if(agtb == up){
                    key[t]=kb; key[ixj]=ka;
                    pos[t]=pb; pos[ixj]=pa;
                }
            }
        }
    }
    __syncthreads();
}

__device__ __forceinline__ float gelu_exact(float v){
    return 0.5f * v * (1.0f + erff(v * 0.70710678118654752440f));
}

// ---------------- compression kernels ----------------
__global__ void k_normalize(const float* __restrict__ x){
    int b = blockIdx.x / TCLIP;
    int r = blockIdx.x % TCLIP;
    const float* row = x + ((size_t)b*TCLIP + r)*DDIM;
    float ss = 0.f;
    for(int i=threadIdx.x;i<DDIM;i+=256){ float v = row[i]; ss += v*v; }
    ss = blockSum256(ss);
    float inv = 1.0f / fmaxf(sqrtf(ss), 1e-12f);
    float* dst = (r < KFT) ? (g_kfn   + ((size_t)b*KFT + r)*DDIM)
                           : (g_incrn + ((size_t)b*NI0 + (r - KFT))*DDIM);
    for(int i=threadIdx.x;i<DDIM;i+=256) dst[i] = row[i]*inv;
}

__global__ void k_sumrows(){
    int b = blockIdx.x;
    int d0 = threadIdx.x * 4;
    float4 acc = make_float4(0.f,0.f,0.f,0.f);
    const float* base = g_kfn + (size_t)b*KFT*DDIM + d0;
    for(int j=0;j<KFT;j++){
        float4 v = *(const float4*)(base + (size_t)j*DDIM);
        acc.x += v.x; acc.y += v.y; acc.z += v.z; acc.w += v.w;
    }
    *(float4*)(g_S + (size_t)b*DDIM + d0) = acc;
}

__global__ void k_reddot(){
    int b = blockIdx.x / KFT, i = blockIdx.x % KFT;
    const float* ri = g_kfn + ((size_t)b*KFT + i)*DDIM;
    const float* S  = g_S + (size_t)b*DDIM;
    float s = 0.f;
    for(int d=threadIdx.x; d<DDIM; d+=256) s += ri[d]*S[d];
    s = blockSum256(s);
    if(threadIdx.x==0) g_red[b*KFT + i] = s - 1.0f;
}

__global__ void k_select(){
    int b = blockIdx.x;
    __shared__ float key[256];
    __shared__ int   pos[256];
    __shared__ unsigned char kept[KFT];
    int t = threadIdx.x;
    key[t] = (t < KFT) ? g_red[b*KFT + t] : __int_as_float(0x7f800000);
    pos[t] = t;
    if(t < KFT) kept[t] = 0;
    bitonic_sort(key, pos, 256);
    if(t < KFK) kept[pos[t]] = 1;
    __syncthreads();
    if(t==0){
        int c = 0;
        for(int i=0;i<KFT;i++) if(kept[i]) g_keep[b*KFK + (c++)] = i;
    }
    for(int s=t;s<NI0;s+=256) g_surv[b*NI0 + s] = s;
}

__global__ void k_init(const float* __restrict__ x){
    int b = blockIdx.x / KFK, k = blockIdx.x % KFK;
    int src = g_keep[b*KFK + k];
    const float* row = x + ((size_t)b*TCLIP + src)*DDIM;
    float* dst = g_kfsum + ((size_t)b*KFK + k)*DDIM;
    for(int i=threadIdx.x;i<DDIM;i+=256) dst[i] = row[i];
    if(threadIdx.x==0) g_kfcnt[b*KFK + k] = 1.0f;
}

// per-kf inverse norm of kfsum (count cancels in l2norm(kfsum/c))
__global__ void k_norms(){
    int row = blockIdx.x*8 + (threadIdx.x >> 5);
    if(row >= NCLIP*KFK) return;
    int lane = threadIdx.x & 31;
    const float4* s = (const float4*)(g_kfsum + (size_t)row*DDIM);
    float ss = 0.f;
    #pragma unroll
    for(int i=0;i<8;i++){
        float4 v = s[lane + i*32];
        ss += v.x*v.x + v.y*v.y + v.z*v.z + v.w*v.w;
    }
    #pragma unroll
    for(int o=16;o;o>>=1) ss += __shfl_xor_sync(0xffffffffu, ss, o);
    if(lane==0) g_kfinv[row] = 1.0f / fmaxf(sqrtf(ss), 1e-12f);
}

// ---- tiled sim: CTA = (64-token tile, clip). kfsum rows scaled by invnorm ----
#define SIM_SMEM (160*64*4 + 64*64*4)
__global__ void __launch_bounds__(256) k_sim_tiled(int n){
    extern __shared__ float sm[];
    float4* kf4 = (float4*)sm;
    float4* in4 = (float4*)(sm + 160*64);
    int b = blockIdx.y;
    int tile0 = blockIdx.x * 64;
    int tid = threadIdx.x;
    int tkf = tid & 31;
    int ttok = tid >> 5;
    int swz = tkf & 7;

    float acc[5][8];
    #pragma unroll
    for(int i=0;i<5;i++)
        #pragma unroll
        for(int j=0;j<8;j++) acc[i][j] = 0.f;

    for(int dc=0; dc<16; dc++){
        int d0 = dc*64;
        for(int idx=tid; idx<2560; idx+=256){
            int row = idx >> 4, g = idx & 15;
            float4 v = make_float4(0.f,0.f,0.f,0.f);
            if(row < KFK)
                v = *(const float4*)(g_kfsum + ((size_t)b*KFK + row)*DDIM + d0 + g*4);
            kf4[(row<<4) + (g ^ (row & 7))] = v;
        }
        for(int idx=tid; idx<1024; idx+=256){
            int row = idx >> 4, g = idx & 15;
            int s = tile0 + row;
            float4 v = make_float4(0.f,0.f,0.f,0.f);
            if(s < n){
                int tok = g_surv[b*NI0 + s];
                v = *(const float4*)(g_incrn + ((size_t)b*NI0 + tok)*DDIM + d0 + g*4);
            }
            in4[(row<<4) + g] = v;
        }
        __syncthreads();
        #pragma unroll
        for(int dg=0; dg<16; dg++){
            float4 kv[5];
            #pragma unroll
            for(int i=0;i<5;i++)
                kv[i] = kf4[((tkf + 32*i)<<4) + (dg ^ swz)];
            #pragma unroll
            for(int jj=0; jj<8; jj++){
                float4 iv = in4[((ttok*8 + jj)<<4) + dg];
                #pragma unroll
                for(int i=0;i<5;i++)
                    acc[i][jj] += kv[i].x*iv.x + kv[i].y*iv.y + kv[i].z*iv.z + kv[i].w*iv.w;
            }
        }
        __syncthreads();
    }

    // scale by kf inv-norms, then per-token first-argmax
    float invs[5];
    #pragma unroll
    for(int i=0;i<5;i++){
        int k = tkf + 32*i;
        invs[i] = (k < KFK) ? g_kfinv[b*KFK + k] : 0.f;
    }
    #pragma unroll
    for(int jj=0; jj<8; jj++){
        float best = -3.0e38f; int bk = 0x7fffffff;
        #pragma unroll
        for(int i=0;i<5;i++){
            int k = tkf + 32*i;
            float v = acc[i][jj] * invs[i];
            if(k < KFK && v > best){ best = v; bk = k; }
        }
        #pragma unroll
        for(int o=16;o;o>>=1){
            float ov = __shfl_xor_sync(0xffffffffu, best, o);
            int   ok = __shfl_xor_sync(0xffffffffu, bk, o);
            if(ov > best || (ov == best && ok < bk)){ best = ov; bk = ok; }
        }
        int s = tile0 + ttok*8 + jj;
        if(tkf == 0 && s < n){
            g_maxsim[b*NI0 + s] = best;
            g_bestkf[b*NI0 + s] = bk;
        }
    }
}

__global__ void k_merge(const float* __restrict__ x, int n, int nm){
    int b = blockIdx.x, t = threadIdx.x;
    __shared__ float key[1024];
    __shared__ int   pos[1024];
    __shared__ int   mpos[196], mtgt[196], mtok[196];
    __shared__ unsigned char mflag[NI0];
    key[t] = (t < n) ? -g_maxsim[b*NI0 + t] : __int_as_float(0x7f800000);
    pos[t] = t;
    bitonic_sort(key, pos, 1024);
    if(t < nm){
        int p = pos[t];
        mpos[t] = p;
        mtgt[t] = g_bestkf[b*NI0 + p];
        mtok[t] = g_surv  [b*NI0 + p];
    }
    __syncthreads();
    // software-pipelined sequential merges (thread t owns dim t)
    if(nm > 0){
        float cur = x[((size_t)b*TCLIP + KFT + mtok[0])*DDIM + t];
        for(int m=0;m<nm;m++){
            float nxt = (m+1 < nm) ? x[((size_t)b*TCLIP + KFT + mtok[m+1])*DDIM + t] : 0.f;
            g_kfsum[((size_t)b*KFK + mtgt[m])*DDIM + t] += cur;
            if(t==0) g_kfcnt[b*KFK + mtgt[m]] += 1.0f;
            cur = nxt;
        }
    }
    for(int i=t;i<n;i+=1024) mflag[i] = 0;
    __syncthreads();
    if(t < nm) mflag[mpos[t]] = 1;
    __syncthreads();
    if(t==0){
        int c = 0;
        for(int p=0;p<n;p++)
            if(!mflag[p]){ int v = g_surv[b*NI0 + p]; g_surv[b*NI0 + c] = v; c++; }
    }
}

// fused z + split-bf16: write g_A1 row [hi|lo] directly (stride 2*DDIM)
__global__ void k_z_split(const float* __restrict__ x, __nv_bfloat16* __restrict__ dst){
    int b = blockIdx.x / NFIN, r = blockIdx.x % NFIN;
    __nv_bfloat16* d = dst + ((size_t)b*NFIN + r)*2*DDIM;
    if(r < KFK){
        float invc = 1.0f / g_kfcnt[b*KFK + r];
        const float* s = g_kfsum + ((size_t)b*KFK + r)*DDIM;
        for(int i=threadIdx.x;i<DDIM;i+=256){
            float v = s[i]*invc;
            __nv_bfloat16 h = __float2bfloat16(v);
            d[i] = h; d[DDIM+i] = __float2bfloat16(v - __bfloat162float(h));
        }
    } else {
        int tok = g_surv[b*NI0 + (r - KFK)];
        const float* s = x + ((size_t)b*TCLIP + KFT + tok)*DDIM;
        for(int i=threadIdx.x;i<DDIM;i+=256){
            float v = s[i];
            __nv_bfloat16 h = __float2bfloat16(v);
            d[i] = h; d[DDIM+i] = __float2bfloat16(v - __bfloat162float(h));
        }
    }
}

__global__ void k_splitW(const float* __restrict__ w, __nv_bfloat16* __restrict__ bt, int K, int N){
    __shared__ float tile[32][33];
    int kb = blockIdx.y*32, nb = blockIdx.x*32;
    int tx = threadIdx.x & 31, ty = threadIdx.x >> 5;
    for(int i=ty;i<32;i+=8) tile[i][tx] = w[(size_t)(kb+i)*N + nb + tx];
    __syncthreads();
    for(int i=ty;i<32;i+=8){
        float v = tile[tx][i];
        __nv_bfloat16 h = __float2bfloat16(v);
        __nv_bfloat16 l = __float2bfloat16(v - __bfloat162float(h));
        size_t base = (size_t)(nb+i)*2*K + kb + tx;
        bt[base]     = h;
        bt[base + K] = l;
    }
}

// ---------------- HMMA bf16 GEMM, super-stage 3-pass, 256x128x64 ------------
// Per k-chunk load {Ahi, Alo, Bhi, Blo} once; passes Ahi*Bhi + Alo*Bhi + Ahi*Blo.
#define BM 256
#define BN 128
#define BK 64
#define OFF_ALO 32768
#define OFF_BHI 65536
#define OFF_BLO 81920
#define STAGE_BYTES 98304
#define SMEM_GEMM (2*STAGE_BYTES)   // 192KB

template<int K, int MODE>
__global__ void __launch_bounds__(512, 1) mma_gemm(
    const __nv_bfloat16* __restrict__ A2s, const __nv_bfloat16* __restrict__ Bt,
    const float* __restrict__ bias, float* __restrict__ outF,
    __nv_bfloat16* __restrict__ outS)
{
    extern __shared__ char smem[];
    uint32_t sb = smem_to_u32(smem);
    int tid = threadIdx.x, wid = tid >> 5, l = tid & 31;
    int row0 = blockIdx.y * BM, col0 = blockIdx.x * BN;
    int wm = wid & 7, wn = wid >> 3;     // 8 x 2 warps; warp tile 32x64
    const int T = K / BK;

    float acc[2][8][4];
    #pragma unroll
    for(int mt=0;mt<2;mt++)
        #pragma unroll
        for(int nt=0;nt<8;nt++)
            #pragma unroll
            for(int q=0;q<4;q++) acc[mt][nt][q] = 0.f;

    int ra   = wm*32 + (l & 15);
    int ca16 = (l >> 4) * 16;
    int rb   = wn*64 + (l & 7) + ((l >> 4) << 3);
    int cb16 = ((l >> 3) & 1) * 16;

    #define LOADS(s, buf) { \
        uint32_t base_ = sb + (buf)*STAGE_BYTES; \
        int w0_ = (s)*BK; \
        const __nv_bfloat16* Ap_ = A2s + (size_t)row0*(2*K) + w0_; \
        const __nv_bfloat16* Bp_ = Bt  + (size_t)col0*(2*K) + w0_; \
        _Pragma("unroll") \
        for(int i_=0;i_<4;i_++){ \
            int u_ = tid + i_*512; \
            int r_ = u_ >> 3, sg_ = u_ & 7; \
            uint32_t off_ = SW128((uint32_t)(r_*128 + sg_*16)); \
            const __nv_bfloat16* a_ = Ap_ + (size_t)r_*(2*K) + sg_*8; \
            cp_async16(base_ + off_,           a_); \
            cp_async16(base_ + OFF_ALO + off_, a_ + K); \
        } \
        _Pragma("unroll") \
        for(int i_=0;i_<2;i_++){ \
            int u_ = tid + i_*512; \
            int r_ = u_ >> 3, sg_ = u_ & 7; \
            uint32_t off_ = SW128((uint32_t)(r_*128 + sg_*16)); \
            const __nv_bfloat16* b_ = Bp_ + (size_t)r_*(2*K) + sg_*8; \
            cp_async16(base_ + OFF_BHI + off_, b_); \
            cp_async16(base_ + OFF_BLO + off_, b_ + K); \
        } }

    LOADS(0, 0); cp_commit();
    LOADS(1, 1); cp_commit();

    for(int t=0; t<T; t++){
        cp_wait1();
        __syncthreads();

        uint32_t sbuf = sb + (t & 1)*STAGE_BYTES;
        #pragma unroll
        for(int ks=0; ks<4; ks++){
            uint32_t aH[2][4], aL[2][4];
            #pragma unroll
            for(int mt=0; mt<2; mt++){
                uint32_t aoff = SW128((uint32_t)((ra + mt*16)*128 + ks*32 + ca16));
                ldmx4(aH[mt], sbuf + aoff);
                ldmx4(aL[mt], sbuf + OFF_ALO + aoff);
            }
            #pragma unroll
            for(int ntp=0; ntp<4; ntp++){
                uint32_t boff = SW128((uint32_t)((rb + ntp*16)*128 + ks*32 + cb16));
                uint32_t bH[4], bL[4];
                ldmx4(bH, sbuf + OFF_BHI + boff);
                ldmx4(bL, sbuf + OFF_BLO + boff);
                #pragma unroll
                for(int mt=0; mt<2; mt++){
                    mma16816(acc[mt][ntp*2],   aH[mt], bH[0], bH[1]);
                    mma16816(acc[mt][ntp*2+1], aH[mt], bH[2], bH[3]);
                    mma16816(acc[mt][ntp*2],   aL[mt], bH[0], bH[1]);
                    mma16816(acc[mt][ntp*2+1], aL[mt], bH[2], bH[3]);
                    mma16816(acc[mt][ntp*2],   aH[mt], bL[0], bL[1]);
                    mma16816(acc[mt][ntp*2+1], aH[mt], bL[2], bL[3]);
                }
            }
        }
        __syncthreads();
        if(t+2 < T){ LOADS(t+2, t & 1); }
        cp_commit();
    }

    // ---- epilogue ----
    #pragma unroll
    for(int mt=0; mt<2; mt++){
        #pragma unroll
        for(int nt=0; nt<8; nt++){
            float* a4 = acc[mt][nt];
            int r = row0 + wm*32 + mt*16 + (l >> 2);
            int c = col0 + wn*64 + nt*8 + ((l & 3) << 1);
            float bi0 = bias[c], bi1 = bias[c+1];
            if(MODE == 0){
                float2 v0; v0.x = a4[0] + bi0; v0.y = a4[1] + bi1;
                float2 v1; v1.x = a4[2] + bi0; v1.y = a4[3] + bi1;
                *(float2*)(outF + (size_t)r*HDIM + c)     = v0;
                *(float2*)(outF + (size_t)(r+8)*HDIM + c) = v1;
            } else {
                #pragma unroll
                for(int hrow=0; hrow<2; hrow++){
                    float v0 = gelu_exact(a4[hrow*2+0] + bi0);
                    float v1 = gelu_exact(a4[hrow*2+1] + bi1);
                    __nv_bfloat16 h0 = __float2bfloat16(v0);
                    __nv_bfloat16 h1 = __float2bfloat16(v1);
                    __nv_bfloat16 l0 = __float2bfloat16(v0 - __bfloat162float(h0));
                    __nv_bfloat16 l1 = __float2bfloat16(v1 - __bfloat162float(h1));
                    __nv_bfloat162 hh; hh.x = h0; hh.y = h1;
                    __nv_bfloat162 ll; ll.x = l0; ll.y = l1;
                    size_t rbse = (size_t)(r + hrow*8) * (2*HDIM);
                    *(__nv_bfloat162*)(outS + rbse + c)        = hh;
                    *(__nv_bfloat162*)(outS + rbse + HDIM + c) = ll;
                }
            }
        }
    }
}

// ---------------- launch ----------------
extern "C" void kernel_launch(void* const* d_in, const int* in_sizes, int n_in,
                              void* d_out, int out_size){
    (void)in_sizes; (void)n_in; (void)out_size;
    const float* x  = (const float*)d_in[0];
    const float* w1 = (const float*)d_in[1];
    const float* b1 = (const float*)d_in[2];
    const float* w2 = (const float*)d_in[3];
    const float* b2 = (const float*)d_in[4];
    float* out = (float*)d_out;

    __nv_bfloat16 *pBt1, *pBt2, *pA1, *pA2;
    cudaGetSymbolAddress((void**)&pBt1, g_Bt1);
    cudaGetSymbolAddress((void**)&pBt2, g_Bt2);
    cudaGetSymbolAddress((void**)&pA1, g_A1);
    cudaGetSymbolAddress((void**)&pA2, g_A2);

    k_splitW<<<dim3(HDIM/32, DDIM/32), 256>>>(w1, pBt1, DDIM, HDIM);
    k_splitW<<<dim3(HDIM/32, HDIM/32), 256>>>(w2, pBt2, HDIM, HDIM);

    k_normalize<<<NCLIP*TCLIP, 256>>>(x);
    k_sumrows<<<NCLIP, 256>>>();
    k_reddot<<<NCLIP*KFT, 256>>>();
    k_select<<<NCLIP, 256>>>();
    k_init<<<NCLIP*KFK, 256>>>(x);

    cudaFuncSetAttribute(k_sim_tiled, cudaFuncAttributeMaxDynamicSharedMemorySize, SIM_SMEM);

    const int nlist[7] = {588, 392, 262, 175, 117, 78, 52};
    const int mlist[7] = {196, 130,  87,  58,  39, 26,  3};
    for(int it=0; it<7; it++){
        int n = nlist[it];
        k_norms<<<(NCLIP*KFK + 7)/8, 256>>>();
        k_sim_tiled<<<dim3((n+63)/64, NCLIP), 256, SIM_SMEM>>>(n);
        k_merge<<<NCLIP, 1024>>>(x, n, mlist[it]);
    }
    k_z_split<<<NCLIP*NFIN, 256>>>(x, pA1);

    cudaFuncSetAttribute(mma_gemm<DDIM,1>, cudaFuncAttributeMaxDynamicSharedMemorySize, SMEM_GEMM);
    cudaFuncSetAttribute(mma_gemm<HDIM,0>, cudaFuncAttributeMaxDynamicSharedMemorySize, SMEM_GEMM);
    dim3 grid(HDIM/BN, MROWS/BM);   // (32, 49)
    mma_gemm<DDIM,1><<<grid, 512, SMEM_GEMM>>>(pA1, pBt1, b1, nullptr, pA2);
    mma_gemm<HDIM,0><<<grid, 512, SMEM_GEMM>>>(pA2, pBt2, b2, out, nullptr);
}

// round 11
// speedup vs baseline: 3.4319x; 1.2266x over previous
#include <cuda_runtime.h>
#include <cuda_bf16.h>
#include <cuda_fp16.h>
#include <math.h>
#include <stdint.h>

// Problem constants
#define NCLIP 64
#define TCLIP 784
#define DDIM  1024
#define KFT   196
#define KFK   147
#define NI0   588
#define NFIN  196
#define HDIM  4096
#define MROWS (NCLIP*NFIN)   // 12544

// ---------------- scratch (device globals) ----------------
__device__ float g_kfn  [NCLIP*KFT*DDIM];
__device__ float g_incrn[NCLIP*NI0*DDIM];
__device__ float g_S    [NCLIP*DDIM];
__device__ float g_red  [NCLIP*KFT];
__device__ int   g_keep [NCLIP*KFK];
__device__ float g_kfsum[NCLIP*KFK*DDIM];
__device__ float g_kfcnt[NCLIP*KFK];
__device__ float g_kfinv[NCLIP*KFK];
__device__ float g_maxsim[NCLIP*NI0];
__device__ int   g_bestkf[NCLIP*NI0];
__device__ int   g_surv [NCLIP*NI0];

// fp16 GEMM operands: A plain fp16 (stride K); B^T split [hi|lo] (stride 2K)
__device__ __half g_A1 [(size_t)MROWS*DDIM];
__device__ __half g_A2 [(size_t)MROWS*HDIM];
__device__ __half g_Bt1[(size_t)HDIM*2*DDIM];
__device__ __half g_Bt2[(size_t)HDIM*2*HDIM];

// ---------------- low-level helpers ----------------
__device__ __forceinline__ uint32_t smem_to_u32(const void* p){
    uint32_t a;
    asm("{ .reg .u64 t; cvta.to.shared.u64 t, %1; cvt.u32.u64 %0, t; }" : "=r"(a) : "l"(p));
    return a;
}
#define SW128(off) ((off) ^ (((off) >> 3) & 0x70))

__device__ __forceinline__ void cp_async16(uint32_t saddr, const void* gaddr){
    asm volatile("cp.async.cg.shared.global [%0], [%1], 16;" :: "r"(saddr), "l"(gaddr));
}
__device__ __forceinline__ void cp_commit(){ asm volatile("cp.async.commit_group;" ::: "memory"); }
__device__ __forceinline__ void cp_wait1(){ asm volatile("cp.async.wait_group 1;" ::: "memory"); }

__device__ __forceinline__ void ldmx4(uint32_t* r, uint32_t addr){
    asm volatile("ldmatrix.sync.aligned.m8n8.x4.shared.b16 {%0,%1,%2,%3}, [%4];"
        : "=r"(r[0]), "=r"(r[1]), "=r"(r[2]), "=r"(r[3]) : "r"(addr));
}
__device__ __forceinline__ void mma16816h(float* c, const uint32_t* a, uint32_t b0, uint32_t b1){
    asm volatile("mma.sync.aligned.m16n8k16.row.col.f32.f16.f16.f32 "
        "{%0,%1,%2,%3}, {%4,%5,%6,%7}, {%8,%9}, {%0,%1,%2,%3};"
        : "+f"(c[0]), "+f"(c[1]), "+f"(c[2]), "+f"(c[3])
        : "r"(a[0]), "r"(a[1]), "r"(a[2]), "r"(a[3]), "r"(b0), "r"(b1));
}

// ---------------- generic helpers ----------------
__device__ __forceinline__ float blockSum256(float v){
    __shared__ float sh[8];
    int lane = threadIdx.x & 31, w = threadIdx.x >> 5;
    #pragma unroll
    for(int o=16;o;o>>=1) v += __shfl_xor_sync(0xffffffffu, v, o);
    if(lane==0) sh[w] = v;
    __syncthreads();
    float r = (threadIdx.x < 8) ? sh[threadIdx.x] : 0.f;
    if(w==0){
        #pragma unroll
        for(int o=4;o;o>>=1) r += __shfl_xor_sync(0xffffffffu, r, o);
        if(lane==0) sh[0] = r;
    }
    __syncthreads();
    float out = sh[0];
    __syncthreads();
    return out;
}

__device__ __forceinline__ void bitonic_sort(float* key, int* pos, int N){
    int t = threadIdx.x;
    for(int k=2;k<=N;k<<=1){
        for(int j=k>>1;j>0;j>>=1){
            __syncthreads();
            int ixj = t ^ j;
            if(ixj > t){
                float ka = key[t], kb = key[ixj];
                int   pa = pos[t], pb = pos[ixj];
                bool agtb = (ka > kb) || (ka == kb && pa > pb);
                bool up = ((t & k) == 0);
                if(agtb == up){
                    key[t]=kb; key[ixj]=ka;
                    pos[t]=pb; pos[ixj]=pa;
                }
            }
        }
    }
    __syncthreads();
}

__device__ __forceinline__ float gelu_exact(float v){
    return 0.5f * v * (1.0f + erff(v * 0.70710678118654752440f));
}

// ---------------- compression kernels ----------------
__global__ void k_normalize(const float* __restrict__ x){
    int b = blockIdx.x / TCLIP;
    int r = blockIdx.x % TCLIP;
    const float* row = x + ((size_t)b*TCLIP + r)*DDIM;
    float ss = 0.f;
    for(int i=threadIdx.x;i<DDIM;i+=256){ float v = row[i]; ss += v*v; }
    ss = blockSum256(ss);
    float inv = 1.0f / fmaxf(sqrtf(ss), 1e-12f);
    float* dst = (r < KFT) ? (g_kfn   + ((size_t)b*KFT + r)*DDIM)
                           : (g_incrn + ((size_t)b*NI0 + (r - KFT))*DDIM);
    for(int i=threadIdx.x;i<DDIM;i+=256) dst[i] = row[i]*inv;
}

__global__ void k_sumrows(){
    int b = blockIdx.x;
    int d0 = threadIdx.x * 4;
    float4 acc = make_float4(0.f,0.f,0.f,0.f);
    const float* base = g_kfn + (size_t)b*KFT*DDIM + d0;
    for(int j=0;j<KFT;j++){
        float4 v = *(const float4*)(base + (size_t)j*DDIM);
        acc.x += v.x; acc.y += v.y; acc.z += v.z; acc.w += v.w;
    }
    *(float4*)(g_S + (size_t)b*DDIM + d0) = acc;
}

__global__ void k_reddot(){
    int b = blockIdx.x / KFT, i = blockIdx.x % KFT;
    const float* ri = g_kfn + ((size_t)b*KFT + i)*DDIM;
    const float* S  = g_S + (size_t)b*DDIM;
    float s = 0.f;
    for(int d=threadIdx.x; d<DDIM; d+=256) s += ri[d]*S[d];
    s = blockSum256(s);
    if(threadIdx.x==0) g_red[b*KFT + i] = s - 1.0f;
}

__global__ void k_select(){
    int b = blockIdx.x;
    __shared__ float key[256];
    __shared__ int   pos[256];
    __shared__ unsigned char kept[KFT];
    int t = threadIdx.x;
    key[t] = (t < KFT) ? g_red[b*KFT + t] : __int_as_float(0x7f800000);
    pos[t] = t;
    if(t < KFT) kept[t] = 0;
    bitonic_sort(key, pos, 256);
    if(t < KFK) kept[pos[t]] = 1;
    __syncthreads();
    if(t==0){
        int c = 0;
        for(int i=0;i<KFT;i++) if(kept[i]) g_keep[b*KFK + (c++)] = i;
    }
    for(int s=t;s<NI0;s+=256) g_surv[b*NI0 + s] = s;
}

__global__ void k_init(const float* __restrict__ x){
    int b = blockIdx.x / KFK, k = blockIdx.x % KFK;
    int src = g_keep[b*KFK + k];
    const float* row = x + ((size_t)b*TCLIP + src)*DDIM;
    float* dst = g_kfsum + ((size_t)b*KFK + k)*DDIM;
    for(int i=threadIdx.x;i<DDIM;i+=256) dst[i] = row[i];
    if(threadIdx.x==0) g_kfcnt[b*KFK + k] = 1.0f;
}

__global__ void k_norms(){
    int row = blockIdx.x*8 + (threadIdx.x >> 5);
    if(row >= NCLIP*KFK) return;
    int lane = threadIdx.x & 31;
    const float4* s = (const float4*)(g_kfsum + (size_t)row*DDIM);
    float ss = 0.f;
    #pragma unroll
    for(int i=0;i<8;i++){
        float4 v = s[lane + i*32];
        ss += v.x*v.x + v.y*v.y + v.z*v.z + v.w*v.w;
    }
    #pragma unroll
    for(int o=16;o;o>>=1) ss += __shfl_xor_sync(0xffffffffu, ss, o);
    if(lane==0) g_kfinv[row] = 1.0f / fmaxf(sqrtf(ss), 1e-12f);
}

// ---- tiled sim ----
#define SIM_SMEM (160*64*4 + 64*64*4)
__global__ void __launch_bounds__(256) k_sim_tiled(int n){
    extern __shared__ float sm[];
    float4* kf4 = (float4*)sm;
    float4* in4 = (float4*)(sm + 160*64);
    int b = blockIdx.y;
    int tile0 = blockIdx.x * 64;
    int tid = threadIdx.x;
    int tkf = tid & 31;
    int ttok = tid >> 5;
    int swz = tkf & 7;

    float acc[5][8];
    #pragma unroll
    for(int i=0;i<5;i++)
        #pragma unroll
        for(int j=0;j<8;j++) acc[i][j] = 0.f;

    for(int dc=0; dc<16; dc++){
        int d0 = dc*64;
        for(int idx=tid; idx<2560; idx+=256){
            int row = idx >> 4, g = idx & 15;
            float4 v = make_float4(0.f,0.f,0.f,0.f);
            if(row < KFK)
                v = *(const float4*)(g_kfsum + ((size_t)b*KFK + row)*DDIM + d0 + g*4);
            kf4[(row<<4) + (g ^ (row & 7))] = v;
        }
        for(int idx=tid; idx<1024; idx+=256){
            int row = idx >> 4, g = idx & 15;
            int s = tile0 + row;
            float4 v = make_float4(0.f,0.f,0.f,0.f);
            if(s < n){
                int tok = g_surv[b*NI0 + s];
                v = *(const float4*)(g_incrn + ((size_t)b*NI0 + tok)*DDIM + d0 + g*4);
            }
            in4[(row<<4) + g] = v;
        }
        __syncthreads();
        #pragma unroll
        for(int dg=0; dg<16; dg++){
            float4 kv[5];
            #pragma unroll
            for(int i=0;i<5;i++)
                kv[i] = kf4[((tkf + 32*i)<<4) + (dg ^ swz)];
            #pragma unroll
            for(int jj=0; jj<8; jj++){
                float4 iv = in4[((ttok*8 + jj)<<4) + dg];
                #pragma unroll
                for(int i=0;i<5;i++)
                    acc[i][jj] += kv[i].x*iv.x + kv[i].y*iv.y + kv[i].z*iv.z + kv[i].w*iv.w;
            }
        }
        __syncthreads();
    }

    float invs[5];
    #pragma unroll
    for(int i=0;i<5;i++){
        int k = tkf + 32*i;
        invs[i] = (k < KFK) ? g_kfinv[b*KFK + k] : 0.f;
    }
    #pragma unroll
    for(int jj=0; jj<8; jj++){
        float best = -3.0e38f; int bk = 0x7fffffff;
        #pragma unroll
        for(int i=0;i<5;i++){
            int k = tkf + 32*i;
            float v = acc[i][jj] * invs[i];
            if(k < KFK && v > best){ best = v; bk = k; }
        }
        #pragma unroll
        for(int o=16;o;o>>=1){
            float ov = __shfl_xor_sync(0xffffffffu, best, o);
            int   ok = __shfl_xor_sync(0xffffffffu, bk, o);
            if(ov > best || (ov == best && ok < bk)){ best = ov; bk = ok; }
        }
        int s = tile0 + ttok*8 + jj;
        if(tkf == 0 && s < n){
            g_maxsim[b*NI0 + s] = best;
            g_bestkf[b*NI0 + s] = bk;
        }
    }
}

__global__ void k_merge(const float* __restrict__ x, int n, int nm){
    int b = blockIdx.x, t = threadIdx.x;
    __shared__ float key[1024];
    __shared__ int   pos[1024];
    __shared__ int   mpos[196], mtgt[196], mtok[196];
    __shared__ unsigned char mflag[NI0];
    key[t] = (t < n) ? -g_maxsim[b*NI0 + t] : __int_as_float(0x7f800000);
    pos[t] = t;
    bitonic_sort(key, pos, 1024);
    if(t < nm){
        int p = pos[t];
        mpos[t] = p;
        mtgt[t] = g_bestkf[b*NI0 + p];
        mtok[t] = g_surv  [b*NI0 + p];
    }
    __syncthreads();
    if(nm > 0){
        float cur = x[((size_t)b*TCLIP + KFT + mtok[0])*DDIM + t];
        for(int m=0;m<nm;m++){
            float nxt = (m+1 < nm) ? x[((size_t)b*TCLIP + KFT + mtok[m+1])*DDIM + t] : 0.f;
            g_kfsum[((size_t)b*KFK + mtgt[m])*DDIM + t] += cur;
            if(t==0) g_kfcnt[b*KFK + mtgt[m]] += 1.0f;
            cur = nxt;
        }
    }
    for(int i=t;i<n;i+=1024) mflag[i] = 0;
    __syncthreads();
    if(t < nm) mflag[mpos[t]] = 1;
    __syncthreads();
    if(t==0){
        int c = 0;
        for(int p=0;p<n;p++)
            if(!mflag[p]){ int v = g_surv[b*NI0 + p]; g_surv[b*NI0 + c] = v; c++; }
    }
}

// fused z + fp16 convert: write g_A1 row (stride DDIM)
__global__ void k_z_half(const float* __restrict__ x, __half* __restrict__ dst){
    int b = blockIdx.x / NFIN, r = blockIdx.x % NFIN;
    __half* d = dst + ((size_t)b*NFIN + r)*DDIM;
    if(r < KFK){
        float invc = 1.0f / g_kfcnt[b*KFK + r];
        const float* s = g_kfsum + ((size_t)b*KFK + r)*DDIM;
        for(int i=threadIdx.x;i<DDIM;i+=256)
            d[i] = __float2half_rn(s[i]*invc);
    } else {
        int tok = g_surv[b*NI0 + (r - KFK)];
        const float* s = x + ((size_t)b*TCLIP + KFT + tok)*DDIM;
        for(int i=threadIdx.x;i<DDIM;i+=256)
            d[i] = __float2half_rn(s[i]);
    }
}

// W fp32 [K,N] -> Bt fp16 [N, 2K]: [hi | lo] along K
__global__ void k_splitW(const float* __restrict__ w, __half* __restrict__ bt, int K, int N){
    __shared__ float tile[32][33];
    int kb = blockIdx.y*32, nb = blockIdx.x*32;
    int tx = threadIdx.x & 31, ty = threadIdx.x >> 5;
    for(int i=ty;i<32;i+=8) tile[i][tx] = w[(size_t)(kb+i)*N + nb + tx];
    __syncthreads();
    for(int i=ty;i<32;i+=8){
        float v = tile[tx][i];
        __half h = __float2half_rn(v);
        __half l = __float2half_rn(v - __half2float(h));
        size_t base = (size_t)(nb+i)*2*K + kb + tx;
        bt[base]     = h;
        bt[base + K] = l;
    }
}

// ---------------- fp16 HMMA GEMM, 2-pass super-stage, 256x128x64 ------------
// acc = A * (Bhi + Blo); A plain fp16 stride K, B [hi|lo] stride 2K.
#define BM 256
#define BN 128
#define BK 64
#define OFF_BHI 32768
#define OFF_BLO 49152
#define STAGE_BYTES 65536
#define SMEM_GEMM (2*STAGE_BYTES)   // 128KB

template<int K, int MODE>
__global__ void __launch_bounds__(512, 1) mma_gemm(
    const __half* __restrict__ A, const __half* __restrict__ Bt,
    const float* __restrict__ bias, float* __restrict__ outF,
    __half* __restrict__ outS)
{
    extern __shared__ char smem[];
    uint32_t sb = smem_to_u32(smem);
    int tid = threadIdx.x, wid = tid >> 5, l = tid & 31;
    int row0 = blockIdx.y * BM, col0 = blockIdx.x * BN;
    int wm = wid & 7, wn = wid >> 3;     // 8 x 2 warps; warp tile 32x64
    const int T = K / BK;

    float acc[2][8][4];
    #pragma unroll
    for(int mt=0;mt<2;mt++)
        #pragma unroll
        for(int nt=0;nt<8;nt++)
            #pragma unroll
            for(int q=0;q<4;q++) acc[mt][nt][q] = 0.f;

    int ra   = wm*32 + (l & 15);
    int ca16 = (l >> 4) * 16;
    int rb   = wn*64 + (l & 7) + ((l >> 4) << 3);
    int cb16 = ((l >> 3) & 1) * 16;

    #define LOADS(s, buf) { \
        uint32_t base_ = sb + (buf)*STAGE_BYTES; \
        int w0_ = (s)*BK; \
        const __half* Ap_ = A  + (size_t)row0*K + w0_; \
        const __half* Bp_ = Bt + (size_t)col0*(2*K) + w0_; \
        _Pragma("unroll") \
        for(int i_=0;i_<4;i_++){ \
            int u_ = tid + i_*512; \
            int r_ = u_ >> 3, sg_ = u_ & 7; \
            cp_async16(base_ + SW128((uint32_t)(r_*128 + sg_*16)), Ap_ + (size_t)r_*K + sg_*8); \
        } \
        _Pragma("unroll") \
        for(int i_=0;i_<2;i_++){ \
            int u_ = tid + i_*512; \
            int r_ = u_ >> 3, sg_ = u_ & 7; \
            uint32_t off_ = SW128((uint32_t)(r_*128 + sg_*16)); \
            const __half* b_ = Bp_ + (size_t)r_*(2*K) + sg_*8; \
            cp_async16(base_ + OFF_BHI + off_, b_); \
            cp_async16(base_ + OFF_BLO + off_, b_ + K); \
        } }

    LOADS(0, 0); cp_commit();
    LOADS(1, 1); cp_commit();

    for(int t=0; t<T; t++){
        cp_wait1();
        __syncthreads();

        uint32_t sbuf = sb + (t & 1)*STAGE_BYTES;
        #pragma unroll
        for(int ks=0; ks<4; ks++){
            uint32_t a[2][4];
            #pragma unroll
            for(int mt=0; mt<2; mt++)
                ldmx4(a[mt], sbuf + SW128((uint32_t)((ra + mt*16)*128 + ks*32 + ca16)));
            #pragma unroll
            for(int ntp=0; ntp<4; ntp++){
                uint32_t boff = SW128((uint32_t)((rb + ntp*16)*128 + ks*32 + cb16));
                uint32_t bH[4], bL[4];
                ldmx4(bH, sbuf + OFF_BHI + boff);
                ldmx4(bL, sbuf + OFF_BLO + boff);
                #pragma unroll
                for(int mt=0; mt<2; mt++){
                    mma16816h(acc[mt][ntp*2],   a[mt], bH[0], bH[1]);
                    mma16816h(acc[mt][ntp*2+1], a[mt], bH[2], bH[3]);
                    mma16816h(acc[mt][ntp*2],   a[mt], bL[0], bL[1]);
                    mma16816h(acc[mt][ntp*2+1], a[mt], bL[2], bL[3]);
                }
            }
        }
        __syncthreads();
        if(t+2 < T){ LOADS(t+2, t & 1); }
        cp_commit();
    }

    // ---- epilogue ----
    #pragma unroll
    for(int mt=0; mt<2; mt++){
        #pragma unroll
        for(int nt=0; nt<8; nt++){
            float* a4 = acc[mt][nt];
            int r = row0 + wm*32 + mt*16 + (l >> 2);
            int c = col0 + wn*64 + nt*8 + ((l & 3) << 1);
            float bi0 = bias[c], bi1 = bias[c+1];
            if(MODE == 0){
                float2 v0; v0.x = a4[0] + bi0; v0.y = a4[1] + bi1;
                float2 v1; v1.x = a4[2] + bi0; v1.y = a4[3] + bi1;
                *(float2*)(outF + (size_t)r*HDIM + c)     = v0;
                *(float2*)(outF + (size_t)(r+8)*HDIM + c) = v1;
            } else {
                #pragma unroll
                for(int hrow=0; hrow<2; hrow++){
                    float v0 = gelu_exact(a4[hrow*2+0] + bi0);
                    float v1 = gelu_exact(a4[hrow*2+1] + bi1);
                    __half2 hh;
                    hh.x = __float2half_rn(v0);
                    hh.y = __float2half_rn(v1);
                    *(__half2*)(outS + (size_t)(r + hrow*8)*HDIM + c) = hh;
                }
            }
        }
    }
}

// ---------------- launch ----------------
extern "C" void kernel_launch(void* const* d_in, const int* in_sizes, int n_in,
                              void* d_out, int out_size){
    (void)in_sizes; (void)n_in; (void)out_size;
    const float* x  = (const float*)d_in[0];
    const float* w1 = (const float*)d_in[1];
    const float* b1 = (const float*)d_in[2];
    const float* w2 = (const float*)d_in[3];
    const float* b2 = (const float*)d_in[4];
    float* out = (float*)d_out;

    __half *pBt1, *pBt2, *pA1, *pA2;
    cudaGetSymbolAddress((void**)&pBt1, g_Bt1);
    cudaGetSymbolAddress((void**)&pBt2, g_Bt2);
    cudaGetSymbolAddress((void**)&pA1, g_A1);
    cudaGetSymbolAddress((void**)&pA2, g_A2);

    k_splitW<<<dim3(HDIM/32, DDIM/32), 256>>>(w1, pBt1, DDIM, HDIM);
    k_splitW<<<dim3(HDIM/32, HDIM/32), 256>>>(w2, pBt2, HDIM, HDIM);

    k_normalize<<<NCLIP*TCLIP, 256>>>(x);
    k_sumrows<<<NCLIP, 256>>>();
    k_reddot<<<NCLIP*KFT, 256>>>();
    k_select<<<NCLIP, 256>>>();
    k_init<<<NCLIP*KFK, 256>>>(x);

    cudaFuncSetAttribute(k_sim_tiled, cudaFuncAttributeMaxDynamicSharedMemorySize, SIM_SMEM);

    const int nlist[7] = {588, 392, 262, 175, 117, 78, 52};
    const int mlist[7] = {196, 130,  87,  58,  39, 26,  3};
    for(int it=0; it<7; it++){
        int n = nlist[it];
        k_norms<<<(NCLIP*KFK + 7)/8, 256>>>();
        k_sim_tiled<<<dim3((n+63)/64, NCLIP), 256, SIM_SMEM>>>(n);
        k_merge<<<NCLIP, 1024>>>(x, n, mlist[it]);
    }
    k_z_half<<<NCLIP*NFIN, 256>>>(x, pA1);

    cudaFuncSetAttribute(mma_gemm<DDIM,1>, cudaFuncAttributeMaxDynamicSharedMemorySize, SMEM_GEMM);
    cudaFuncSetAttribute(mma_gemm<HDIM,0>, cudaFuncAttributeMaxDynamicSharedMemorySize, SMEM_GEMM);
    dim3 grid(HDIM/BN, MROWS/BM);   // (32, 49)
    mma_gemm<DDIM,1><<<grid, 512, SMEM_GEMM>>>(pA1, pBt1, b1, nullptr, pA2);
    mma_gemm<HDIM,0><<<grid, 512, SMEM_GEMM>>>(pA2, pBt2, b2, out, nullptr);
}

// round 12
// speedup vs baseline: 4.4206x; 1.2881x over previous
#include <cuda_runtime.h>
#include <cuda_bf16.h>
#include <cuda_fp16.h>
#include <math.h>
#include <stdint.h>

// Problem constants
#define NCLIP 64
#define TCLIP 784
#define DDIM  1024
#define KFT   196
#define KFK   147
#define NI0   588
#define NFIN  196
#define HDIM  4096
#define MROWS (NCLIP*NFIN)   // 12544

// ---------------- scratch (device globals) ----------------
__device__ float g_kfn  [NCLIP*KFT*DDIM];
__device__ float g_Sp   [NCLIP*4*DDIM];
__device__ float g_red  [NCLIP*KFT];
__device__ int   g_keep [NCLIP*KFK];
__device__ float g_kfsum[NCLIP*KFK*DDIM];
__device__ float g_kfcnt[NCLIP*KFK];
__device__ float g_kfinv[NCLIP*KFK];
__device__ float g_maxsim[NCLIP*NI0];
__device__ int   g_bestkf[NCLIP*NI0];
__device__ int   g_surv [NCLIP*NI0];

// fp16 hi|lo token / kf buffers for tensor-core sim (row stride 2048 halves)
__device__ __half g_Ihl [(size_t)NCLIP*NI0*2048];
__device__ __half g_KFhl[(size_t)NCLIP*KFK*2048];

// fp16 GEMM operands: A plain fp16 (stride K); B^T split [hi|lo] (stride 2K)
__device__ __half g_A1 [(size_t)MROWS*DDIM];
__device__ __half g_A2 [(size_t)MROWS*HDIM];
__device__ __half g_Bt1[(size_t)HDIM*2*DDIM];
__device__ __half g_Bt2[(size_t)HDIM*2*HDIM];

// ---------------- low-level helpers ----------------
__device__ __forceinline__ uint32_t smem_to_u32(const void* p){
    uint32_t a;
    asm("{ .reg .u64 t; cvta.to.shared.u64 t, %1; cvt.u32.u64 %0, t; }" : "=r"(a) : "l"(p));
    return a;
}
#define SW128(off) ((off) ^ (((off) >> 3) & 0x70))

__device__ __forceinline__ void cp_async16(uint32_t saddr, const void* gaddr){
    asm volatile("cp.async.cg.shared.global [%0], [%1], 16;" :: "r"(saddr), "l"(gaddr));
}
__device__ __forceinline__ void cp_commit(){ asm volatile("cp.async.commit_group;" ::: "memory"); }
__device__ __forceinline__ void cp_wait1(){ asm volatile("cp.async.wait_group 1;" ::: "memory"); }

__device__ __forceinline__ void ldmx4(uint32_t* r, uint32_t addr){
    asm volatile("ldmatrix.sync.aligned.m8n8.x4.shared.b16 {%0,%1,%2,%3}, [%4];"
        : "=r"(r[0]), "=r"(r[1]), "=r"(r[2]), "=r"(r[3]) : "r"(addr));
}
__device__ __forceinline__ void mma16816h(float* c, const uint32_t* a, uint32_t b0, uint32_t b1){
    asm volatile("mma.sync.aligned.m16n8k16.row.col.f32.f16.f16.f32 "
        "{%0,%1,%2,%3}, {%4,%5,%6,%7}, {%8,%9}, {%0,%1,%2,%3};"
        : "+f"(c[0]), "+f"(c[1]), "+f"(c[2]), "+f"(c[3])
        : "r"(a[0]), "r"(a[1]), "r"(a[2]), "r"(a[3]), "r"(b0), "r"(b1));
}

// ---------------- generic helpers ----------------
__device__ __forceinline__ float blockSum256(float v){
    __shared__ float sh[8];
    int lane = threadIdx.x & 31, w = threadIdx.x >> 5;
    #pragma unroll
    for(int o=16;o;o>>=1) v += __shfl_xor_sync(0xffffffffu, v, o);
    if(lane==0) sh[w] = v;
    __syncthreads();
    float r = (threadIdx.x < 8) ? sh[threadIdx.x] : 0.f;
    if(w==0){
        #pragma unroll
        for(int o=4;o;o>>=1) r += __shfl_xor_sync(0xffffffffu, r, o);
        if(lane==0) sh[0] = r;
    }
    __syncthreads();
    float out = sh[0];
    __syncthreads();
    return out;
}

__device__ __forceinline__ void bitonic_sort(float* key, int* pos, int N){
    int t = threadIdx.x;
    for(int k=2;k<=N;k<<=1){
        for(int j=k>>1;j>0;j>>=1){
            __syncthreads();
            int ixj = t ^ j;
            if(ixj > t){
                float ka = key[t], kb = key[ixj];
                int   pa = pos[t], pb = pos[ixj];
                bool agtb = (ka > kb) || (ka == kb && pa > pb);
                bool up = ((t & k) == 0);
                if(agtb == up){
                    key[t]=kb; key[ixj]=ka;
                    pos[t]=pb; pos[ixj]=pa;
                }
            }
        }
    }
    __syncthreads();
}

__device__ __forceinline__ float gelu_exact(float v){
    return 0.5f * v * (1.0f + erff(v * 0.70710678118654752440f));
}

// ---------------- compression kernels ----------------
// kf rows -> fp32 g_kfn (for redundancy); incr rows -> normalized fp16 hi|lo g_Ihl
__global__ void k_normalize(const float* __restrict__ x){
    int b = blockIdx.x / TCLIP;
    int r = blockIdx.x % TCLIP;
    const float* row = x + ((size_t)b*TCLIP + r)*DDIM;
    float ss = 0.f;
    for(int i=threadIdx.x;i<DDIM;i+=256){ float v = row[i]; ss += v*v; }
    ss = blockSum256(ss);
    float inv = 1.0f / fmaxf(sqrtf(ss), 1e-12f);
    if(r < KFT){
        float* dst = g_kfn + ((size_t)b*KFT + r)*DDIM;
        for(int i=threadIdx.x;i<DDIM;i+=256) dst[i] = row[i]*inv;
    } else {
        __half* d = g_Ihl + ((size_t)b*NI0 + (r - KFT))*2048;
        for(int i=threadIdx.x;i<DDIM;i+=256){
            float v = row[i]*inv;
            __half h = __float2half_rn(v);
            d[i] = h;
            d[1024+i] = __float2half_rn(v - __half2float(h));
        }
    }
}

// split-K partial row sums of g_kfn: 4 chunks of 49 rows
__global__ void k_sumrows(){
    int b = blockIdx.x, part = blockIdx.y;
    int d0 = threadIdx.x * 4;
    int j0 = part*49, j1 = j0 + 49;
    float4 acc = make_float4(0.f,0.f,0.f,0.f);
    const float* base = g_kfn + (size_t)b*KFT*DDIM + d0;
    for(int j=j0;j<j1;j++){
        float4 v = *(const float4*)(base + (size_t)j*DDIM);
        acc.x += v.x; acc.y += v.y; acc.z += v.z; acc.w += v.w;
    }
    *(float4*)(g_Sp + ((size_t)b*4 + part)*DDIM + d0) = acc;
}

__global__ void k_reddot(){
    int b = blockIdx.x / KFT, i = blockIdx.x % KFT;
    const float* ri = g_kfn + ((size_t)b*KFT + i)*DDIM;
    const float* S0 = g_Sp + (size_t)b*4*DDIM;
    float s = 0.f;
    for(int d=threadIdx.x; d<DDIM; d+=256)
        s += ri[d]*(S0[d] + S0[DDIM+d] + S0[2*DDIM+d] + S0[3*DDIM+d]);
    s = blockSum256(s);
    if(threadIdx.x==0) g_red[b*KFT + i] = s - 1.0f;
}

__global__ void k_select(){
    int b = blockIdx.x;
    __shared__ float key[256];
    __shared__ int   pos[256];
    __shared__ unsigned char kept[KFT];
    int t = threadIdx.x;
    key[t] = (t < KFT) ? g_red[b*KFT + t] : __int_as_float(0x7f800000);
    pos[t] = t;
    if(t < KFT) kept[t] = 0;
    bitonic_sort(key, pos, 256);
    if(t < KFK) kept[pos[t]] = 1;
    __syncthreads();
    if(t==0){
        int c = 0;
        for(int i=0;i<KFT;i++) if(kept[i]) g_keep[b*KFK + (c++)] = i;
    }
    for(int s=t;s<NI0;s+=256) g_surv[b*NI0 + s] = s;
}

__global__ void k_init(const float* __restrict__ x){
    int b = blockIdx.x / KFK, k = blockIdx.x % KFK;
    int src = g_keep[b*KFK + k];
    const float* row = x + ((size_t)b*TCLIP + src)*DDIM;
    float* dst = g_kfsum + ((size_t)b*KFK + k)*DDIM;
    for(int i=threadIdx.x;i<DDIM;i+=256) dst[i] = row[i];
    if(threadIdx.x==0) g_kfcnt[b*KFK + k] = 1.0f;
}

// per-kf inverse norm of kfsum + fp16 hi|lo re-split (count cancels in l2norm)
__global__ void k_norms(){
    int row = blockIdx.x*8 + (threadIdx.x >> 5);
    if(row >= NCLIP*KFK) return;
    int lane = threadIdx.x & 31;
    const float4* s = (const float4*)(g_kfsum + (size_t)row*DDIM);
    __half* dh = g_KFhl + (size_t)row*2048;
    float ss = 0.f;
    #pragma unroll
    for(int i=0;i<8;i++){
        float4 v = s[lane + i*32];
        ss += v.x*v.x + v.y*v.y + v.z*v.z + v.w*v.w;
        __half h0 = __float2half_rn(v.x), h1 = __float2half_rn(v.y);
        __half h2 = __float2half_rn(v.z), h3 = __float2half_rn(v.w);
        __half l0 = __float2half_rn(v.x - __half2float(h0));
        __half l1 = __float2half_rn(v.y - __half2float(h1));
        __half l2 = __float2half_rn(v.z - __half2float(h2));
        __half l3 = __float2half_rn(v.w - __half2float(h3));
        int e = (lane + i*32)*4;
        __half2 a; a.x = h0; a.y = h1; *(__half2*)(dh + e)     = a;
        __half2 c; c.x = h2; c.y = h3; *(__half2*)(dh + e + 2) = c;
        __half2 p; p.x = l0; p.y = l1; *(__half2*)(dh + 1024 + e)     = p;
        __half2 q; q.x = l2; q.y = l3; *(__half2*)(dh + 1024 + e + 2) = q;
    }
    #pragma unroll
    for(int o=16;o;o>>=1) ss += __shfl_xor_sync(0xffffffffu, ss, o);
    if(lane==0) g_kfinv[row] = 1.0f / fmaxf(sqrtf(ss), 1e-12f);
}

// ---------------- tensor-core sim: C[160pad,64] = KF * I^T, fused argmax ----
// fp16 3-term split: KFh*Ih + KFl*Ih + KFh*Il ; fp32 accum; scale by kfinv.
#define SIMH_STAGE 57344
#define SIMH_SMEM  (2*SIMH_STAGE)
#define S_KFH 0
#define S_KFL 20480
#define S_IH  40960
#define S_IL  49152

__global__ void __launch_bounds__(256, 1) k_sim_mma(int n){
    extern __shared__ char sm[];
    uint32_t sb = smem_to_u32(sm);
    int b = blockIdx.y, tile0 = blockIdx.x*64;
    int tid = threadIdx.x, wid = tid >> 5, l = tid & 31;
    int wm = wid & 1, wn = wid >> 1;   // 2(m) x 4(n); warp tile 80x16

    __shared__ int   stok[64];
    __shared__ float kfinv_s[KFK];
    __shared__ float svals[2][64];
    __shared__ int   sidx [2][64];

    // zero both stages (pad kf rows 147..159 and missing token rows stay 0)
    for(int i=tid; i<SIMH_SMEM/16; i+=256) *(uint4*)(sm + i*16) = make_uint4(0,0,0,0);
    if(tid < 64){
        int s = tile0 + tid;
        stok[tid] = (s < n) ? g_surv[b*NI0 + s] : -1;
    }
    if(tid < KFK) kfinv_s[tid] = g_kfinv[b*KFK + tid];
    __syncthreads();

    const __half* KF = g_KFhl + (size_t)b*KFK*2048;

    float acc[5][2][4];
    #pragma unroll
    for(int mt=0;mt<5;mt++)
        #pragma unroll
        for(int ntp=0;ntp<2;ntp++)
            #pragma unroll
            for(int q=0;q<4;q++) acc[mt][ntp][q] = 0.f;

    #define SIMLOAD(kc, buf) { \
        uint32_t base_ = sb + (buf)*SIMH_STAGE; \
        _Pragma("unroll") \
        for(int i_=0;i_<10;i_++){ \
            int u_ = tid + i_*256; \
            int row_ = u_ >> 4, q_ = u_ & 15; \
            int seg_ = q_ & 7, hl_ = q_ >> 3; \
            if(row_ < KFK) \
                cp_async16(base_ + (hl_?S_KFL:S_KFH) + SW128((uint32_t)(row_*128 + seg_*16)), \
                           KF + (size_t)row_*2048 + hl_*1024 + (kc)*64 + seg_*8); \
        } \
        _Pragma("unroll") \
        for(int i_=0;i_<4;i_++){ \
            int u_ = tid + i_*256; \
            int row_ = u_ >> 4, q_ = u_ & 15; \
            int seg_ = q_ & 7, hl_ = q_ >> 3; \
            int tok_ = stok[row_]; \
            if(tok_ >= 0) \
                cp_async16(base_ + (hl_?S_IL:S_IH) + SW128((uint32_t)(row_*128 + seg_*16)), \
                           g_Ihl + ((size_t)b*NI0 + tok_)*2048 + hl_*1024 + (kc)*64 + seg_*8); \
        } }

    SIMLOAD(0, 0); cp_commit();
    SIMLOAD(1, 1); cp_commit();

    for(int t=0; t<16; t++){
        cp_wait1();
        __syncthreads();
        uint32_t sbuf = sb + (t & 1)*SIMH_STAGE;
        #pragma unroll
        for(int ks=0; ks<4; ks++){
            uint32_t aH[5][4], aL[5][4];
            #pragma unroll
            for(int mt=0; mt<5; mt++){
                uint32_t aoff = SW128((uint32_t)((wm*80 + mt*16 + (l & 15))*128 + ks*32 + (l >> 4)*16));
                ldmx4(aH[mt], sbuf + S_KFH + aoff);
                ldmx4(aL[mt], sbuf + S_KFL + aoff);
            }
            uint32_t bH[4], bL[4];
            uint32_t boff = SW128((uint32_t)((wn*16 + (l & 7) + ((l >> 4) << 3))*128 + ks*32 + ((l >> 3) & 1)*16));
            ldmx4(bH, sbuf + S_IH + boff);
            ldmx4(bL, sbuf + S_IL + boff);
            #pragma unroll
            for(int mt=0; mt<5; mt++){
                #pragma unroll
                for(int ntp=0; ntp<2; ntp++){
                    mma16816h(acc[mt][ntp], aH[mt], bH[ntp*2], bH[ntp*2+1]);
                    mma16816h(acc[mt][ntp], aL[mt], bH[ntp*2], bH[ntp*2+1]);
                    mma16816h(acc[mt][ntp], aH[mt], bL[ntp*2], bL[ntp*2+1]);
                }
            }
        }
        __syncthreads();
        if(t+2 < 16){ SIMLOAD(t+2, t & 1); }
        cp_commit();
    }

    // ---- epilogue: scale by kfinv, first-argmax over kf rows ----
    float bv[4]; int bi[4];
    #pragma unroll
    for(int ci=0; ci<4; ci++){ bv[ci] = -3.0e38f; bi[ci] = 0x7fffffff; }
    #pragma unroll
    for(int mt=0; mt<5; mt++){
        #pragma unroll
        for(int h=0; h<2; h++){
            int row = wm*80 + mt*16 + (l >> 2) + h*8;
            if(row < KFK){
                float inv = kfinv_s[row];
                #pragma unroll
                for(int ntp=0; ntp<2; ntp++){
                    #pragma unroll
                    for(int c01=0; c01<2; c01++){
                        int ci = ntp*2 + c01;
                        float v = acc[mt][ntp][h*2 + c01] * inv;
                        if(v > bv[ci]){ bv[ci] = v; bi[ci] = row; }
                    }
                }
            }
        }
    }
    #pragma unroll
    for(int off=4; off<32; off<<=1){
        #pragma unroll
        for(int ci=0; ci<4; ci++){
            float ov = __shfl_xor_sync(0xffffffffu, bv[ci], off);
            int   oi = __shfl_xor_sync(0xffffffffu, bi[ci], off);
            if(ov > bv[ci] || (ov == bv[ci] && oi < bi[ci])){ bv[ci] = ov; bi[ci] = oi; }
        }
    }
    if(l < 4){
        #pragma unroll
        for(int ci=0; ci<4; ci++){
            int col = wn*16 + (ci >> 1)*8 + l*2 + (ci & 1);
            svals[wm][col] = bv[ci];
            sidx [wm][col] = bi[ci];
        }
    }
    __syncthreads();
    if(tid < 64){
        int s = tile0 + tid;
        if(s < n){
            float v0 = svals[0][tid], v1 = svals[1][tid];
            int   i0 = sidx[0][tid],  i1 = sidx[1][tid];
            bool take1 = (v1 > v0) || (v1 == v0 && i1 < i0);
            g_maxsim[b*NI0 + s] = take1 ? v1 : v0;
            g_bestkf[b*NI0 + s] = take1 ? i1 : i0;
        }
    }
}

__global__ void k_merge(const float* __restrict__ x, int n, int nm){
    int b = blockIdx.x, t = threadIdx.x;
    __shared__ float key[1024];
    __shared__ int   pos[1024];
    __shared__ int   mpos[196], mtgt[196], mtok[196];
    __shared__ unsigned char mflag[NI0];
    key[t] = (t < n) ? -g_maxsim[b*NI0 + t] : __int_as_float(0x7f800000);
    pos[t] = t;
    bitonic_sort(key, pos, 1024);
    if(t < nm){
        int p = pos[t];
        mpos[t] = p;
        mtgt[t] = g_bestkf[b*NI0 + p];
        mtok[t] = g_surv  [b*NI0 + p];
    }
    __syncthreads();
    if(nm > 0){
        float cur = x[((size_t)b*TCLIP + KFT + mtok[0])*DDIM + t];
        for(int m=0;m<nm;m++){
            float nxt = (m+1 < nm) ? x[((size_t)b*TCLIP + KFT + mtok[m+1])*DDIM + t] : 0.f;
            g_kfsum[((size_t)b*KFK + mtgt[m])*DDIM + t] += cur;
            if(t==0) g_kfcnt[b*KFK + mtgt[m]] += 1.0f;
            cur = nxt;
        }
    }
    for(int i=t;i<n;i+=1024) mflag[i] = 0;
    __syncthreads();
    if(t < nm) mflag[mpos[t]] = 1;
    __syncthreads();
    if(t==0){
        int c = 0;
        for(int p=0;p<n;p++)
            if(!mflag[p]){ int v = g_surv[b*NI0 + p]; g_surv[b*NI0 + c] = v; c++; }
    }
}

// fused z + fp16 convert: write g_A1 row (stride DDIM); incr rows from raw x
__global__ void k_z_half(const float* __restrict__ x, __half* __restrict__ dst){
    int b = blockIdx.x / NFIN, r = blockIdx.x % NFIN;
    __half* d = dst + ((size_t)b*NFIN + r)*DDIM;
    if(r < KFK){
        float invc = 1.0f / g_kfcnt[b*KFK + r];
        const float* s = g_kfsum + ((size_t)b*KFK + r)*DDIM;
        for(int i=threadIdx.x;i<DDIM;i+=256)
            d[i] = __float2half_rn(s[i]*invc);
    } else {
        int tok = g_surv[b*NI0 + (r - KFK)];
        const float* s = x + ((size_t)b*TCLIP + KFT + tok)*DDIM;
        for(int i=threadIdx.x;i<DDIM;i+=256)
            d[i] = __float2half_rn(s[i]);
    }
}

// W fp32 [K,N] -> Bt fp16 [N, 2K]: [hi | lo] along K
__global__ void k_splitW(const float* __restrict__ w, __half* __restrict__ bt, int K, int N){
    __shared__ float tile[32][33];
    int kb = blockIdx.y*32, nb = blockIdx.x*32;
    int tx = threadIdx.x & 31, ty = threadIdx.x >> 5;
    for(int i=ty;i<32;i+=8) tile[i][tx] = w[(size_t)(kb+i)*N + nb + tx];
    __syncthreads();
    for(int i=ty;i<32;i+=8){
        float v = tile[tx][i];
        __half h = __float2half_rn(v);
        __half l = __float2half_rn(v - __half2float(h));
        size_t base = (size_t)(nb+i)*2*K + kb + tx;
        bt[base]     = h;
        bt[base + K] = l;
    }
}

// ---------------- fp16 HMMA GEMM, 2-pass super-stage, 256x128x64 ------------
#define BM 256
#define BN 128
#define BK 64
#define OFF_BHI 32768
#define OFF_BLO 49152
#define STAGE_BYTES 65536
#define SMEM_GEMM (2*STAGE_BYTES)   // 128KB

template<int K, int MODE>
__global__ void __launch_bounds__(512, 1) mma_gemm(
    const __half* __restrict__ A, const __half* __restrict__ Bt,
    const float* __restrict__ bias, float* __restrict__ outF,
    __half* __restrict__ outS)
{
    extern __shared__ char smem[];
    uint32_t sb = smem_to_u32(smem);
    int tid = threadIdx.x, wid = tid >> 5, l = tid & 31;
    int row0 = blockIdx.y * BM, col0 = blockIdx.x * BN;
    int wm = wid & 7, wn = wid >> 3;
    const int T = K / BK;

    float acc[2][8][4];
    #pragma unroll
    for(int mt=0;mt<2;mt++)
        #pragma unroll
        for(int nt=0;nt<8;nt++)
            #pragma unroll
            for(int q=0;q<4;q++) acc[mt][nt][q] = 0.f;

    int ra   = wm*32 + (l & 15);
    int ca16 = (l >> 4) * 16;
    int rb   = wn*64 + (l & 7) + ((l >> 4) << 3);
    int cb16 = ((l >> 3) & 1) * 16;

    #define LOADS(s, buf) { \
        uint32_t base_ = sb + (buf)*STAGE_BYTES; \
        int w0_ = (s)*BK; \
        const __half* Ap_ = A  + (size_t)row0*K + w0_; \
        const __half* Bp_ = Bt + (size_t)col0*(2*K) + w0_; \
        _Pragma("unroll") \
        for(int i_=0;i_<4;i_++){ \
            int u_ = tid + i_*512; \
            int r_ = u_ >> 3, sg_ = u_ & 7; \
            cp_async16(base_ + SW128((uint32_t)(r_*128 + sg_*16)), Ap_ + (size_t)r_*K + sg_*8); \
        } \
        _Pragma("unroll") \
        for(int i_=0;i_<2;i_++){ \
            int u_ = tid + i_*512; \
            int r_ = u_ >> 3, sg_ = u_ & 7; \
            uint32_t off_ = SW128((uint32_t)(r_*128 + sg_*16)); \
            const __half* b_ = Bp_ + (size_t)r_*(2*K) + sg_*8; \
            cp_async16(base_ + OFF_BHI + off_, b_); \
            cp_async16(base_ + OFF_BLO + off_, b_ + K); \
        } }

    LOADS(0, 0); cp_commit();
    LOADS(1, 1); cp_commit();

    for(int t=0; t<T; t++){
        cp_wait1();
        __syncthreads();

        uint32_t sbuf = sb + (t & 1)*STAGE_BYTES;
        #pragma unroll
        for(int ks=0; ks<4; ks++){
            uint32_t a[2][4];
            #pragma unroll
            for(int mt=0; mt<2; mt++)
                ldmx4(a[mt], sbuf + SW128((uint32_t)((ra + mt*16)*128 + ks*32 + ca16)));
            #pragma unroll
            for(int ntp=0; ntp<4; ntp++){
                uint32_t boff = SW128((uint32_t)((rb + ntp*16)*128 + ks*32 + cb16));
                uint32_t bH[4], bL[4];
                ldmx4(bH, sbuf + OFF_BHI + boff);
                ldmx4(bL, sbuf + OFF_BLO + boff);
                #pragma unroll
                for(int mt=0; mt<2; mt++){
                    mma16816h(acc[mt][ntp*2],   a[mt], bH[0], bH[1]);
                    mma16816h(acc[mt][ntp*2+1], a[mt], bH[2], bH[3]);
                    mma16816h(acc[mt][ntp*2],   a[mt], bL[0], bL[1]);
                    mma16816h(acc[mt][ntp*2+1], a[mt], bL[2], bL[3]);
                }
            }
        }
        __syncthreads();
        if(t+2 < T){ LOADS(t+2, t & 1); }
        cp_commit();
    }

    // ---- epilogue ----
    #pragma unroll
    for(int mt=0; mt<2; mt++){
        #pragma unroll
        for(int nt=0; nt<8; nt++){
            float* a4 = acc[mt][nt];
            int r = row0 + wm*32 + mt*16 + (l >> 2);
            int c = col0 + wn*64 + nt*8 + ((l & 3) << 1);
            float bi0 = bias[c], bi1 = bias[c+1];
            if(MODE == 0){
                float2 v0; v0.x = a4[0] + bi0; v0.y = a4[1] + bi1;
                float2 v1; v1.x = a4[2] + bi0; v1.y = a4[3] + bi1;
                *(float2*)(outF + (size_t)r*HDIM + c)     = v0;
                *(float2*)(outF + (size_t)(r+8)*HDIM + c) = v1;
            } else {
                #pragma unroll
                for(int hrow=0; hrow<2; hrow++){
                    float v0 = gelu_exact(a4[hrow*2+0] + bi0);
                    float v1 = gelu_exact(a4[hrow*2+1] + bi1);
                    __half2 hh;
                    hh.x = __float2half_rn(v0);
                    hh.y = __float2half_rn(v1);
                    *(__half2*)(outS + (size_t)(r + hrow*8)*HDIM + c) = hh;
                }
            }
        }
    }
}

// ---------------- launch ----------------
extern "C" void kernel_launch(void* const* d_in, const int* in_sizes, int n_in,
                              void* d_out, int out_size){
    (void)in_sizes; (void)n_in; (void)out_size;
    const float* x  = (const float*)d_in[0];
    const float* w1 = (const float*)d_in[1];
    const float* b1 = (const float*)d_in[2];
    const float* w2 = (const float*)d_in[3];
    const float* b2 = (const float*)d_in[4];
    float* out = (float*)d_out;

    __half *pBt1, *pBt2, *pA1, *pA2;
    cudaGetSymbolAddress((void**)&pBt1, g_Bt1);
    cudaGetSymbolAddress((void**)&pBt2, g_Bt2);
    cudaGetSymbolAddress((void**)&pA1, g_A1);
    cudaGetSymbolAddress((void**)&pA2, g_A2);

    k_splitW<<<dim3(HDIM/32, DDIM/32), 256>>>(w1, pBt1, DDIM, HDIM);
    k_splitW<<<dim3(HDIM/32, HDIM/32), 256>>>(w2, pBt2, HDIM, HDIM);

    k_normalize<<<NCLIP*TCLIP, 256>>>(x);
    k_sumrows<<<dim3(NCLIP, 4), 256>>>();
    k_reddot<<<NCLIP*KFT, 256>>>();
    k_select<<<NCLIP, 256>>>();
    k_init<<<NCLIP*KFK, 256>>>(x);

    cudaFuncSetAttribute(k_sim_mma, cudaFuncAttributeMaxDynamicSharedMemorySize, SIMH_SMEM);

    const int nlist[7] = {588, 392, 262, 175, 117, 78, 52};
    const int mlist[7] = {196, 130,  87,  58,  39, 26,  3};
    for(int it=0; it<7; it++){
        int n = nlist[it];
        k_norms<<<(NCLIP*KFK + 7)/8, 256>>>();
        k_sim_mma<<<dim3((n+63)/64, NCLIP), 256, SIMH_SMEM>>>(n);
        k_merge<<<NCLIP, 1024>>>(x, n, mlist[it]);
    }
    k_z_half<<<NCLIP*NFIN, 256>>>(x, pA1);

    cudaFuncSetAttribute(mma_gemm<DDIM,1>, cudaFuncAttributeMaxDynamicSharedMemorySize, SMEM_GEMM);
    cudaFuncSetAttribute(mma_gemm<HDIM,0>, cudaFuncAttributeMaxDynamicSharedMemorySize, SMEM_GEMM);
    dim3 grid(HDIM/BN, MROWS/BM);   // (32, 49)
    mma_gemm<DDIM,1><<<grid, 512, SMEM_GEMM>>>(pA1, pBt1, b1, nullptr, pA2);
    mma_gemm<HDIM,0><<<grid, 512, SMEM_GEMM>>>(pA2, pBt2, b2, out, nullptr);
}

// round 13
// speedup vs baseline: 4.4219x; 1.0003x over previous
#include <cuda_runtime.h>
#include <cuda_bf16.h>
#include <cuda_fp16.h>
#include <math.h>
#include <stdint.h>

// Problem constants
#define NCLIP 64
#define TCLIP 784
#define DDIM  1024
#define KFT   196
#define KFK   147
#define NI0   588
#define NFIN  196
#define HDIM  4096
#define MROWS (NCLIP*NFIN)   // 12544

// ---------------- scratch (device globals) ----------------
__device__ float g_kfn  [NCLIP*KFT*DDIM];
__device__ float g_Sp   [NCLIP*4*DDIM];
__device__ float g_red  [NCLIP*KFT];
__device__ int   g_keep [NCLIP*KFK];
__device__ float g_kfsum[NCLIP*KFK*DDIM];
__device__ float g_kfcnt[NCLIP*KFK];
__device__ float g_kfinv[NCLIP*KFK];
__device__ float g_maxsim[NCLIP*NI0];
__device__ int   g_bestkf[NCLIP*NI0];
__device__ int   g_surv [NCLIP*NI0];

// fp16 hi|lo token / kf buffers for tensor-core sim (row stride 2048 halves)
__device__ __half g_Ihl [(size_t)NCLIP*NI0*2048];
__device__ __half g_KFhl[(size_t)NCLIP*KFK*2048];

// fp16 GEMM operands: A plain fp16 (stride K); B^T split [hi|lo] (stride 2K)
__device__ __half g_A1 [(size_t)MROWS*DDIM];
__device__ __half g_A2 [(size_t)MROWS*HDIM];
__device__ __half g_Bt1[(size_t)HDIM*2*DDIM];
__device__ __half g_Bt2[(size_t)HDIM*2*HDIM];

// ---------------- low-level helpers ----------------
__device__ __forceinline__ uint32_t smem_to_u32(const void* p){
    uint32_t a;
    asm("{ .reg .u64 t; cvta.to.shared.u64 t, %1; cvt.u32.u64 %0, t; }" : "=r"(a) : "l"(p));
    return a;
}
#define SW128(off) ((off) ^ (((off) >> 3) & 0x70))

__device__ __forceinline__ void cp_async16(uint32_t saddr, const void* gaddr){
    asm volatile("cp.async.cg.shared.global [%0], [%1], 16;" :: "r"(saddr), "l"(gaddr));
}
__device__ __forceinline__ void cp_commit(){ asm volatile("cp.async.commit_group;" ::: "memory"); }
__device__ __forceinline__ void cp_wait1(){ asm volatile("cp.async.wait_group 1;" ::: "memory"); }

__device__ __forceinline__ void ldmx4(uint32_t* r, uint32_t addr){
    asm volatile("ldmatrix.sync.aligned.m8n8.x4.shared.b16 {%0,%1,%2,%3}, [%4];"
        : "=r"(r[0]), "=r"(r[1]), "=r"(r[2]), "=r"(r[3]) : "r"(addr));
}
__device__ __forceinline__ void mma16816h(float* c, const uint32_t* a, uint32_t b0, uint32_t b1){
    asm volatile("mma.sync.aligned.m16n8k16.row.col.f32.f16.f16.f32 "
        "{%0,%1,%2,%3}, {%4,%5,%6,%7}, {%8,%9}, {%0,%1,%2,%3};"
        : "+f"(c[0]), "+f"(c[1]), "+f"(c[2]), "+f"(c[3])
        : "r"(a[0]), "r"(a[1]), "r"(a[2]), "r"(a[3]), "r"(b0), "r"(b1));
}

// ---------------- generic helpers ----------------
__device__ __forceinline__ float blockSum256(float v){
    __shared__ float sh[8];
    int lane = threadIdx.x & 31, w = threadIdx.x >> 5;
    #pragma unroll
    for(int o=16;o;o>>=1) v += __shfl_xor_sync(0xffffffffu, v, o);
    if(lane==0) sh[w] = v;
    __syncthreads();
    float r = (threadIdx.x < 8) ? sh[threadIdx.x] : 0.f;
    if(w==0){
        #pragma unroll
        for(int o=4;o;o>>=1) r += __shfl_xor_sync(0xffffffffu, r, o);
        if(lane==0) sh[0] = r;
    }
    __syncthreads();
    float out = sh[0];
    __syncthreads();
    return out;
}

__device__ __forceinline__ void bitonic_sort(float* key, int* pos, int N){
    int t = threadIdx.x;
    for(int k=2;k<=N;k<<=1){
        for(int j=k>>1;j>0;j>>=1){
            __syncthreads();
            int ixj = t ^ j;
            if(ixj > t){
                float ka = key[t], kb = key[ixj];
                int   pa = pos[t], pb = pos[ixj];
                bool agtb = (ka > kb) || (ka == kb && pa > pb);
                bool up = ((t & k) == 0);
                if(agtb == up){
                    key[t]=kb; key[ixj]=ka;
                    pos[t]=pb; pos[ixj]=pa;
                }
            }
        }
    }
    __syncthreads();
}

__device__ __forceinline__ float gelu_exact(float v){
    return 0.5f * v * (1.0f + erff(v * 0.70710678118654752440f));
}

// ---------------- compression kernels ----------------
// kf rows -> fp32 g_kfn (for redundancy); incr rows -> normalized fp16 hi|lo g_Ihl
__global__ void k_normalize(const float* __restrict__ x){
    int b = blockIdx.x / TCLIP;
    int r = blockIdx.x % TCLIP;
    const float* row = x + ((size_t)b*TCLIP + r)*DDIM;
    float ss = 0.f;
    for(int i=threadIdx.x;i<DDIM;i+=256){ float v = row[i]; ss += v*v; }
    ss = blockSum256(ss);
    float inv = 1.0f / fmaxf(sqrtf(ss), 1e-12f);
    if(r < KFT){
        float* dst = g_kfn + ((size_t)b*KFT + r)*DDIM;
        for(int i=threadIdx.x;i<DDIM;i+=256) dst[i] = row[i]*inv;
    } else {
        __half* d = g_Ihl + ((size_t)b*NI0 + (r - KFT))*2048;
        for(int i=threadIdx.x;i<DDIM;i+=256){
            float v = row[i]*inv;
            __half h = __float2half_rn(v);
            d[i] = h;
            d[1024+i] = __float2half_rn(v - __half2float(h));
        }
    }
}

// split-K partial row sums of g_kfn: 4 chunks of 49 rows
__global__ void k_sumrows(){
    int b = blockIdx.x, part = blockIdx.y;
    int d0 = threadIdx.x * 4;
    int j0 = part*49, j1 = j0 + 49;
    float4 acc = make_float4(0.f,0.f,0.f,0.f);
    const float* base = g_kfn + (size_t)b*KFT*DDIM + d0;
    for(int j=j0;j<j1;j++){
        float4 v = *(const float4*)(base + (size_t)j*DDIM);
        acc.x += v.x; acc.y += v.y; acc.z += v.z; acc.w += v.w;
    }
    *(float4*)(g_Sp + ((size_t)b*4 + part)*DDIM + d0) = acc;
}

__global__ void k_reddot(){
    int b = blockIdx.x / KFT, i = blockIdx.x % KFT;
    const float* ri = g_kfn + ((size_t)b*KFT + i)*DDIM;
    const float* S0 = g_Sp + (size_t)b*4*DDIM;
    float s = 0.f;
    for(int d=threadIdx.x; d<DDIM; d+=256)
        s += ri[d]*(S0[d] + S0[DDIM+d] + S0[2*DDIM+d] + S0[3*DDIM+d]);
    s = blockSum256(s);
    if(threadIdx.x==0) g_red[b*KFT + i] = s - 1.0f;
}

__global__ void k_select(){
    int b = blockIdx.x;
    __shared__ float key[256];
    __shared__ int   pos[256];
    __shared__ unsigned char kept[KFT];
    int t = threadIdx.x;
    key[t] = (t < KFT) ? g_red[b*KFT + t] : __int_as_float(0x7f800000);
    pos[t] = t;
    if(t < KFT) kept[t] = 0;
    bitonic_sort(key, pos, 256);
    if(t < KFK) kept[pos[t]] = 1;
    __syncthreads();
    if(t==0){
        int c = 0;
        for(int i=0;i<KFT;i++) if(kept[i]) g_keep[b*KFK + (c++)] = i;
    }
    for(int s=t;s<NI0;s+=256) g_surv[b*NI0 + s] = s;
}

__global__ void k_init(const float* __restrict__ x){
    int b = blockIdx.x / KFK, k = blockIdx.x % KFK;
    int src = g_keep[b*KFK + k];
    const float* row = x + ((size_t)b*TCLIP + src)*DDIM;
    float* dst = g_kfsum + ((size_t)b*KFK + k)*DDIM;
    for(int i=threadIdx.x;i<DDIM;i+=256) dst[i] = row[i];
    if(threadIdx.x==0) g_kfcnt[b*KFK + k] = 1.0f;
}

// per-kf inverse norm of kfsum + fp16 hi|lo re-split (count cancels in l2norm)
__global__ void k_norms(){
    int row = blockIdx.x*8 + (threadIdx.x >> 5);
    if(row >= NCLIP*KFK) return;
    int lane = threadIdx.x & 31;
    const float4* s = (const float4*)(g_kfsum + (size_t)row*DDIM);
    __half* dh = g_KFhl + (size_t)row*2048;
    float ss = 0.f;
    #pragma unroll
    for(int i=0;i<8;i++){
        float4 v = s[lane + i*32];
        ss += v.x*v.x + v.y*v.y + v.z*v.z + v.w*v.w;
        __half h0 = __float2half_rn(v.x), h1 = __float2half_rn(v.y);
        __half h2 = __float2half_rn(v.z), h3 = __float2half_rn(v.w);
        __half l0 = __float2half_rn(v.x - __half2float(h0));
        __half l1 = __float2half_rn(v.y - __half2float(h1));
        __half l2 = __float2half_rn(v.z - __half2float(h2));
        __half l3 = __float2half_rn(v.w - __half2float(h3));
        int e = (lane + i*32)*4;
        __half2 a; a.x = h0; a.y = h1; *(__half2*)(dh + e)     = a;
        __half2 c; c.x = h2; c.y = h3; *(__half2*)(dh + e + 2) = c;
        __half2 p; p.x = l0; p.y = l1; *(__half2*)(dh + 1024 + e)     = p;
        __half2 q; q.x = l2; q.y = l3; *(__half2*)(dh + 1024 + e + 2) = q;
    }
    #pragma unroll
    for(int o=16;o;o>>=1) ss += __shfl_xor_sync(0xffffffffu, ss, o);
    if(lane==0) g_kfinv[row] = 1.0f / fmaxf(sqrtf(ss), 1e-12f);
}

// ---------------- tensor-core sim: C[160pad,64] = KF * I^T, fused argmax ----
// fp16 3-term split: KFh*Ih + KFl*Ih + KFh*Il ; fp32 accum; scale by kfinv.
#define SIMH_STAGE 57344
#define SIMH_SMEM  (2*SIMH_STAGE)
#define S_KFH 0
#define S_KFL 20480
#define S_IH  40960
#define S_IL  49152

__global__ void __launch_bounds__(256, 1) k_sim_mma(int n){
    extern __shared__ char sm[];
    uint32_t sb = smem_to_u32(sm);
    int b = blockIdx.y, tile0 = blockIdx.x*64;
    int tid = threadIdx.x, wid = tid >> 5, l = tid & 31;
    int wm = wid & 1, wn = wid >> 1;   // 2(m) x 4(n); warp tile 80x16

    __shared__ int   stok[64];
    __shared__ float kfinv_s[KFK];
    __shared__ float svals[2][64];
    __shared__ int   sidx [2][64];

    // zero both stages (pad kf rows 147..159 and missing token rows stay 0)
    for(int i=tid; i<SIMH_SMEM/16; i+=256) *(uint4*)(sm + i*16) = make_uint4(0,0,0,0);
    if(tid < 64){
        int s = tile0 + tid;
        stok[tid] = (s < n) ? g_surv[b*NI0 + s] : -1;
    }
    if(tid < KFK) kfinv_s[tid] = g_kfinv[b*KFK + tid];
    __syncthreads();

    const __half* KF = g_KFhl + (size_t)b*KFK*2048;

    float acc[5][2][4];
    #pragma unroll
    for(int mt=0;mt<5;mt++)
        #pragma unroll
        for(int ntp=0;ntp<2;ntp++)
            #pragma unroll
            for(int q=0;q<4;q++) acc[mt][ntp][q] = 0.f;

    #define SIMLOAD(kc, buf) { \
        uint32_t base_ = sb + (buf)*SIMH_STAGE; \
        _Pragma("unroll") \
        for(int i_=0;i_<10;i_++){ \
            int u_ = tid + i_*256; \
            int row_ = u_ >> 4, q_ = u_ & 15; \
            int seg_ = q_ & 7, hl_ = q_ >> 3; \
            if(row_ < KFK) \
                cp_async16(base_ + (hl_?S_KFL:S_KFH) + SW128((uint32_t)(row_*128 + seg_*16)), \
                           KF + (size_t)row_*2048 + hl_*1024 + (kc)*64 + seg_*8); \
        } \
        _Pragma("unroll") \
        for(int i_=0;i_<4;i_++){ \
            int u_ = tid + i_*256; \
            int row_ = u_ >> 4, q_ = u_ & 15; \
            int seg_ = q_ & 7, hl_ = q_ >> 3; \
            int tok_ = stok[row_]; \
            if(tok_ >= 0) \
                cp_async16(base_ + (hl_?S_IL:S_IH) + SW128((uint32_t)(row_*128 + seg_*16)), \
                           g_Ihl + ((size_t)b*NI0 + tok_)*2048 + hl_*1024 + (kc)*64 + seg_*8); \
        } }

    SIMLOAD(0, 0); cp_commit();
    SIMLOAD(1, 1); cp_commit();

    for(int t=0; t<16; t++){
        cp_wait1();
        __syncthreads();
        uint32_t sbuf = sb + (t & 1)*SIMH_STAGE;
        #pragma unroll
        for(int ks=0; ks<4; ks++){
            uint32_t aH[5][4], aL[5][4];
            #pragma unroll
            for(int mt=0; mt<5; mt++){
                uint32_t aoff = SW128((uint32_t)((wm*80 + mt*16 + (l & 15))*128 + ks*32 + (l >> 4)*16));
                ldmx4(aH[mt], sbuf + S_KFH + aoff);
                ldmx4(aL[mt], sbuf + S_KFL + aoff);
            }
            uint32_t bH[4], bL[4];
            uint32_t boff = SW128((uint32_t)((wn*16 + (l & 7) + ((l >> 4) << 3))*128 + ks*32 + ((l >> 3) & 1)*16));
            ldmx4(bH, sbuf + S_IH + boff);
            ldmx4(bL, sbuf + S_IL + boff);
            #pragma unroll
            for(int mt=0; mt<5; mt++){
                #pragma unroll
                for(int ntp=0; ntp<2; ntp++){
                    mma16816h(acc[mt][ntp], aH[mt], bH[ntp*2], bH[ntp*2+1]);
                    mma16816h(acc[mt][ntp], aL[mt], bH[ntp*2], bH[ntp*2+1]);
                    mma16816h(acc[mt][ntp], aH[mt], bL[ntp*2], bL[ntp*2+1]);
                }
            }
        }
        __syncthreads();
        if(t+2 < 16){ SIMLOAD(t+2, t & 1); }
        cp_commit();
    }

    // ---- epilogue: scale by kfinv, first-argmax over kf rows ----
    float bv[4]; int bi[4];
    #pragma unroll
    for(int ci=0; ci<4; ci++){ bv[ci] = -3.0e38f; bi[ci] = 0x7fffffff; }
    #pragma unroll
    for(int mt=0; mt<5; mt++){
        #pragma unroll
        for(int h=0; h<2; h++){
            int row = wm*80 + mt*16 + (l >> 2) + h*8;
            if(row < KFK){
                float inv = kfinv_s[row];
                #pragma unroll
                for(int ntp=0; ntp<2; ntp++){
                    #pragma unroll
                    for(int c01=0; c01<2; c01++){
                        int ci = ntp*2 + c01;
                        float v = acc[mt][ntp][h*2 + c01] * inv;
                        if(v > bv[ci]){ bv[ci] = v; bi[ci] = row; }
                    }
                }
            }
        }
    }
    #pragma unroll
    for(int off=4; off<32; off<<=1){
        #pragma unroll
        for(int ci=0; ci<4; ci++){
            float ov = __shfl_xor_sync(0xffffffffu, bv[ci], off);
            int   oi = __shfl_xor_sync(0xffffffffu, bi[ci], off);
            if(ov > bv[ci] || (ov == bv[ci] && oi < bi[ci])){ bv[ci] = ov; bi[ci] = oi; }
        }
    }
    if(l < 4){
        #pragma unroll
        for(int ci=0; ci<4; ci++){
            int col = wn*16 + (ci >> 1)*8 + l*2 + (ci & 1);
            svals[wm][col] = bv[ci];
            sidx [wm][col] = bi[ci];
        }
    }
    __syncthreads();
    if(tid < 64){
        int s = tile0 + tid;
        if(s < n){
            float v0 = svals[0][tid], v1 = svals[1][tid];
            int   i0 = sidx[0][tid],  i1 = sidx[1][tid];
            bool take1 = (v1 > v0) || (v1 == v0 && i1 < i0);
            g_maxsim[b*NI0 + s] = take1 ? v1 : v0;
            g_bestkf[b*NI0 + s] = take1 ? i1 : i0;
        }
    }
}

__global__ void k_merge(const float* __restrict__ x, int n, int nm){
    int b = blockIdx.x, t = threadIdx.x;
    __shared__ float key[1024];
    __shared__ int   pos[1024];
    __shared__ int   mpos[196], mtgt[196], mtok[196];
    __shared__ unsigned char mflag[NI0];
    key[t] = (t < n) ? -g_maxsim[b*NI0 + t] : __int_as_float(0x7f800000);
    pos[t] = t;
    bitonic_sort(key, pos, 1024);
    if(t < nm){
        int p = pos[t];
        mpos[t] = p;
        mtgt[t] = g_bestkf[b*NI0 + p];
        mtok[t] = g_surv  [b*NI0 + p];
    }
    __syncthreads();
    if(nm > 0){
        float cur = x[((size_t)b*TCLIP + KFT + mtok[0])*DDIM + t];
        for(int m=0;m<nm;m++){
            float nxt = (m+1 < nm) ? x[((size_t)b*TCLIP + KFT + mtok[m+1])*DDIM + t] : 0.f;
            g_kfsum[((size_t)b*KFK + mtgt[m])*DDIM + t] += cur;
            if(t==0) g_kfcnt[b*KFK + mtgt[m]] += 1.0f;
            cur = nxt;
        }
    }
    for(int i=t;i<n;i+=1024) mflag[i] = 0;
    __syncthreads();
    if(t < nm) mflag[mpos[t]] = 1;
    __syncthreads();
    if(t==0){
        int c = 0;
        for(int p=0;p<n;p++)
            if(!mflag[p]){ int v = g_surv[b*NI0 + p]; g_surv[b*NI0 + c] = v; c++; }
    }
}

// fused z + fp16 convert: write g_A1 row (stride DDIM); incr rows from raw x
__global__ void k_z_half(const float* __restrict__ x, __half* __restrict__ dst){
    int b = blockIdx.x / NFIN, r = blockIdx.x % NFIN;
    __half* d = dst + ((size_t)b*NFIN + r)*DDIM;
    if(r < KFK){
        float invc = 1.0f / g_kfcnt[b*KFK + r];
        const float* s = g_kfsum + ((size_t)b*KFK + r)*DDIM;
        for(int i=threadIdx.x;i<DDIM;i+=256)
            d[i] = __float2half_rn(s[i]*invc);
    } else {
        int tok = g_surv[b*NI0 + (r - KFK)];
        const float* s = x + ((size_t)b*TCLIP + KFT + tok)*DDIM;
        for(int i=threadIdx.x;i<DDIM;i+=256)
            d[i] = __float2half_rn(s[i]);
    }
}

// W fp32 [K,N] -> Bt fp16 [N, 2K]: [hi | lo] along K
__global__ void k_splitW(const float* __restrict__ w, __half* __restrict__ bt, int K, int N){
    __shared__ float tile[32][33];
    int kb = blockIdx.y*32, nb = blockIdx.x*32;
    int tx = threadIdx.x & 31, ty = threadIdx.x >> 5;
    for(int i=ty;i<32;i+=8) tile[i][tx] = w[(size_t)(kb+i)*N + nb + tx];
    __syncthreads();
    for(int i=ty;i<32;i+=8){
        float v = tile[tx][i];
        __half h = __float2half_rn(v);
        __half l = __float2half_rn(v - __half2float(h));
        size_t base = (size_t)(nb+i)*2*K + kb + tx;
        bt[base]     = h;
        bt[base + K] = l;
    }
}

// ---------------- fp16 HMMA GEMM, 2-pass super-stage, 256x128x64 ------------
#define BM 256
#define BN 128
#define BK 64
#define OFF_BHI 32768
#define OFF_BLO 49152
#define STAGE_BYTES 65536
#define SMEM_GEMM (2*STAGE_BYTES)   // 128KB

template<int K, int MODE>
__global__ void __launch_bounds__(512, 1) mma_gemm(
    const __half* __restrict__ A, const __half* __restrict__ Bt,
    const float* __restrict__ bias, float* __restrict__ outF,
    __half* __restrict__ outS)
{
    extern __shared__ char smem[];
    uint32_t sb = smem_to_u32(smem);
    int tid = threadIdx.x, wid = tid >> 5, l = tid & 31;
    int row0 = blockIdx.y * BM, col0 = blockIdx.x * BN;
    int wm = wid & 7, wn = wid >> 3;
    const int T = K / BK;

    float acc[2][8][4];
    #pragma unroll
    for(int mt=0;mt<2;mt++)
        #pragma unroll
        for(int nt=0;nt<8;nt++)
            #pragma unroll
            for(int q=0;q<4;q++) acc[mt][nt][q] = 0.f;

    int ra   = wm*32 + (l & 15);
    int ca16 = (l >> 4) * 16;
    int rb   = wn*64 + (l & 7) + ((l >> 4) << 3);
    int cb16 = ((l >> 3) & 1) * 16;

    #define LOADS(s, buf) { \
        uint32_t base_ = sb + (buf)*STAGE_BYTES; \
        int w0_ = (s)*BK; \
        const __half* Ap_ = A  + (size_t)row0*K + w0_; \
        const __half* Bp_ = Bt + (size_t)col0*(2*K) + w0_; \
        _Pragma("unroll") \
        for(int i_=0;i_<4;i_++){ \
            int u_ = tid + i_*512; \
            int r_ = u_ >> 3, sg_ = u_ & 7; \
            cp_async16(base_ + SW128((uint32_t)(r_*128 + sg_*16)), Ap_ + (size_t)r_*K + sg_*8); \
        } \
        _Pragma("unroll") \
        for(int i_=0;i_<2;i_++){ \
            int u_ = tid + i_*512; \
            int r_ = u_ >> 3, sg_ = u_ & 7; \
            uint32_t off_ = SW128((uint32_t)(r_*128 + sg_*16)); \
            const __half* b_ = Bp_ + (size_t)r_*(2*K) + sg_*8; \
            cp_async16(base_ + OFF_BHI + off_, b_); \
            cp_async16(base_ + OFF_BLO + off_, b_ + K); \
        } }

    LOADS(0, 0); cp_commit();
    LOADS(1, 1); cp_commit();

    for(int t=0; t<T; t++){
        cp_wait1();
        __syncthreads();

        uint32_t sbuf = sb + (t & 1)*STAGE_BYTES;
        #pragma unroll
        for(int ks=0; ks<4; ks++){
            uint32_t a[2][4];
            #pragma unroll
            for(int mt=0; mt<2; mt++)
                ldmx4(a[mt], sbuf + SW128((uint32_t)((ra + mt*16)*128 + ks*32 + ca16)));
            #pragma unroll
            for(int ntp=0; ntp<4; ntp++){
                uint32_t boff = SW128((uint32_t)((rb + ntp*16)*128 + ks*32 + cb16));
                uint32_t bH[4], bL[4];
                ldmx4(bH, sbuf + OFF_BHI + boff);
                ldmx4(bL, sbuf + OFF_BLO + boff);
                #pragma unroll
                for(int mt=0; mt<2; mt++){
                    mma16816h(acc[mt][ntp*2],   a[mt], bH[0], bH[1]);
                    mma16816h(acc[mt][ntp*2+1], a[mt], bH[2], bH[3]);
                    mma16816h(acc[mt][ntp*2],   a[mt], bL[0], bL[1]);
                    mma16816h(acc[mt][ntp*2+1], a[mt], bL[2], bL[3]);
                }
            }
        }
        __syncthreads();
        if(t+2 < T){ LOADS(t+2, t & 1); }
        cp_commit();
    }

    // ---- epilogue ----
    #pragma unroll
    for(int mt=0; mt<2; mt++){
        #pragma unroll
        for(int nt=0; nt<8; nt++){
            float* a4 = acc[mt][nt];
            int r = row0 + wm*32 + mt*16 + (l >> 2);
            int c = col0 + wn*64 + nt*8 + ((l & 3) << 1);
            float bi0 = bias[c], bi1 = bias[c+1];
            if(MODE == 0){
                float2 v0; v0.x = a4[0] + bi0; v0.y = a4[1] + bi1;
                float2 v1; v1.x = a4[2] + bi0; v1.y = a4[3] + bi1;
                *(float2*)(outF + (size_t)r*HDIM + c)     = v0;
                *(float2*)(outF + (size_t)(r+8)*HDIM + c) = v1;
            } else {
                #pragma unroll
                for(int hrow=0; hrow<2; hrow++){
                    float v0 = gelu_exact(a4[hrow*2+0] + bi0);
                    float v1 = gelu_exact(a4[hrow*2+1] + bi1);
                    __half2 hh;
                    hh.x = __float2half_rn(v0);
                    hh.y = __float2half_rn(v1);
                    *(__half2*)(outS + (size_t)(r + hrow*8)*HDIM + c) = hh;
                }
            }
        }
    }
}

// ---------------- launch ----------------
extern "C" void kernel_launch(void* const* d_in, const int* in_sizes, int n_in,
                              void* d_out, int out_size){
    (void)in_sizes; (void)n_in; (void)out_size;
    const float* x  = (const float*)d_in[0];
    const float* w1 = (const float*)d_in[1];
    const float* b1 = (const float*)d_in[2];
    const float* w2 = (const float*)d_in[3];
    const float* b2 = (const float*)d_in[4];
    float* out = (float*)d_out;

    __half *pBt1, *pBt2, *pA1, *pA2;
    cudaGetSymbolAddress((void**)&pBt1, g_Bt1);
    cudaGetSymbolAddress((void**)&pBt2, g_Bt2);
    cudaGetSymbolAddress((void**)&pA1, g_A1);
    cudaGetSymbolAddress((void**)&pA2, g_A2);

    k_splitW<<<dim3(HDIM/32, DDIM/32), 256>>>(w1, pBt1, DDIM, HDIM);
    k_splitW<<<dim3(HDIM/32, HDIM/32), 256>>>(w2, pBt2, HDIM, HDIM);

    k_normalize<<<NCLIP*TCLIP, 256>>>(x);
    k_sumrows<<<dim3(NCLIP, 4), 256>>>();
    k_reddot<<<NCLIP*KFT, 256>>>();
    k_select<<<NCLIP, 256>>>();
    k_init<<<NCLIP*KFK, 256>>>(x);

    cudaFuncSetAttribute(k_sim_mma, cudaFuncAttributeMaxDynamicSharedMemorySize, SIMH_SMEM);

    const int nlist[7] = {588, 392, 262, 175, 117, 78, 52};
    const int mlist[7] = {196, 130,  87,  58,  39, 26,  3};
    for(int it=0; it<7; it++){
        int n = nlist[it];
        k_norms<<<(NCLIP*KFK + 7)/8, 256>>>();
        k_sim_mma<<<dim3((n+63)/64, NCLIP), 256, SIMH_SMEM>>>(n);
        k_merge<<<NCLIP, 1024>>>(x, n, mlist[it]);
    }
    k_z_half<<<NCLIP*NFIN, 256>>>(x, pA1);

    cudaFuncSetAttribute(mma_gemm<DDIM,1>, cudaFuncAttributeMaxDynamicSharedMemorySize, SMEM_GEMM);
    cudaFuncSetAttribute(mma_gemm<HDIM,0>, cudaFuncAttributeMaxDynamicSharedMemorySize, SMEM_GEMM);
    dim3 grid(HDIM/BN, MROWS/BM);   // (32, 49)
    mma_gemm<DDIM,1><<<grid, 512, SMEM_GEMM>>>(pA1, pBt1, b1, nullptr, pA2);
    mma_gemm<HDIM,0><<<grid, 512, SMEM_GEMM>>>(pA2, pBt2, b2, out, nullptr);
}

// round 17
// speedup vs baseline: 5.9813x; 1.3527x over previous
#include <cuda_runtime.h>
#include <cuda_bf16.h>
#include <cuda_fp16.h>
#include <math.h>
#include <stdint.h>

// Problem constants
#define NCLIP 64
#define TCLIP 784
#define DDIM  1024
#define KFT   196
#define KFK   147
#define NI0   588
#define NFIN  196
#define HDIM  4096
#define MROWS (NCLIP*NFIN)   // 12544

// ---------------- scratch (device globals) ----------------
__device__ float g_kfn  [NCLIP*KFT*DDIM];
__device__ float g_Sp   [NCLIP*4*DDIM];
__device__ float g_red  [NCLIP*KFT];
__device__ int   g_keep [NCLIP*KFK];
__device__ float g_kfsum[NCLIP*KFK*DDIM];
__device__ float g_kfcnt[NCLIP*KFK];
__device__ float g_kfinv[NCLIP*KFK];
__device__ float g_maxsim[NCLIP*NI0];
__device__ int   g_bestkf[NCLIP*NI0];
__device__ int   g_surv [NCLIP*NI0];

// fp16 hi|lo token / kf buffers for tensor-core sim (row stride 2048 halves)
__device__ __half g_Ihl [(size_t)NCLIP*NI0*2048];
__device__ __half g_KFhl[(size_t)NCLIP*KFK*2048];

// plain fp16 GEMM operands (A stride K; B^T stride K)
__device__ __half g_A1 [(size_t)MROWS*DDIM];
__device__ __half g_A2 [(size_t)MROWS*HDIM];
__device__ __half g_Bt1[(size_t)HDIM*DDIM];
__device__ __half g_Bt2[(size_t)HDIM*HDIM];

// ---------------- low-level helpers ----------------
__device__ __forceinline__ uint32_t smem_to_u32(const void* p){
    uint32_t a;
    asm("{ .reg .u64 t; cvta.to.shared.u64 t, %1; cvt.u32.u64 %0, t; }" : "=r"(a) : "l"(p));
    return a;
}
#define SW128(off) ((off) ^ (((off) >> 3) & 0x70))

__device__ __forceinline__ void cp_async16(uint32_t saddr, const void* gaddr){
    asm volatile("cp.async.cg.shared.global [%0], [%1], 16;" :: "r"(saddr), "l"(gaddr));
}
__device__ __forceinline__ void cp_commit(){ asm volatile("cp.async.commit_group;" ::: "memory"); }
__device__ __forceinline__ void cp_wait1(){ asm volatile("cp.async.wait_group 1;" ::: "memory"); }

__device__ __forceinline__ void ldmx4(uint32_t* r, uint32_t addr){
    asm volatile("ldmatrix.sync.aligned.m8n8.x4.shared.b16 {%0,%1,%2,%3}, [%4];"
        : "=r"(r[0]), "=r"(r[1]), "=r"(r[2]), "=r"(r[3]) : "r"(addr));
}
__device__ __forceinline__ void mma16816h(float* c, const uint32_t* a, uint32_t b0, uint32_t b1){
    asm volatile("mma.sync.aligned.m16n8k16.row.col.f32.f16.f16.f32 "
        "{%0,%1,%2,%3}, {%4,%5,%6,%7}, {%8,%9}, {%0,%1,%2,%3};"
        : "+f"(c[0]), "+f"(c[1]), "+f"(c[2]), "+f"(c[3])
        : "r"(a[0]), "r"(a[1]), "r"(a[2]), "r"(a[3]), "r"(b0), "r"(b1));
}

// ---------------- generic helpers ----------------
__device__ __forceinline__ float blockSum256(float v){
    __shared__ float sh[8];
    int lane = threadIdx.x & 31, w = threadIdx.x >> 5;
    #pragma unroll
    for(int o=16;o;o>>=1) v += __shfl_xor_sync(0xffffffffu, v, o);
    if(lane==0) sh[w] = v;
    __syncthreads();
    float r = (threadIdx.x < 8) ? sh[threadIdx.x] : 0.f;
    if(w==0){
        #pragma unroll
        for(int o=4;o;o>>=1) r += __shfl_xor_sync(0xffffffffu, r, o);
        if(lane==0) sh[0] = r;
    }
    __syncthreads();
    float out = sh[0];
    __syncthreads();
    return out;
}

__device__ __forceinline__ void bitonic_sort(float* key, int* pos, int N){
    int t = threadIdx.x;
    for(int k=2;k<=N;k<<=1){
        for(int j=k>>1;j>0;j>>=1){
            __syncthreads();
            int ixj = t ^ j;
            if(ixj > t){
                float ka = key[t], kb = key[ixj];
                int   pa = pos[t], pb = pos[ixj];
                bool agtb = (ka > kb) || (ka == kb && pa > pb);
                bool up = ((t & k) == 0);
                if(agtb == up){
                    key[t]=kb; key[ixj]=ka;
                    pos[t]=pb; pos[ixj]=pa;
                }
            }
        }
    }
    __syncthreads();
}

__device__ __forceinline__ float gelu_exact(float v){
    return 0.5f * v * (1.0f + erff(v * 0.70710678118654752440f));
}

// ---------------- compression kernels ----------------
__global__ void k_normalize(const float* __restrict__ x){
    int b = blockIdx.x / TCLIP;
    int r = blockIdx.x % TCLIP;
    const float* row = x + ((size_t)b*TCLIP + r)*DDIM;
    float ss = 0.f;
    for(int i=threadIdx.x;i<DDIM;i+=256){ float v = row[i]; ss += v*v; }
    ss = blockSum256(ss);
    float inv = 1.0f / fmaxf(sqrtf(ss), 1e-12f);
    if(r < KFT){
        float* dst = g_kfn + ((size_t)b*KFT + r)*DDIM;
        for(int i=threadIdx.x;i<DDIM;i+=256) dst[i] = row[i]*inv;
    } else {
        __half* d = g_Ihl + ((size_t)b*NI0 + (r - KFT))*2048;
        for(int i=threadIdx.x;i<DDIM;i+=256){
            float v = row[i]*inv;
            __half h = __float2half_rn(v);
            d[i] = h;
            d[1024+i] = __float2half_rn(v - __half2float(h));
        }
    }
}

__global__ void k_sumrows(){
    int b = blockIdx.x, part = blockIdx.y;
    int d0 = threadIdx.x * 4;
    int j0 = part*49, j1 = j0 + 49;
    float4 acc = make_float4(0.f,0.f,0.f,0.f);
    const float* base = g_kfn + (size_t)b*KFT*DDIM + d0;
    for(int j=j0;j<j1;j++){
        float4 v = *(const float4*)(base + (size_t)j*DDIM);
        acc.x += v.x; acc.y += v.y; acc.z += v.z; acc.w += v.w;
    }
    *(float4*)(g_Sp + ((size_t)b*4 + part)*DDIM + d0) = acc;
}

__global__ void k_reddot(){
    int b = blockIdx.x / KFT, i = blockIdx.x % KFT;
    const float* ri = g_kfn + ((size_t)b*KFT + i)*DDIM;
    const float* S0 = g_Sp + (size_t)b*4*DDIM;
    float s = 0.f;
    for(int d=threadIdx.x; d<DDIM; d+=256)
        s += ri[d]*(S0[d] + S0[DDIM+d] + S0[2*DDIM+d] + S0[3*DDIM+d]);
    s = blockSum256(s);
    if(threadIdx.x==0) g_red[b*KFT + i] = s - 1.0f;
}

__global__ void k_select(){
    int b = blockIdx.x;
    __shared__ float key[256];
    __shared__ int   pos[256];
    __shared__ unsigned char kept[KFT];
    int t = threadIdx.x;
    key[t] = (t < KFT) ? g_red[b*KFT + t] : __int_as_float(0x7f800000);
    pos[t] = t;
    if(t < KFT) kept[t] = 0;
    bitonic_sort(key, pos, 256);
    if(t < KFK) kept[pos[t]] = 1;
    __syncthreads();
    if(t==0){
        int c = 0;
        for(int i=0;i<KFT;i++) if(kept[i]) g_keep[b*KFK + (c++)] = i;
    }
    for(int s=t;s<NI0;s+=256) g_surv[b*NI0 + s] = s;
}

__global__ void k_init(const float* __restrict__ x){
    int b = blockIdx.x / KFK, k = blockIdx.x % KFK;
    int src = g_keep[b*KFK + k];
    const float* row = x + ((size_t)b*TCLIP + src)*DDIM;
    float* dst = g_kfsum + ((size_t)b*KFK + k)*DDIM;
    for(int i=threadIdx.x;i<DDIM;i+=256) dst[i] = row[i];
    if(threadIdx.x==0) g_kfcnt[b*KFK + k] = 1.0f;
}

// per-kf inverse norm of kfsum + fp16 hi|lo re-split
__global__ void k_norms(){
    int row = blockIdx.x*8 + (threadIdx.x >> 5);
    if(row >= NCLIP*KFK) return;
    int lane = threadIdx.x & 31;
    const float4* s = (const float4*)(g_kfsum + (size_t)row*DDIM);
    __half* dh = g_KFhl + (size_t)row*2048;
    float ss = 0.f;
    #pragma unroll
    for(int i=0;i<8;i++){
        float4 v = s[lane + i*32];
        ss += v.x*v.x + v.y*v.y + v.z*v.z + v.w*v.w;
        __half h0 = __float2half_rn(v.x), h1 = __float2half_rn(v.y);
        __half h2 = __float2half_rn(v.z), h3 = __float2half_rn(v.w);
        __half l0 = __float2half_rn(v.x - __half2float(h0));
        __half l1 = __float2half_rn(v.y - __half2float(h1));
        __half l2 = __float2half_rn(v.z - __half2float(h2));
        __half l3 = __float2half_rn(v.w - __half2float(h3));
        int e = (lane + i*32)*4;
        __half2 a; a.x = h0; a.y = h1; *(__half2*)(dh + e)     = a;
        __half2 c; c.x = h2; c.y = h3; *(__half2*)(dh + e + 2) = c;
        __half2 p; p.x = l0; p.y = l1; *(__half2*)(dh + 1024 + e)     = p;
        __half2 q; q.x = l2; q.y = l3; *(__half2*)(dh + 1024 + e + 2) = q;
    }
    #pragma unroll
    for(int o=16;o;o>>=1) ss += __shfl_xor_sync(0xffffffffu, ss, o);
    if(lane==0) g_kfinv[row] = 1.0f / fmaxf(sqrtf(ss), 1e-12f);
}

// ---------------- tensor-core sim: C[160pad,64] = KF * I^T, fused argmax ----
#define SIMH_STAGE 57344
#define SIMH_SMEM  (2*SIMH_STAGE)
#define S_KFH 0
#define S_KFL 20480
#define S_IH  40960
#define S_IL  49152

__global__ void __launch_bounds__(256, 1) k_sim_mma(int n){
    extern __shared__ char sm[];
    uint32_t sb = smem_to_u32(sm);
    int b = blockIdx.y, tile0 = blockIdx.x*64;
    int tid = threadIdx.x, wid = tid >> 5, l = tid & 31;
    int wm = wid & 1, wn = wid >> 1;   // 2(m) x 4(n); warp tile 80x16

    __shared__ int   stok[64];
    __shared__ float kfinv_s[KFK];
    __shared__ float svals[2][64];
    __shared__ int   sidx [2][64];

    for(int i=tid; i<SIMH_SMEM/16; i+=256) *(uint4*)(sm + i*16) = make_uint4(0,0,0,0);
    if(tid < 64){
        int s = tile0 + tid;
        stok[tid] = (s < n) ? g_surv[b*NI0 + tid + tile0] : -1;
    }
    if(tid < KFK) kfinv_s[tid] = g_kfinv[b*KFK + tid];
    __syncthreads();

    const __half* KF = g_KFhl + (size_t)b*KFK*2048;

    float acc[5][2][4];
    #pragma unroll
    for(int mt=0;mt<5;mt++)
        #pragma unroll
        for(int ntp=0;ntp<2;ntp++)
            #pragma unroll
            for(int q=0;q<4;q++) acc[mt][ntp][q] = 0.f;

    #define SIMLOAD(kc, buf) { \
        uint32_t base_ = sb + (buf)*SIMH_STAGE; \
        _Pragma("unroll") \
        for(int i_=0;i_<10;i_++){ \
            int u_ = tid + i_*256; \
            int row_ = u_ >> 4, q_ = u_ & 15; \
            int seg_ = q_ & 7, hl_ = q_ >> 3; \
            if(row_ < KFK) \
                cp_async16(base_ + (hl_?S_KFL:S_KFH) + SW128((uint32_t)(row_*128 + seg_*16)), \
                           KF + (size_t)row_*2048 + hl_*1024 + (kc)*64 + seg_*8); \
        } \
        _Pragma("unroll") \
        for(int i_=0;i_<4;i_++){ \
            int u_ = tid + i_*256; \
            int row_ = u_ >> 4, q_ = u_ & 15; \
            int seg_ = q_ & 7, hl_ = q_ >> 3; \
            int tok_ = stok[row_]; \
            if(tok_ >= 0) \
                cp_async16(base_ + (hl_?S_IL:S_IH) + SW128((uint32_t)(row_*128 + seg_*16)), \
                           g_Ihl + ((size_t)b*NI0 + tok_)*2048 + hl_*1024 + (kc)*64 + seg_*8); \
        } }

    SIMLOAD(0, 0); cp_commit();
    SIMLOAD(1, 1); cp_commit();

    for(int t=0; t<16; t++){
        cp_wait1();
        __syncthreads();
        uint32_t sbuf = sb + (t & 1)*SIMH_STAGE;
        #pragma unroll
        for(int ks=0; ks<4; ks++){
            uint32_t aH[5][4], aL[5][4];
            #pragma unroll
            for(int mt=0; mt<5; mt++){
                uint32_t aoff = SW128((uint32_t)((wm*80 + mt*16 + (l & 15))*128 + ks*32 + (l >> 4)*16));
                ldmx4(aH[mt], sbuf + S_KFH + aoff);
                ldmx4(aL[mt], sbuf + S_KFL + aoff);
            }
            uint32_t bH[4], bL[4];
            uint32_t boff = SW128((uint32_t)((wn*16 + (l & 7) + ((l >> 4) << 3))*128 + ks*32 + ((l >> 3) & 1)*16));
            ldmx4(bH, sbuf + S_IH + boff);
            ldmx4(bL, sbuf + S_IL + boff);
            #pragma unroll
            for(int mt=0; mt<5; mt++){
                #pragma unroll
                for(int ntp=0; ntp<2; ntp++){
                    mma16816h(acc[mt][ntp], aH[mt], bH[ntp*2], bH[ntp*2+1]);
                    mma16816h(acc[mt][ntp], aL[mt], bH[ntp*2], bH[ntp*2+1]);
                    mma16816h(acc[mt][ntp], aH[mt], bL[ntp*2], bL[ntp*2+1]);
                }
            }
        }
        __syncthreads();
        if(t+2 < 16){ SIMLOAD(t+2, t & 1); }
        cp_commit();
    }

    float bv[4]; int bi[4];
    #pragma unroll
    for(int ci=0; ci<4; ci++){ bv[ci] = -3.0e38f; bi[ci] = 0x7fffffff; }
    #pragma unroll
    for(int mt=0; mt<5; mt++){
        #pragma unroll
        for(int h=0; h<2; h++){
            int row = wm*80 + mt*16 + (l >> 2) + h*8;
            if(row < KFK){
                float inv = kfinv_s[row];
                #pragma unroll
                for(int ntp=0; ntp<2; ntp++){
                    #pragma unroll
                    for(int c01=0; c01<2; c01++){
                        int ci = ntp*2 + c01;
                        float v = acc[mt][ntp][h*2 + c01] * inv;
                        if(v > bv[ci]){ bv[ci] = v; bi[ci] = row; }
                    }
                }
            }
        }
    }
    #pragma unroll
    for(int off=4; off<32; off<<=1){
        #pragma unroll
        for(int ci=0; ci<4; ci++){
            float ov = __shfl_xor_sync(0xffffffffu, bv[ci], off);
            int   oi = __shfl_xor_sync(0xffffffffu, bi[ci], off);
            if(ov > bv[ci] || (ov == bv[ci] && oi < bi[ci])){ bv[ci] = ov; bi[ci] = oi; }
        }
    }
    if(l < 4){
        #pragma unroll
        for(int ci=0; ci<4; ci++){
            int col = wn*16 + (ci >> 1)*8 + l*2 + (ci & 1);
            svals[wm][col] = bv[ci];
            sidx [wm][col] = bi[ci];
        }
    }
    __syncthreads();
    if(tid < 64){
        int s = tile0 + tid;
        if(s < n){
            float v0 = svals[0][tid], v1 = svals[1][tid];
            int   i0 = sidx[0][tid],  i1 = sidx[1][tid];
            bool take1 = (v1 > v0) || (v1 == v0 && i1 < i0);
            g_maxsim[b*NI0 + s] = take1 ? v1 : v0;
            g_bestkf[b*NI0 + s] = take1 ? i1 : i0;
        }
    }
}

__global__ void k_merge(const float* __restrict__ x, int n, int nm){
    int b = blockIdx.x, t = threadIdx.x;
    __shared__ float key[1024];
    __shared__ int   pos[1024];
    __shared__ int   mpos[196], mtgt[196], mtok[196];
    __shared__ unsigned char mflag[NI0];
    key[t] = (t < n) ? -g_maxsim[b*NI0 + t] : __int_as_float(0x7f800000);
    pos[t] = t;
    bitonic_sort(key, pos, 1024);
    if(t < nm){
        int p = pos[t];
        mpos[t] = p;
        mtgt[t] = g_bestkf[b*NI0 + p];
        mtok[t] = g_surv  [b*NI0 + p];
    }
    __syncthreads();
    if(nm > 0){
        float cur = x[((size_t)b*TCLIP + KFT + mtok[0])*DDIM + t];
        for(int m=0;m<nm;m++){
            float nxt = (m+1 < nm) ? x[((size_t)b*TCLIP + KFT + mtok[m+1])*DDIM + t] : 0.f;
            g_kfsum[((size_t)b*KFK + mtgt[m])*DDIM + t] += cur;
            if(t==0) g_kfcnt[b*KFK + mtgt[m]] += 1.0f;
            cur = nxt;
        }
    }
    for(int i=t;i<n;i+=1024) mflag[i] = 0;
    __syncthreads();
    if(t < nm) mflag[mpos[t]] = 1;
    __syncthreads();
    if(t==0){
        int c = 0;
        for(int p=0;p<n;p++)
            if(!mflag[p]){ int v = g_surv[b*NI0 + p]; g_surv[b*NI0 + c] = v; c++; }
    }
}

// fused z + fp16 convert
__global__ void k_z_half(const float* __restrict__ x, __half* __restrict__ dst){
    int b = blockIdx.x / NFIN, r = blockIdx.x % NFIN;
    __half* d = dst + ((size_t)b*NFIN + r)*DDIM;
    if(r < KFK){
        float invc = 1.0f / g_kfcnt[b*KFK + r];
        const float* s = g_kfsum + ((size_t)b*KFK + r)*DDIM;
        for(int i=threadIdx.x;i<DDIM;i+=256)
            d[i] = __float2half_rn(s[i]*invc);
    } else {
        int tok = g_surv[b*NI0 + (r - KFK)];
        const float* s = x + ((size_t)b*TCLIP + KFT + tok)*DDIM;
        for(int i=threadIdx.x;i<DDIM;i+=256)
            d[i] = __float2half_rn(s[i]);
    }
}

// W fp32 [K,N] -> Bt fp16 [N,K] (transpose + convert, no split)
__global__ void k_convW(const float* __restrict__ w, __half* __restrict__ bt, int K, int N){
    __shared__ float tile[32][33];
    int kb = blockIdx.y*32, nb = blockIdx.x*32;
    int tx = threadIdx.x & 31, ty = threadIdx.x >> 5;
    for(int i=ty;i<32;i+=8) tile[i][tx] = w[(size_t)(kb+i)*N + nb + tx];
    __syncthreads();
    for(int i=ty;i<32;i+=8)
        bt[(size_t)(nb+i)*K + kb + tx] = __float2half_rn(tile[tx][i]);
}

// ---------------- plain fp16 HMMA GEMM, 256x128x64, 3-stage ----------------
#define BM 256
#define BN 128
#define BK 64
#define OFF_B 32768
#define STAGE_BYTES 49152
#define SMEM_GEMM (3*STAGE_BYTES)   // 144KB

template<int K, int MODE>
__global__ void __launch_bounds__(512, 1) mma_gemm(
    const __half* __restrict__ A, const __half* __restrict__ Bt,
    const float* __restrict__ bias, float* __restrict__ outF,
    __half* __restrict__ outS)
{
    extern __shared__ char smem[];
    uint32_t sb = smem_to_u32(smem);
    int tid = threadIdx.x, wid = tid >> 5, l = tid & 31;
    int row0 = blockIdx.y * BM, col0 = blockIdx.x * BN;
    int wm = wid & 7, wn = wid >> 3;     // 8 x 2 warps; warp tile 32x64
    const int T = K / BK;

    float acc[2][8][4];
    #pragma unroll
    for(int mt=0;mt<2;mt++)
        #pragma unroll
        for(int nt=0;nt<8;nt++)
            #pragma unroll
            for(int q=0;q<4;q++) acc[mt][nt][q] = 0.f;

    int ra   = wm*32 + (l & 15);
    int ca16 = (l >> 4) * 16;
    int rb   = wn*64 + (l & 7) + ((l >> 4) << 3);
    int cb16 = ((l >> 3) & 1) * 16;

    #define LOADS(s, buf) { \
        uint32_t base_ = sb + (buf)*STAGE_BYTES; \
        int w0_ = (s)*BK; \
        const __half* Ap_ = A  + (size_t)row0*K + w0_; \
        const __half* Bp_ = Bt + (size_t)col0*K + w0_; \
        _Pragma("unroll") \
        for(int i_=0;i_<4;i_++){ \
            int u_ = tid + i_*512; \
            int r_ = u_ >> 3, sg_ = u_ & 7; \
            cp_async16(base_ + SW128((uint32_t)(r_*128 + sg_*16)), Ap_ + (size_t)r_*K + sg_*8); \
        } \
        _Pragma("unroll") \
        for(int i_=0;i_<2;i_++){ \
            int u_ = tid + i_*512; \
            int r_ = u_ >> 3, sg_ = u_ & 7; \
            cp_async16(base_ + OFF_B + SW128((uint32_t)(r_*128 + sg_*16)), Bp_ + (size_t)r_*K + sg_*8); \
        } }

    LOADS(0, 0); cp_commit();
    LOADS(1, 1); cp_commit();

    for(int t=0; t<T; t++){
        cp_wait1();
        __syncthreads();
        // load t+2 into buffer (t+2)%3: that buffer was consumed in iter t-1,
        // and the sync above guarantees all warps have finished iter t-1.
        if(t+2 < T){ LOADS(t+2, (t+2)%3); }
        cp_commit();

        uint32_t sbuf = sb + (t%3)*STAGE_BYTES;
        #pragma unroll
        for(int ks=0; ks<4; ks++){
            uint32_t a[2][4];
            #pragma unroll
            for(int mt=0; mt<2; mt++)
                ldmx4(a[mt], sbuf + SW128((uint32_t)((ra + mt*16)*128 + ks*32 + ca16)));
            #pragma unroll
            for(int ntp=0; ntp<4; ntp++){
                uint32_t bfr[4];
                ldmx4(bfr, sbuf + OFF_B + SW128((uint32_t)((rb + ntp*16)*128 + ks*32 + cb16)));
                #pragma unroll
                for(int mt=0; mt<2; mt++){
                    mma16816h(acc[mt][ntp*2],   a[mt], bfr[0], bfr[1]);
                    mma16816h(acc[mt][ntp*2+1], a[mt], bfr[2], bfr[3]);
                }
            }
        }
    }

    // ---- epilogue ----
    #pragma unroll
    for(int mt=0; mt<2; mt++){
        #pragma unroll
        for(int nt=0; nt<8; nt++){
            float* a4 = acc[mt][nt];
            int r = row0 + wm*32 + mt*16 + (l >> 2);
            int c = col0 + wn*64 + nt*8 + ((l & 3) << 1);
            float bi0 = bias[c], bi1 = bias[c+1];
            if(MODE == 0){
                float2 v0; v0.x = a4[0] + bi0; v0.y = a4[1] + bi1;
                float2 v1; v1.x = a4[2] + bi0; v1.y = a4[3] + bi1;
                *(float2*)(outF + (size_t)r*HDIM + c)     = v0;
                *(float2*)(outF + (size_t)(r+8)*HDIM + c) = v1;
            } else {
                #pragma unroll
                for(int hrow=0; hrow<2; hrow++){
                    float v0 = gelu_exact(a4[hrow*2+0] + bi0);
                    float v1 = gelu_exact(a4[hrow*2+1] + bi1);
                    __half2 hh;
                    hh.x = __float2half_rn(v0);
                    hh.y = __float2half_rn(v1);
                    *(__half2*)(outS + (size_t)(r + hrow*8)*HDIM + c) = hh;
                }
            }
        }
    }
}

// ---------------- launch ----------------
extern "C" void kernel_launch(void* const* d_in, const int* in_sizes, int n_in,
                              void* d_out, int out_size){
    (void)in_sizes; (void)n_in; (void)out_size;
    const float* x  = (const float*)d_in[0];
    const float* w1 = (const float*)d_in[1];
    const float* b1 = (const float*)d_in[2];
    const float* w2 = (const float*)d_in[3];
    const float* b2 = (const float*)d_in[4];
    float* out = (float*)d_out;

    __half *pBt1, *pBt2, *pA1, *pA2;
    cudaGetSymbolAddress((void**)&pBt1, g_Bt1);
    cudaGetSymbolAddress((void**)&pBt2, g_Bt2);
    cudaGetSymbolAddress((void**)&pA1, g_A1);
    cudaGetSymbolAddress((void**)&pA2, g_A2);

    k_convW<<<dim3(HDIM/32, DDIM/32), 256>>>(w1, pBt1, DDIM, HDIM);
    k_convW<<<dim3(HDIM/32, HDIM/32), 256>>>(w2, pBt2, HDIM, HDIM);

    k_normalize<<<NCLIP*TCLIP, 256>>>(x);
    k_sumrows<<<dim3(NCLIP, 4), 256>>>();
    k_reddot<<<NCLIP*KFT, 256>>>();
    k_select<<<NCLIP, 256>>>();
    k_init<<<NCLIP*KFK, 256>>>(x);

    cudaFuncSetAttribute(k_sim_mma, cudaFuncAttributeMaxDynamicSharedMemorySize, SIMH_SMEM);

    const int nlist[7] = {588, 392, 262, 175, 117, 78, 52};
    const int mlist[7] = {196, 130,  87,  58,  39, 26,  3};
    for(int it=0; it<7; it++){
        int n = nlist[it];
        k_norms<<<(NCLIP*KFK + 7)/8, 256>>>();
        k_sim_mma<<<dim3((n+63)/64, NCLIP), 256, SIMH_SMEM>>>(n);
        k_merge<<<NCLIP, 1024>>>(x, n, mlist[it]);
    }
    k_z_half<<<NCLIP*NFIN, 256>>>(x, pA1);

    cudaFuncSetAttribute(mma_gemm<DDIM,1>, cudaFuncAttributeMaxDynamicSharedMemorySize, SMEM_GEMM);
    cudaFuncSetAttribute(mma_gemm<HDIM,0>, cudaFuncAttributeMaxDynamicSharedMemorySize, SMEM_GEMM);
    dim3 grid(HDIM/BN, MROWS/BM);   // (32, 49)
    mma_gemm<DDIM,1><<<grid, 512, SMEM_GEMM>>>(pA1, pBt1, b1, nullptr, pA2);
    mma_gemm<HDIM,0><<<grid, 512, SMEM_GEMM>>>(pA2, pBt2, b2, out, nullptr);
}